// round 4
// baseline (speedup 1.0000x reference)
#include <cuda_runtime.h>
#include <cuda_bf16.h>
#include <cstdint>
#include <math.h>

// ---------------- problem constants ----------------
#define Bsz   4096
#define Hn    512
#define H3    1536
#define Ln    3
#define Tn    16
#define Cn    512
#define NSTEP 17
#define KDIM  512
#define NCH   4            // K chunks of 128 int8 (128B rows)

static const size_t BH   = (size_t)Bsz * Hn;     // 2,097,152
static const size_t BH3  = (size_t)Bsz * H3;     // 6,291,456
static const size_t SLOT = (size_t)Bsz * Hn;     // int8 plane slot stride (bytes=elems)

// ---------------- persistent device scratch ----------------
// int8 activation plane ping-pong (17 slots each)
__device__ __align__(128) int8_t g_uA_hi[(size_t)NSTEP * Bsz * Hn];
__device__ __align__(128) int8_t g_uA_lo[(size_t)NSTEP * Bsz * Hn];
__device__ __align__(128) int8_t g_uB_hi[(size_t)NSTEP * Bsz * Hn];
__device__ __align__(128) int8_t g_uB_lo[(size_t)NSTEP * Bsz * Hn];
__device__ __align__(128) float  g_scA[(size_t)NSTEP * Bsz];
__device__ __align__(128) float  g_scB[(size_t)NSTEP * Bsz];
// prev hidden quantized
__device__ __align__(128) int8_t g_pq_hi[(size_t)Ln * Bsz * Hn];
__device__ __align__(128) int8_t g_pq_lo[(size_t)Ln * Bsz * Hn];
__device__ __align__(128) float  g_sprev[(size_t)Ln * Bsz];
// fp32 state + gate buffers
__device__ __align__(128) float  g_hseqF[(size_t)NSTEP * Bsz * Hn];
__device__ __align__(128) float  g_GI[(size_t)NSTEP * Bsz * H3];
__device__ __align__(128) float  g_GH[(size_t)Bsz * H3];
// quantized weights
__device__ __align__(128) int8_t g_wihq_hi[(size_t)Ln * H3 * Hn];
__device__ __align__(128) int8_t g_wihq_lo[(size_t)Ln * H3 * Hn];
__device__ __align__(128) float  g_swih[(size_t)Ln * H3];
__device__ __align__(128) int8_t g_whhq_hi[(size_t)Ln * H3 * Hn];
__device__ __align__(128) int8_t g_whhq_lo[(size_t)Ln * H3 * Hn];
__device__ __align__(128) float  g_swhh[(size_t)Ln * H3];
__device__ __align__(128) int8_t g_woq_hi[(size_t)Cn * Hn];
__device__ __align__(128) int8_t g_woq_lo[(size_t)Cn * Hn];
__device__ __align__(128) float  g_swo[Cn];
__device__ __align__(128) int8_t g_embq_hi[(size_t)Cn * Hn];
__device__ __align__(128) int8_t g_embq_lo[(size_t)Cn * Hn];
__device__ __align__(128) float  g_semb[Cn];
__device__ __align__(128) int8_t g_wtq_hi[(size_t)Hn * Hn];
__device__ __align__(128) int8_t g_wtq_lo[(size_t)Hn * Hn];
__device__ __align__(128) float  g_swt[Hn];
// projection table
__device__ __align__(128) float  g_P[(size_t)Cn * Hn];
__device__ __align__(128) int8_t g_Pq_hi[(size_t)Cn * Hn];
__device__ __align__(128) int8_t g_Pq_lo[(size_t)Cn * Hn];
__device__ __align__(128) float  g_Psc[Cn];

// ---------------- PTX helpers (baseline features only) ----------------
__device__ __forceinline__ uint32_t smem_u32(const void* p) {
    uint32_t a;
    asm("{ .reg .u64 t; cvta.to.shared.u64 t, %1; cvt.u32.u64 %0, t; }" : "=r"(a) : "l"(p));
    return a;
}
__device__ __forceinline__ void cpasync16(uint32_t s, const void* g) {
    asm volatile("cp.async.cg.shared.global [%0], [%1], 16;" :: "r"(s), "l"(g));
}
__device__ __forceinline__ void cp_commit() {
    asm volatile("cp.async.commit_group;" ::: "memory");
}
template <int N> __device__ __forceinline__ void cp_wait() {
    asm volatile("cp.async.wait_group %0;" :: "n"(N) : "memory");
}
__device__ __forceinline__ void ldsm4(uint32_t& r0, uint32_t& r1, uint32_t& r2, uint32_t& r3,
                                      uint32_t addr) {
    asm volatile("ldmatrix.sync.aligned.m8n8.x4.shared.b16 {%0,%1,%2,%3}, [%4];"
                 : "=r"(r0), "=r"(r1), "=r"(r2), "=r"(r3) : "r"(addr));
}
__device__ __forceinline__ void imma16832(int* d, const uint32_t* a, uint32_t b0, uint32_t b1) {
    asm volatile(
        "mma.sync.aligned.m16n8k32.row.col.s32.s8.s8.s32 "
        "{%0,%1,%2,%3}, {%4,%5,%6,%7}, {%8,%9}, {%0,%1,%2,%3};"
        : "+r"(d[0]), "+r"(d[1]), "+r"(d[2]), "+r"(d[3])
        : "r"(a[0]), "r"(a[1]), "r"(a[2]), "r"(a[3]), "r"(b0), "r"(b1));
}

#define GEMM_SMEM (2 * 65536)   // 2 stages x (4 plane-tiles x 16KB)

// ---------------------------------------------------------------------------
// int8x3 tensor-core GEMM:
//   C[m,n] = sA[m]*sB[n]*(P_hh + (P_hl + P_lh)/128) + bias[n]
// A planes [M,512] s8, B planes [N,512] s8 (K contiguous), per-row scales.
// 128x128 CTA tile, chunk=128B of K, cp.async double buffer, 8 warps (4x2).
// MODE 0: row-major C (ld=ldc). MODE 2: logits scatter [B,T,C].
// ---------------------------------------------------------------------------
template <int MODE>
__global__ void __launch_bounds__(256)
gemm_i8(const int8_t* __restrict__ Ahi, const int8_t* __restrict__ Alo,
        const int8_t* __restrict__ Bhi, const int8_t* __restrict__ Blo,
        const float* __restrict__ sA, const float* __restrict__ sB,
        const float* __restrict__ bias, float* __restrict__ C, int ldc)
{
    extern __shared__ __align__(128) char smem[];
    const uint32_t sb = smem_u32(smem);
    const int tid  = threadIdx.x;
    const int wid  = tid >> 5, lane = tid & 31;
    const int wM   = wid >> 1;             // 0..3  (m offset 32 each)
    const int wN   = wid & 1;              // 0..1  (n offset 64 each)
    const int m0   = blockIdx.y << 7, n0 = blockIdx.x << 7;

    const int8_t* gAh = Ahi + (size_t)m0 * KDIM;
    const int8_t* gAl = Alo + (size_t)m0 * KDIM;
    const int8_t* gBh = Bhi + (size_t)n0 * KDIM;
    const int8_t* gBl = Blo + (size_t)n0 * KDIM;

    int srow[4], soff[4]; uint32_t sso[4];
#pragma unroll
    for (int q = 0; q < 4; q++) {
        int id = tid * 4 + q;              // 0..1023 segments of 16B
        srow[q] = id >> 3;
        soff[q] = (id & 7) << 4;
        sso[q]  = (uint32_t)((srow[q] << 7) | (soff[q] ^ ((srow[q] & 7) << 4)));
    }

    const int lr16 = lane & 15;
    const int lhi  = (lane >> 4) << 4;     // 0 or 16: k-half byte offset
    uint32_t aBase[2], aXr[2];
#pragma unroll
    for (int mt = 0; mt < 2; mt++) {
        int r = wM * 32 + mt * 16 + lr16;
        aBase[mt] = (uint32_t)(r << 7);
        aXr[mt]   = ((r & 7) << 4);
    }
    uint32_t bBase[4], bXr[4];
#pragma unroll
    for (int nt = 0; nt < 4; nt++) {
        int r = wN * 64 + nt * 16 + lr16;
        bBase[nt] = (uint32_t)(r << 7);
        bXr[nt]   = ((r & 7) << 4);
    }

    int acch[2][8][4], accl[2][8][4];
#pragma unroll
    for (int i = 0; i < 2; i++)
#pragma unroll
        for (int j = 0; j < 8; j++)
#pragma unroll
            for (int v = 0; v < 4; v++) { acch[i][j][v] = 0; accl[i][j][v] = 0; }

    auto load_chunk = [&](int s, int c) {
        const uint32_t st = sb + s * 65536;
        const int cb = c * 128;
#pragma unroll
        for (int q = 0; q < 4; q++) {
            int go = srow[q] * 512 + cb + soff[q];
            cpasync16(st +         sso[q], gAh + go);
            cpasync16(st + 16384 + sso[q], gAl + go);
            cpasync16(st + 32768 + sso[q], gBh + go);
            cpasync16(st + 49152 + sso[q], gBl + go);
        }
        cp_commit();
    };

    load_chunk(0, 0);

    for (int c = 0; c < NCH; c++) {
        const int s = c & 1;
        if (c + 1 < NCH) { load_chunk(s ^ 1, c + 1); cp_wait<1>(); }
        else             { cp_wait<0>(); }
        __syncthreads();

        const uint32_t stA0 = sb + s * 65536;           // Ah
        const uint32_t stA1 = stA0 + 16384;             // Al
        const uint32_t stB0 = stA0 + 32768;             // Bh
        const uint32_t stB1 = stA0 + 49152;             // Bl

#pragma unroll
        for (int k32 = 0; k32 < 4; k32++) {
            const uint32_t ko = (uint32_t)(k32 * 32 + lhi);
            uint32_t ah[2][4], al[2][4];
#pragma unroll
            for (int mt = 0; mt < 2; mt++) {
                ldsm4(ah[mt][0], ah[mt][1], ah[mt][2], ah[mt][3],
                      stA0 + aBase[mt] + (ko ^ aXr[mt]));
                ldsm4(al[mt][0], al[mt][1], al[mt][2], al[mt][3],
                      stA1 + aBase[mt] + (ko ^ aXr[mt]));
            }
            uint32_t bh[4][4], bl[4][4];
#pragma unroll
            for (int nt = 0; nt < 4; nt++) {
                ldsm4(bh[nt][0], bh[nt][1], bh[nt][2], bh[nt][3],
                      stB0 + bBase[nt] + (ko ^ bXr[nt]));
                ldsm4(bl[nt][0], bl[nt][1], bl[nt][2], bl[nt][3],
                      stB1 + bBase[nt] + (ko ^ bXr[nt]));
            }
#pragma unroll
            for (int mt = 0; mt < 2; mt++)
#pragma unroll
                for (int nt = 0; nt < 4; nt++) {
                    imma16832(acch[mt][2 * nt + 0], ah[mt], bh[nt][0], bh[nt][2]);
                    imma16832(acch[mt][2 * nt + 1], ah[mt], bh[nt][1], bh[nt][3]);
                    imma16832(accl[mt][2 * nt + 0], ah[mt], bl[nt][0], bl[nt][2]);
                    imma16832(accl[mt][2 * nt + 1], ah[mt], bl[nt][1], bl[nt][3]);
                    imma16832(accl[mt][2 * nt + 0], al[mt], bh[nt][0], bh[nt][2]);
                    imma16832(accl[mt][2 * nt + 1], al[mt], bh[nt][1], bh[nt][3]);
                }
        }
        __syncthreads();
    }

    // ---- epilogue: dequant + bias + store ----
    const int lr = lane >> 2;          // 0..7
    const int lc = (lane & 3) << 1;    // 0,2,4,6
#pragma unroll
    for (int mt = 0; mt < 2; mt++) {
        const int mBase = m0 + wM * 32 + mt * 16 + lr;
        const float sa0 = sA[mBase], sa1 = sA[mBase + 8];
#pragma unroll
        for (int nt = 0; nt < 8; nt++) {
            const int n = n0 + wN * 64 + nt * 8 + lc;
            const float sb0 = sB[n], sb1 = sB[n + 1];
            const float bb0 = bias[n], bb1 = bias[n + 1];
            float f00 = (float)acch[mt][nt][0] + (float)accl[mt][nt][0] * 0.0078125f;
            float f01 = (float)acch[mt][nt][1] + (float)accl[mt][nt][1] * 0.0078125f;
            float f10 = (float)acch[mt][nt][2] + (float)accl[mt][nt][2] * 0.0078125f;
            float f11 = (float)acch[mt][nt][3] + (float)accl[mt][nt][3] * 0.0078125f;
            float2 v0 = make_float2(f00 * sa0 * sb0 + bb0, f01 * sa0 * sb1 + bb1);
            float2 v1 = make_float2(f10 * sa1 * sb0 + bb0, f11 * sa1 * sb1 + bb1);
            size_t o0, o1;
            if (MODE == 2) {
                int bb_0 = mBase & (Bsz - 1),       t0 = mBase >> 12;
                int bb_1 = (mBase + 8) & (Bsz - 1), t1 = (mBase + 8) >> 12;
                o0 = (size_t)bb_0 * (Tn * Cn) + (size_t)t0 * Cn + n;
                o1 = (size_t)bb_1 * (Tn * Cn) + (size_t)t1 * Cn + n;
            } else {
                o0 = (size_t)mBase * ldc + n;
                o1 = (size_t)(mBase + 8) * ldc + n;
            }
            *(float2*)(C + o0) = v0;
            *(float2*)(C + o1) = v1;
        }
    }
}

// ---------------- quantization helpers ----------------
__device__ __forceinline__ float warpmax(float m) {
#pragma unroll
    for (int o = 16; o > 0; o >>= 1)
        m = fmaxf(m, __shfl_xor_sync(0xffffffffu, m, o));
    return m;
}

// quantize 4 values with inv scale, pack into hi/lo u32
__device__ __forceinline__ void quant4(const float* v, float inv, uint32_t& hp, uint32_t& lp) {
    hp = 0; lp = 0;
#pragma unroll
    for (int i = 0; i < 4; i++) {
        float x = v[i] * inv;
        int ih = __float2int_rn(x);
        int il = __float2int_rn((x - (float)ih) * 128.f);
        hp |= (uint32_t)(ih & 255) << (8 * i);
        lp |= (uint32_t)(il & 255) << (8 * i);
    }
}

// generic per-row quantizer: 1 block (128 threads) per row of 512 floats
__global__ void quant_rows(const float* __restrict__ src, int8_t* __restrict__ hi,
                           int8_t* __restrict__ lo, float* __restrict__ sc, int nrows)
{
    __shared__ float red[4];
    int row = blockIdx.x;
    if (row >= nrows) return;
    int t = threadIdx.x;
    const float* s = src + (size_t)row * 512 + t * 4;
    float v[4];
    float4 vv = *(const float4*)s;
    v[0] = vv.x; v[1] = vv.y; v[2] = vv.z; v[3] = vv.w;
    float m = fmaxf(fmaxf(fabsf(v[0]), fabsf(v[1])), fmaxf(fabsf(v[2]), fabsf(v[3])));
    m = warpmax(m);
    if ((t & 31) == 0) red[t >> 5] = m;
    __syncthreads();
    float rmax = fmaxf(fmaxf(red[0], red[1]), fmaxf(red[2], red[3]));
    float inv = rmax > 0.f ? 127.f / rmax : 0.f;
    uint32_t hp, lp;
    quant4(v, inv, hp, lp);
    ((uint32_t*)(hi + (size_t)row * 512))[t] = hp;
    ((uint32_t*)(lo + (size_t)row * 512))[t] = lp;
    if (t == 0) sc[row] = rmax * (1.f / 127.f);
}

// all weight matrices in one launch (for stable ncu launch indexing)
__global__ void quant_weights(const float* __restrict__ W_ih, const float* __restrict__ W_hh,
                              const float* __restrict__ W_out, const float* __restrict__ emb,
                              const float* __restrict__ W_tp,
                              int8_t* wihh, int8_t* wihl, float* swih,
                              int8_t* whhh, int8_t* whhl, float* swhh,
                              int8_t* woh,  int8_t* wol,  float* swo,
                              int8_t* embh, int8_t* embl, float* semb,
                              int8_t* wth,  int8_t* wtl,  float* swt)
{
    __shared__ float red[4];
    int r = blockIdx.x;
    const float* src; int8_t* hi; int8_t* lo; float* sc; int lr;
    if (r < 4608)       { lr = r;         src = W_ih;  hi = wihh; lo = wihl; sc = swih; }
    else if (r < 9216)  { lr = r - 4608;  src = W_hh;  hi = whhh; lo = whhl; sc = swhh; }
    else if (r < 9728)  { lr = r - 9216;  src = W_out; hi = woh;  lo = wol;  sc = swo; }
    else if (r < 10240) { lr = r - 9728;  src = emb;   hi = embh; lo = embl; sc = semb; }
    else                { lr = r - 10240; src = W_tp;  hi = wth;  lo = wtl;  sc = swt; }
    int t = threadIdx.x;
    float4 vv = *(const float4*)(src + (size_t)lr * 512 + t * 4);
    float v[4] = {vv.x, vv.y, vv.z, vv.w};
    float m = fmaxf(fmaxf(fabsf(v[0]), fabsf(v[1])), fmaxf(fabsf(v[2]), fabsf(v[3])));
    m = warpmax(m);
    if ((t & 31) == 0) red[t >> 5] = m;
    __syncthreads();
    float rmax = fmaxf(fmaxf(red[0], red[1]), fmaxf(red[2], red[3]));
    float inv = rmax > 0.f ? 127.f / rmax : 0.f;
    uint32_t hp, lp;
    quant4(v, inv, hp, lp);
    ((uint32_t*)(hi + (size_t)lr * 512))[t] = hp;
    ((uint32_t*)(lo + (size_t)lr * 512))[t] = lp;
    if (t == 0) sc[lr] = rmax * (1.f / 127.f);
}

// x0 = action @ W_a.T + b_a, quantized into slot0; slot1 zeroed
__global__ void u0_quant(const float* __restrict__ action, const float* __restrict__ W_a,
                         const float* __restrict__ b_a,
                         int8_t* __restrict__ hi, int8_t* __restrict__ lo,
                         float* __restrict__ sc)
{
    __shared__ float red[4];
    int b = blockIdx.x;
    int t = threadIdx.x;
    float a0 = action[b * 3 + 0], a1 = action[b * 3 + 1], a2 = action[b * 3 + 2];
    float v[4];
#pragma unroll
    for (int i = 0; i < 4; i++) {
        int j = t * 4 + i;
        v[i] = b_a[j] + a0 * W_a[j * 3 + 0] + a1 * W_a[j * 3 + 1] + a2 * W_a[j * 3 + 2];
    }
    float m = fmaxf(fmaxf(fabsf(v[0]), fabsf(v[1])), fmaxf(fabsf(v[2]), fabsf(v[3])));
    m = warpmax(m);
    if ((t & 31) == 0) red[t >> 5] = m;
    __syncthreads();
    float rmax = fmaxf(fmaxf(red[0], red[1]), fmaxf(red[2], red[3]));
    float inv = rmax > 0.f ? 127.f / rmax : 0.f;
    uint32_t hp, lp;
    quant4(v, inv, hp, lp);
    ((uint32_t*)(hi + (size_t)b * 512))[t] = hp;
    ((uint32_t*)(lo + (size_t)b * 512))[t] = lp;
    ((uint32_t*)(hi + SLOT + (size_t)b * 512))[t] = 0;   // slot1 = zeros
    ((uint32_t*)(lo + SLOT + (size_t)b * 512))[t] = 0;
    if (t == 0) { sc[b] = rmax * (1.f / 127.f); sc[Bsz + b] = 0.f; }
}

// gather quantized projected-embedding rows into slots 2..16
__global__ void gatherP_kernel(const int8_t* __restrict__ Pqh, const int8_t* __restrict__ Pql,
                               const float* __restrict__ Psc, const int* __restrict__ gt,
                               int8_t* __restrict__ hi, int8_t* __restrict__ lo,
                               float* __restrict__ sc)
{
    int i = blockIdx.x * blockDim.x + threadIdx.x;   // over 15*B*64
    if (i >= 15 * Bsz * 64) return;
    int seg = i & 63;
    int row = i >> 6;
    int b   = row & (Bsz - 1);
    int s   = row >> 12;                             // 0..14
    int tok = gt[b * Tn + s];
    int slot = 2 + s;
    size_t po = (size_t)tok * 512 + (seg & 31) * 16;
    size_t uo = (size_t)slot * SLOT + (size_t)b * 512 + (seg & 31) * 16;
    if (seg < 32) *(uint4*)(hi + uo) = *(const uint4*)(Pqh + po);
    else          *(uint4*)(lo + uo) = *(const uint4*)(Pql + po);
    if (seg == 0) sc[(size_t)slot * Bsz + b] = Psc[tok];
}

__device__ __forceinline__ float sigf(float x) { return 1.f / (1.f + __expf(-x)); }

// GRU gate + rowwise quantization of new hidden state.
// 256 threads = 2 rows x 128 threads, 4 elems/thread.
__global__ void gate_quant(const float* __restrict__ GIt, const float* __restrict__ GH,
                           const float* __restrict__ hprevF, float* __restrict__ houtF,
                           int8_t* __restrict__ hi, int8_t* __restrict__ lo,
                           float* __restrict__ sc)
{
    __shared__ float red[2][4];
    int half = threadIdx.x >> 7;                 // 0/1 (row within block)
    int t    = threadIdx.x & 127;
    int b    = blockIdx.x * 2 + half;
    int j    = t * 4;
    size_t o  = (size_t)b * H3 + j;
    size_t ih = (size_t)b * Hn + j;
    float4 gir = *(const float4*)(GIt + o);
    float4 giz = *(const float4*)(GIt + o + 512);
    float4 gin = *(const float4*)(GIt + o + 1024);
    float4 ghr = *(const float4*)(GH + o);
    float4 ghz = *(const float4*)(GH + o + 512);
    float4 ghn = *(const float4*)(GH + o + 1024);
    float4 hp  = *(const float4*)(hprevF + ih);
    float h[4];
    {
        float r0 = sigf(gir.x + ghr.x), r1 = sigf(gir.y + ghr.y);
        float r2 = sigf(gir.z + ghr.z), r3 = sigf(gir.w + ghr.w);
        float z0 = sigf(giz.x + ghz.x), z1 = sigf(giz.y + ghz.y);
        float z2 = sigf(giz.z + ghz.z), z3 = sigf(giz.w + ghz.w);
        float n0 = tanhf(gin.x + r0 * ghn.x), n1 = tanhf(gin.y + r1 * ghn.y);
        float n2 = tanhf(gin.z + r2 * ghn.z), n3 = tanhf(gin.w + r3 * ghn.w);
        h[0] = (1.f - z0) * n0 + z0 * hp.x;
        h[1] = (1.f - z1) * n1 + z1 * hp.y;
        h[2] = (1.f - z2) * n2 + z2 * hp.z;
        h[3] = (1.f - z3) * n3 + z3 * hp.w;
    }
    *(float4*)(houtF + ih) = make_float4(h[0], h[1], h[2], h[3]);
    float m = fmaxf(fmaxf(fabsf(h[0]), fabsf(h[1])), fmaxf(fabsf(h[2]), fabsf(h[3])));
    m = warpmax(m);
    if ((t & 31) == 0) red[half][t >> 5] = m;
    __syncthreads();
    float rmax = fmaxf(fmaxf(red[half][0], red[half][1]), fmaxf(red[half][2], red[half][3]));
    float inv = rmax > 0.f ? 127.f / rmax : 0.f;
    uint32_t hpk, lpk;
    quant4(h, inv, hpk, lpk);
    ((uint32_t*)(hi + (size_t)b * 512))[t] = hpk;
    ((uint32_t*)(lo + (size_t)b * 512))[t] = lpk;
    if (t == 0) sc[b] = rmax * (1.f / 127.f);
}

__global__ void copyf4_kernel(const float* __restrict__ src, float* __restrict__ dst)
{
    int i = blockIdx.x * blockDim.x + threadIdx.x;
    if (i >= (int)(BH / 4)) return;
    ((float4*)dst)[i] = ((const float4*)src)[i];
}

__global__ void heads_kernel(const float* __restrict__ h2, const float* __restrict__ W_r,
                             const float* __restrict__ b_r, const float* __restrict__ W_d,
                             const float* __restrict__ b_d,
                             float* __restrict__ outr, float* __restrict__ outd)
{
    int gw = (blockIdx.x * blockDim.x + threadIdx.x) >> 5;
    int lane = threadIdx.x & 31;
    if (gw >= Bsz) return;
    const float* hb = h2 + (size_t)gw * Hn;
    float sr = 0.f, sd = 0.f;
#pragma unroll
    for (int k = lane; k < Hn; k += 32) {
        float v = hb[k];
        sr = fmaf(v, W_r[k], sr);
        sd = fmaf(v, W_d[k], sd);
    }
#pragma unroll
    for (int o = 16; o > 0; o >>= 1) {
        sr += __shfl_down_sync(0xffffffffu, sr, o);
        sd += __shfl_down_sync(0xffffffffu, sd, o);
    }
    if (lane == 0) { outr[gw] = sr + b_r[0]; outd[gw] = sd + b_d[0]; }
}

// ---------------------------------------------------------------------------
extern "C" void kernel_launch(void* const* d_in, const int* in_sizes, int n_in,
                              void* d_out, int out_size)
{
    const float* action      = (const float*)d_in[0];
    const float* prev_hidden = (const float*)d_in[1];
    const int*   gt          = (const int*)d_in[2];
    const float* W_a         = (const float*)d_in[3];
    const float* b_a         = (const float*)d_in[4];
    const float* emb         = (const float*)d_in[5];
    const float* W_tp        = (const float*)d_in[6];
    const float* b_tp        = (const float*)d_in[7];
    const float* W_ih        = (const float*)d_in[8];
    const float* W_hh        = (const float*)d_in[9];
    const float* b_ih        = (const float*)d_in[10];
    const float* b_hh        = (const float*)d_in[11];
    const float* W_out       = (const float*)d_in[12];
    const float* b_out       = (const float*)d_in[13];
    const float* W_r         = (const float*)d_in[14];
    const float* b_r         = (const float*)d_in[15];
    const float* W_d         = (const float*)d_in[16];
    const float* b_d         = (const float*)d_in[17];
    float* out = (float*)d_out;

    static bool attr_done = false;
    if (!attr_done) {
        cudaFuncSetAttribute(gemm_i8<0>, cudaFuncAttributeMaxDynamicSharedMemorySize, GEMM_SMEM);
        cudaFuncSetAttribute(gemm_i8<2>, cudaFuncAttributeMaxDynamicSharedMemorySize, GEMM_SMEM);
        attr_done = true;
    }

    int8_t *uAh, *uAl, *uBh, *uBl, *pqh, *pql;
    int8_t *wihh, *wihl, *whhh, *whhl, *woh, *wol, *embh, *embl, *wth, *wtl, *Pqh, *Pql;
    float *scA, *scB, *sprev, *swih, *swhh, *swo, *semb, *swt, *Psc;
    float *hseqF, *GI, *GH, *P;
    cudaGetSymbolAddress((void**)&uAh, g_uA_hi);   cudaGetSymbolAddress((void**)&uAl, g_uA_lo);
    cudaGetSymbolAddress((void**)&uBh, g_uB_hi);   cudaGetSymbolAddress((void**)&uBl, g_uB_lo);
    cudaGetSymbolAddress((void**)&scA, g_scA);     cudaGetSymbolAddress((void**)&scB, g_scB);
    cudaGetSymbolAddress((void**)&pqh, g_pq_hi);   cudaGetSymbolAddress((void**)&pql, g_pq_lo);
    cudaGetSymbolAddress((void**)&sprev, g_sprev);
    cudaGetSymbolAddress((void**)&wihh, g_wihq_hi); cudaGetSymbolAddress((void**)&wihl, g_wihq_lo);
    cudaGetSymbolAddress((void**)&swih, g_swih);
    cudaGetSymbolAddress((void**)&whhh, g_whhq_hi); cudaGetSymbolAddress((void**)&whhl, g_whhq_lo);
    cudaGetSymbolAddress((void**)&swhh, g_swhh);
    cudaGetSymbolAddress((void**)&woh, g_woq_hi);  cudaGetSymbolAddress((void**)&wol, g_woq_lo);
    cudaGetSymbolAddress((void**)&swo, g_swo);
    cudaGetSymbolAddress((void**)&embh, g_embq_hi); cudaGetSymbolAddress((void**)&embl, g_embq_lo);
    cudaGetSymbolAddress((void**)&semb, g_semb);
    cudaGetSymbolAddress((void**)&wth, g_wtq_hi);  cudaGetSymbolAddress((void**)&wtl, g_wtq_lo);
    cudaGetSymbolAddress((void**)&swt, g_swt);
    cudaGetSymbolAddress((void**)&Pqh, g_Pq_hi);   cudaGetSymbolAddress((void**)&Pql, g_Pq_lo);
    cudaGetSymbolAddress((void**)&Psc, g_Psc);
    cudaGetSymbolAddress((void**)&hseqF, g_hseqF);
    cudaGetSymbolAddress((void**)&GI, g_GI);
    cudaGetSymbolAddress((void**)&GH, g_GH);
    cudaGetSymbolAddress((void**)&P, g_P);

    float* outLogits = out;
    float* outReward = out + (size_t)Bsz * Tn * Cn;
    float* outDone   = outReward + Bsz;
    float* outFinal  = outDone + Bsz;

    // [0] quantize all weights (one launch)
    quant_weights<<<10752, 128>>>(W_ih, W_hh, W_out, emb, W_tp,
                                  wihh, wihl, swih, whhh, whhl, swhh,
                                  woh, wol, swo, embh, embl, semb, wth, wtl, swt);
    // [1] quantize prev hidden (3*4096 rows)
    quant_rows<<<Ln * Bsz, 128>>>(prev_hidden, pqh, pql, sprev, Ln * Bsz);
    // [2] x0 -> slot0, zeros -> slot1
    u0_quant<<<Bsz, 128>>>(action, W_a, b_a, uAh, uAl, scA);
    // [3] P = emb @ W_tp.T + b_tp  (int8x3 GEMM)
    gemm_i8<0><<<dim3(4, 4), 256, GEMM_SMEM>>>(embh, embl, wth, wtl, semb, swt, b_tp, P, Hn);
    // [4] quantize P rows
    quant_rows<<<Cn, 128>>>(P, Pqh, Pql, Psc, Cn);
    // [5] GH gemm (layer0, t=0)  <-- ncu -s 5 captures this
    gemm_i8<0><<<dim3(12, 32), 256, GEMM_SMEM>>>(pqh, pql, whhh, whhl,
                                                 sprev, swhh, b_hh, GH, H3);
    // [6] gather projected embeddings into slots 2..16
    gatherP_kernel<<<(15 * Bsz * 64 + 255) / 256, 256>>>(Pqh, Pql, Psc, gt, uAh, uAl, scA);

    int8_t *Uh = uAh, *Ul = uAl, *Oh = uBh, *Ol = uBl;
    float *sU = scA, *sO = scB;
    for (int l = 0; l < Ln; l++) {
        // batched input-gate GEMM over all 17 slots
        gemm_i8<0><<<dim3(12, 544), 256, GEMM_SMEM>>>(
            Uh, Ul, wihh + (size_t)l * H3 * Hn, wihl + (size_t)l * H3 * Hn,
            sU, swih + (size_t)l * H3, b_ih + l * H3, GI, H3);
        for (int t = 0; t < NSTEP; t++) {
            if (!(l == 0 && t == 0)) {     // (l0,t0) GH was launched at index 5
                const int8_t* ph; const int8_t* pl; const float* ps;
                if (t == 0) {
                    ph = pqh + (size_t)l * SLOT; pl = pql + (size_t)l * SLOT;
                    ps = sprev + (size_t)l * Bsz;
                } else {
                    ph = Oh + (size_t)(t - 1) * SLOT; pl = Ol + (size_t)(t - 1) * SLOT;
                    ps = sO + (size_t)(t - 1) * Bsz;
                }
                gemm_i8<0><<<dim3(12, 32), 256, GEMM_SMEM>>>(
                    ph, pl, whhh + (size_t)l * H3 * Hn, whhl + (size_t)l * H3 * Hn,
                    ps, swhh + (size_t)l * H3, b_hh + l * H3, GH, H3);
            }
            const float* hpF = t ? (hseqF + (size_t)(t - 1) * BH)
                                 : (prev_hidden + (size_t)l * BH);
            gate_quant<<<Bsz / 2, 256>>>(
                GI + (size_t)t * BH3, GH, hpF, hseqF + (size_t)t * BH,
                Oh + (size_t)t * SLOT, Ol + (size_t)t * SLOT, sO + (size_t)t * Bsz);
        }
        copyf4_kernel<<<((int)(BH / 4) + 255) / 256, 256>>>(
            hseqF + (size_t)16 * BH, outFinal + (size_t)l * BH);
        int8_t* tp;
        tp = Uh; Uh = Oh; Oh = tp;
        tp = Ul; Ul = Ol; Ol = tp;
        float* tf = sU; sU = sO; sO = tf;
    }

    // logits over scan slots 1..16 (layer-2 output planes, now in U)
    gemm_i8<2><<<dim3(4, 512), 256, GEMM_SMEM>>>(
        Uh + SLOT, Ul + SLOT, woh, wol, sU + Bsz, swo, b_out, outLogits, 0);

    // reward / done heads from layer-2 fp32 state at slot 0
    heads_kernel<<<(Bsz * 32 + 255) / 256, 256>>>(
        hseqF, W_r, b_r, W_d, b_d, outReward, outDone);
}

// round 5
// speedup vs baseline: 3.0700x; 3.0700x over previous
#include <cuda_runtime.h>
#include <cuda_fp16.h>
#include <cstdint>
#include <math.h>

// ---------------- problem constants ----------------
#define Bsz   4096
#define Hn    512
#define H3    1536
#define Ln    3
#define Tn    16
#define Cn    512
#define NSTEP 17
#define KDIM  512
#define NCH   8            // K chunks of 64 fp16 (128B rows)

static const size_t BH  = (size_t)Bsz * Hn;    // 2,097,152
static const size_t BH3 = (size_t)Bsz * H3;    // 6,291,456

// ---------------- persistent device scratch ----------------
__device__ __align__(128) __half g_uA_hi[(size_t)NSTEP * Bsz * Hn];
__device__ __align__(128) __half g_uA_lo[(size_t)NSTEP * Bsz * Hn];
__device__ __align__(128) __half g_uB_hi[(size_t)NSTEP * Bsz * Hn];
__device__ __align__(128) __half g_uB_lo[(size_t)NSTEP * Bsz * Hn];
__device__ __align__(128) __half g_pq_hi[(size_t)Ln * Bsz * Hn];
__device__ __align__(128) __half g_pq_lo[(size_t)Ln * Bsz * Hn];
__device__ __align__(128) float  g_hseqF[(size_t)NSTEP * Bsz * Hn];
__device__ __align__(128) float  g_GI[(size_t)NSTEP * Bsz * H3];
__device__ __align__(128) float  g_GH[(size_t)Bsz * H3];
__device__ __align__(128) __half g_wih[(size_t)Ln * H3 * Hn];
__device__ __align__(128) __half g_whh[(size_t)Ln * H3 * Hn];
__device__ __align__(128) __half g_wo[(size_t)Cn * Hn];
__device__ __align__(128) __half g_wt[(size_t)Hn * Hn];
__device__ __align__(128) __half g_embh[(size_t)Cn * Hn];
__device__ __align__(128) __half g_embl[(size_t)Cn * Hn];
__device__ __align__(128) float  g_P[(size_t)Cn * Hn];

// ---------------- PTX helpers (baseline features only) ----------------
__device__ __forceinline__ uint32_t smem_u32(const void* p) {
    uint32_t a;
    asm("{ .reg .u64 t; cvta.to.shared.u64 t, %1; cvt.u32.u64 %0, t; }" : "=r"(a) : "l"(p));
    return a;
}
__device__ __forceinline__ void cpasync16(uint32_t s, const void* g) {
    asm volatile("cp.async.cg.shared.global [%0], [%1], 16;" :: "r"(s), "l"(g));
}
__device__ __forceinline__ void cp_commit() {
    asm volatile("cp.async.commit_group;" ::: "memory");
}
template <int N> __device__ __forceinline__ void cp_wait() {
    asm volatile("cp.async.wait_group %0;" :: "n"(N) : "memory");
}
__device__ __forceinline__ void ldsm4(uint32_t& r0, uint32_t& r1, uint32_t& r2, uint32_t& r3,
                                      uint32_t addr) {
    asm volatile("ldmatrix.sync.aligned.m8n8.x4.shared.b16 {%0,%1,%2,%3}, [%4];"
                 : "=r"(r0), "=r"(r1), "=r"(r2), "=r"(r3) : "r"(addr));
}
__device__ __forceinline__ void hmma16816(float* d, const uint32_t* a, uint32_t b0, uint32_t b1) {
    asm volatile(
        "mma.sync.aligned.m16n8k16.row.col.f32.f16.f16.f32 "
        "{%0,%1,%2,%3}, {%4,%5,%6,%7}, {%8,%9}, {%0,%1,%2,%3};"
        : "+f"(d[0]), "+f"(d[1]), "+f"(d[2]), "+f"(d[3])
        : "r"(a[0]), "r"(a[1]), "r"(a[2]), "r"(a[3]), "r"(b0), "r"(b1));
}

#define GEMM_SMEM (2 * 49152)   // 2 stages x (3 plane-tiles x 16KB)

// ---------------------------------------------------------------------------
// fp16x2 tensor-core GEMM: C[m,n] = sum_k (Ah+Al)[m,k]*Bh[n,k] + bias[n]
// A planes [M,512] fp16, B plane [N,512] fp16, all K-contiguous row-major.
// 128x128 CTA tile, BK=64, cp.async double buffer, 8 warps (4x2), 2 CTAs/SM.
// MODE 0: row-major C (ld=ldc). MODE 2: logits scatter [B,T,C].
// ---------------------------------------------------------------------------
template <int MODE>
__global__ void __launch_bounds__(256, 2)
gemm_h2(const __half* __restrict__ Ahi, const __half* __restrict__ Alo,
        const __half* __restrict__ Bh,
        const float* __restrict__ bias, float* __restrict__ C, int ldc)
{
    extern __shared__ __align__(128) char smem[];
    const uint32_t sb = smem_u32(smem);
    const int tid  = threadIdx.x;
    const int wid  = tid >> 5, lane = tid & 31;
    const int wM   = wid >> 1;             // 0..3  (m offset 32 each)
    const int wN   = wid & 1;              // 0..1  (n offset 64 each)
    const int m0   = blockIdx.y << 7, n0 = blockIdx.x << 7;

    const char* gAh = (const char*)(Ahi + (size_t)m0 * KDIM);
    const char* gAl = (const char*)(Alo + (size_t)m0 * KDIM);
    const char* gB  = (const char*)(Bh  + (size_t)n0 * KDIM);

    int srow[4], soff[4]; uint32_t sso[4];
#pragma unroll
    for (int q = 0; q < 4; q++) {
        int id = tid * 4 + q;              // 0..1023 segments of 16B
        srow[q] = id >> 3;
        soff[q] = (id & 7) << 4;
        sso[q]  = (uint32_t)((srow[q] << 7) | (soff[q] ^ ((srow[q] & 7) << 4)));
    }

    const int lr16 = lane & 15;
    const int lhi  = (lane >> 4) << 4;     // 0 or 16: k-half byte offset
    uint32_t aBase[2], aXr[2];
#pragma unroll
    for (int mt = 0; mt < 2; mt++) {
        int r = wM * 32 + mt * 16 + lr16;
        aBase[mt] = (uint32_t)(r << 7);
        aXr[mt]   = ((r & 7) << 4);
    }
    uint32_t bBase[4], bXr[4];
#pragma unroll
    for (int nt = 0; nt < 4; nt++) {
        int r = wN * 64 + nt * 16 + lr16;
        bBase[nt] = (uint32_t)(r << 7);
        bXr[nt]   = ((r & 7) << 4);
    }

    float acc[2][8][4];
#pragma unroll
    for (int i = 0; i < 2; i++)
#pragma unroll
        for (int j = 0; j < 8; j++)
#pragma unroll
            for (int v = 0; v < 4; v++) acc[i][j][v] = 0.f;

    auto load_chunk = [&](int s, int c) {
        const uint32_t st = sb + s * 49152;
        const int cb = c * 128;
#pragma unroll
        for (int q = 0; q < 4; q++) {
            int go = srow[q] * 1024 + cb + soff[q];
            cpasync16(st +         sso[q], gAh + go);
            cpasync16(st + 16384 + sso[q], gAl + go);
            cpasync16(st + 32768 + sso[q], gB  + go);
        }
        cp_commit();
    };

    load_chunk(0, 0);

    for (int c = 0; c < NCH; c++) {
        const int s = c & 1;
        if (c + 1 < NCH) { load_chunk(s ^ 1, c + 1); cp_wait<1>(); }
        else             { cp_wait<0>(); }
        __syncthreads();

        const uint32_t stA0 = sb + s * 49152;           // Ah
        const uint32_t stA1 = stA0 + 16384;             // Al
        const uint32_t stB0 = stA0 + 32768;             // Bh

#pragma unroll
        for (int k16 = 0; k16 < 4; k16++) {
            const uint32_t ko = (uint32_t)(k16 * 32 + lhi);
            uint32_t ah[2][4], al[2][4];
#pragma unroll
            for (int mt = 0; mt < 2; mt++) {
                ldsm4(ah[mt][0], ah[mt][1], ah[mt][2], ah[mt][3],
                      stA0 + aBase[mt] + (ko ^ aXr[mt]));
                ldsm4(al[mt][0], al[mt][1], al[mt][2], al[mt][3],
                      stA1 + aBase[mt] + (ko ^ aXr[mt]));
            }
            uint32_t bh[4][4];
#pragma unroll
            for (int nt = 0; nt < 4; nt++)
                ldsm4(bh[nt][0], bh[nt][1], bh[nt][2], bh[nt][3],
                      stB0 + bBase[nt] + (ko ^ bXr[nt]));
#pragma unroll
            for (int mt = 0; mt < 2; mt++)
#pragma unroll
                for (int nt = 0; nt < 4; nt++) {
                    hmma16816(acc[mt][2 * nt + 0], ah[mt], bh[nt][0], bh[nt][2]);
                    hmma16816(acc[mt][2 * nt + 1], ah[mt], bh[nt][1], bh[nt][3]);
                    hmma16816(acc[mt][2 * nt + 0], al[mt], bh[nt][0], bh[nt][2]);
                    hmma16816(acc[mt][2 * nt + 1], al[mt], bh[nt][1], bh[nt][3]);
                }
        }
        __syncthreads();
    }

    // ---- epilogue: bias add + store ----
    const int lr = lane >> 2;          // 0..7
    const int lc = (lane & 3) << 1;    // 0,2,4,6
#pragma unroll
    for (int mt = 0; mt < 2; mt++) {
        const int mBase = m0 + wM * 32 + mt * 16 + lr;
#pragma unroll
        for (int nt = 0; nt < 8; nt++) {
            const int n = n0 + wN * 64 + nt * 8 + lc;
            const float b0 = bias[n], b1 = bias[n + 1];
            float2 v0 = make_float2(acc[mt][nt][0] + b0, acc[mt][nt][1] + b1);
            float2 v1 = make_float2(acc[mt][nt][2] + b0, acc[mt][nt][3] + b1);
            size_t o0, o1;
            if (MODE == 2) {
                int bb0 = mBase & (Bsz - 1),       t0 = mBase >> 12;
                int bb1 = (mBase + 8) & (Bsz - 1), t1 = (mBase + 8) >> 12;
                o0 = (size_t)bb0 * (Tn * Cn) + (size_t)t0 * Cn + n;
                o1 = (size_t)bb1 * (Tn * Cn) + (size_t)t1 * Cn + n;
            } else {
                o0 = (size_t)mBase * ldc + n;
                o1 = (size_t)(mBase + 8) * ldc + n;
            }
            *(float2*)(C + o0) = v0;
            *(float2*)(C + o1) = v1;
        }
    }
}

// ---------------- elementwise kernels ----------------
__device__ __forceinline__ void split1h(float x, __half& h, __half& l) {
    h = __float2half_rn(x);
    l = __float2half_rn(x - __half2float(h));
}

// convert all weights in one launch: W_ih, W_hh, W_out, W_tp -> fp16 hi plane;
// emb -> fp16 hi+lo planes. i indexes float4 groups.
__global__ void convW(const float* __restrict__ W_ih, const float* __restrict__ W_hh,
                      const float* __restrict__ W_out, const float* __restrict__ W_tp,
                      const float* __restrict__ emb,
                      __half* __restrict__ wih, __half* __restrict__ whh,
                      __half* __restrict__ wo,  __half* __restrict__ wt,
                      __half* __restrict__ embh, __half* __restrict__ embl)
{
    int i = blockIdx.x * blockDim.x + threadIdx.x;
    if (i >= 1376256) return;
    if (i < 1310720) {
        const float* s; __half* d; int j;
        if (i < 589824)       { s = W_ih;  d = wih; j = i; }
        else if (i < 1179648) { s = W_hh;  d = whh; j = i - 589824; }
        else if (i < 1245184) { s = W_out; d = wo;  j = i - 1179648; }
        else                  { s = W_tp;  d = wt;  j = i - 1245184; }
        float4 v = ((const float4*)s)[j];
        ((__half2*)d)[2 * j + 0] = __floats2half2_rn(v.x, v.y);
        ((__half2*)d)[2 * j + 1] = __floats2half2_rn(v.z, v.w);
    } else {
        int j = i - 1310720;
        float4 v = ((const float4*)emb)[j];
        __half h0, h1, h2, h3, l0, l1, l2, l3;
        split1h(v.x, h0, l0); split1h(v.y, h1, l1);
        split1h(v.z, h2, l2); split1h(v.w, h3, l3);
        ((__half2*)embh)[2 * j + 0] = __halves2half2(h0, h1);
        ((__half2*)embh)[2 * j + 1] = __halves2half2(h2, h3);
        ((__half2*)embl)[2 * j + 0] = __halves2half2(l0, l1);
        ((__half2*)embl)[2 * j + 1] = __halves2half2(l2, l3);
    }
}

// fp32 -> fp16 hi/lo planes (generic, float4 granularity)
__global__ void split2_kernel(const float* __restrict__ src,
                              __half* __restrict__ hi, __half* __restrict__ lo, int n4)
{
    int i = blockIdx.x * blockDim.x + threadIdx.x;
    if (i >= n4) return;
    float4 v = ((const float4*)src)[i];
    __half h0, h1, h2, h3, l0, l1, l2, l3;
    split1h(v.x, h0, l0); split1h(v.y, h1, l1);
    split1h(v.z, h2, l2); split1h(v.w, h3, l3);
    ((__half2*)hi)[2 * i + 0] = __halves2half2(h0, h1);
    ((__half2*)hi)[2 * i + 1] = __halves2half2(h2, h3);
    ((__half2*)lo)[2 * i + 0] = __halves2half2(l0, l1);
    ((__half2*)lo)[2 * i + 1] = __halves2half2(l2, l3);
}

// x0 planes (slot0) + zero planes (slot1)
__global__ void u0_kernel(const float* __restrict__ action, const float* __restrict__ W_a,
                          const float* __restrict__ b_a,
                          __half* __restrict__ hi, __half* __restrict__ lo)
{
    int i = blockIdx.x * blockDim.x + threadIdx.x;
    if (i >= Bsz * Hn) return;
    int b = i >> 9, j = i & 511;
    float s = b_a[j];
    s = fmaf(action[b * 3 + 0], W_a[j * 3 + 0], s);
    s = fmaf(action[b * 3 + 1], W_a[j * 3 + 1], s);
    s = fmaf(action[b * 3 + 2], W_a[j * 3 + 2], s);
    __half h, l;
    split1h(s, h, l);
    hi[i] = h; lo[i] = l;
    __half z = __float2half(0.f);
    hi[BH + i] = z; lo[BH + i] = z;
}

// gather projected-embedding rows into slots 2..16, splitting fp32 -> fp16 planes
__global__ void gatherP_kernel(const float* __restrict__ P, const int* __restrict__ gt,
                               __half* __restrict__ hi, __half* __restrict__ lo)
{
    int i = blockIdx.x * blockDim.x + threadIdx.x;   // over 15*B*(H/4)
    if (i >= 15 * Bsz * (Hn / 4)) return;
    int j4  = (i & 127) << 2;
    int row = i >> 7;
    int b   = row & (Bsz - 1);
    int s   = row >> 12;                              // 0..14
    int tok = gt[b * Tn + s];
    float4 v = *(const float4*)(P + (size_t)tok * Hn + j4);
    __half h0, h1, h2, h3, l0, l1, l2, l3;
    split1h(v.x, h0, l0); split1h(v.y, h1, l1);
    split1h(v.z, h2, l2); split1h(v.w, h3, l3);
    size_t o = (size_t)(2 + s) * BH + (size_t)b * Hn + j4;
    *(__half2*)(hi + o)     = __halves2half2(h0, h1);
    *(__half2*)(hi + o + 2) = __halves2half2(h2, h3);
    *(__half2*)(lo + o)     = __halves2half2(l0, l1);
    *(__half2*)(lo + o + 2) = __halves2half2(l2, l3);
}

__device__ __forceinline__ float sigf(float x) { return 1.f / (1.f + __expf(-x)); }

// GRU gate: h' = (1-z)*n + z*h  (fp32 state + fp16 planes out)
__global__ void gate_kernel(const float* __restrict__ GIt, const float* __restrict__ GH,
                            const float* __restrict__ hprev, float* __restrict__ houtF,
                            __half* __restrict__ hi, __half* __restrict__ lo)
{
    int i = blockIdx.x * blockDim.x + threadIdx.x;   // over B*H/2
    if (i >= Bsz * Hn / 2) return;
    int b  = i >> 8;
    int j2 = (i & 255) << 1;
    size_t o  = (size_t)b * H3 + j2;
    size_t ih = (size_t)b * Hn + j2;
    float2 gir = *(const float2*)(GIt + o);
    float2 giz = *(const float2*)(GIt + o + 512);
    float2 gin = *(const float2*)(GIt + o + 1024);
    float2 ghr = *(const float2*)(GH + o);
    float2 ghz = *(const float2*)(GH + o + 512);
    float2 ghn = *(const float2*)(GH + o + 1024);
    float2 hp  = *(const float2*)(hprev + ih);
    float rx = sigf(gir.x + ghr.x), ry = sigf(gir.y + ghr.y);
    float zx = sigf(giz.x + ghz.x), zy = sigf(giz.y + ghz.y);
    float nx = tanhf(gin.x + rx * ghn.x), ny = tanhf(gin.y + ry * ghn.y);
    float hx = (1.f - zx) * nx + zx * hp.x;
    float hy = (1.f - zy) * ny + zy * hp.y;
    *(float2*)(houtF + ih) = float2{hx, hy};
    __half hh0, hh1, ll0, ll1;
    split1h(hx, hh0, ll0); split1h(hy, hh1, ll1);
    *(__half2*)(hi + ih) = __halves2half2(hh0, hh1);
    *(__half2*)(lo + ih) = __halves2half2(ll0, ll1);
}

__global__ void copyf4_kernel(const float* __restrict__ src, float* __restrict__ dst)
{
    int i = blockIdx.x * blockDim.x + threadIdx.x;
    if (i >= (int)(BH / 4)) return;
    ((float4*)dst)[i] = ((const float4*)src)[i];
}

__global__ void heads_kernel(const float* __restrict__ h2, const float* __restrict__ W_r,
                             const float* __restrict__ b_r, const float* __restrict__ W_d,
                             const float* __restrict__ b_d,
                             float* __restrict__ outr, float* __restrict__ outd)
{
    int gw = (blockIdx.x * blockDim.x + threadIdx.x) >> 5;
    int lane = threadIdx.x & 31;
    if (gw >= Bsz) return;
    const float* hb = h2 + (size_t)gw * Hn;
    float sr = 0.f, sd = 0.f;
#pragma unroll
    for (int k = lane; k < Hn; k += 32) {
        float v = hb[k];
        sr = fmaf(v, W_r[k], sr);
        sd = fmaf(v, W_d[k], sd);
    }
#pragma unroll
    for (int o = 16; o > 0; o >>= 1) {
        sr += __shfl_down_sync(0xffffffffu, sr, o);
        sd += __shfl_down_sync(0xffffffffu, sd, o);
    }
    if (lane == 0) { outr[gw] = sr + b_r[0]; outd[gw] = sd + b_d[0]; }
}

// ---------------------------------------------------------------------------
extern "C" void kernel_launch(void* const* d_in, const int* in_sizes, int n_in,
                              void* d_out, int out_size)
{
    const float* action      = (const float*)d_in[0];
    const float* prev_hidden = (const float*)d_in[1];
    const int*   gt          = (const int*)d_in[2];
    const float* W_a         = (const float*)d_in[3];
    const float* b_a         = (const float*)d_in[4];
    const float* emb         = (const float*)d_in[5];
    const float* W_tp        = (const float*)d_in[6];
    const float* b_tp        = (const float*)d_in[7];
    const float* W_ih        = (const float*)d_in[8];
    const float* W_hh        = (const float*)d_in[9];
    const float* b_ih        = (const float*)d_in[10];
    const float* b_hh        = (const float*)d_in[11];
    const float* W_out       = (const float*)d_in[12];
    const float* b_out       = (const float*)d_in[13];
    const float* W_r         = (const float*)d_in[14];
    const float* b_r         = (const float*)d_in[15];
    const float* W_d         = (const float*)d_in[16];
    const float* b_d         = (const float*)d_in[17];
    float* out = (float*)d_out;

    static bool attr_done = false;
    if (!attr_done) {
        cudaFuncSetAttribute(gemm_h2<0>, cudaFuncAttributeMaxDynamicSharedMemorySize, GEMM_SMEM);
        cudaFuncSetAttribute(gemm_h2<2>, cudaFuncAttributeMaxDynamicSharedMemorySize, GEMM_SMEM);
        attr_done = true;
    }

    __half *uAh, *uAl, *uBh, *uBl, *pqh, *pql;
    __half *wih, *whh, *wo, *wt, *embh, *embl;
    float *hseqF, *GI, *GH, *P;
    cudaGetSymbolAddress((void**)&uAh, g_uA_hi);  cudaGetSymbolAddress((void**)&uAl, g_uA_lo);
    cudaGetSymbolAddress((void**)&uBh, g_uB_hi);  cudaGetSymbolAddress((void**)&uBl, g_uB_lo);
    cudaGetSymbolAddress((void**)&pqh, g_pq_hi);  cudaGetSymbolAddress((void**)&pql, g_pq_lo);
    cudaGetSymbolAddress((void**)&wih, g_wih);    cudaGetSymbolAddress((void**)&whh, g_whh);
    cudaGetSymbolAddress((void**)&wo,  g_wo);     cudaGetSymbolAddress((void**)&wt,  g_wt);
    cudaGetSymbolAddress((void**)&embh, g_embh);  cudaGetSymbolAddress((void**)&embl, g_embl);
    cudaGetSymbolAddress((void**)&hseqF, g_hseqF);
    cudaGetSymbolAddress((void**)&GI, g_GI);
    cudaGetSymbolAddress((void**)&GH, g_GH);
    cudaGetSymbolAddress((void**)&P, g_P);

    float* outLogits = out;
    float* outReward = out + (size_t)Bsz * Tn * Cn;
    float* outDone   = outReward + Bsz;
    float* outFinal  = outDone + Bsz;

    // [0] all weight conversions (one launch)
    convW<<<(1376256 + 255) / 256, 256>>>(W_ih, W_hh, W_out, W_tp, emb,
                                          wih, whh, wo, wt, embh, embl);
    // [1] prev hidden -> fp16 planes
    split2_kernel<<<((int)(Ln * BH / 4) + 255) / 256, 256>>>(
        prev_hidden, pqh, pql, (int)(Ln * BH / 4));
    // [2] x0 -> slot0, zeros -> slot1
    u0_kernel<<<(Bsz * Hn + 255) / 256, 256>>>(action, W_a, b_a, uAh, uAl);
    // [3] P = emb @ W_tp.T + b_tp
    gemm_h2<0><<<dim3(4, 4), 256, GEMM_SMEM>>>(embh, embl, wt, b_tp, P, Hn);
    // [4] gather projected embeddings into slots 2..16
    gatherP_kernel<<<(15 * Bsz * (Hn / 4) + 255) / 256, 256>>>(P, gt, uAh, uAl);

    // ---- 3 GRU layers; launch index 5 = batched GI GEMM (layer 0) ----
    __half *Uh = uAh, *Ul = uAl, *Oh = uBh, *Ol = uBl;
    for (int l = 0; l < Ln; l++) {
        gemm_h2<0><<<dim3(12, 544), 256, GEMM_SMEM>>>(
            Uh, Ul, wih + (size_t)l * H3 * Hn, b_ih + l * H3, GI, H3);
        for (int t = 0; t < NSTEP; t++) {
            const __half* ph = t ? (Oh + (size_t)(t - 1) * BH) : (pqh + (size_t)l * BH);
            const __half* pl = t ? (Ol + (size_t)(t - 1) * BH) : (pql + (size_t)l * BH);
            gemm_h2<0><<<dim3(12, 32), 256, GEMM_SMEM>>>(
                ph, pl, whh + (size_t)l * H3 * Hn, b_hh + l * H3, GH, H3);
            const float* hpF = t ? (hseqF + (size_t)(t - 1) * BH)
                                 : (prev_hidden + (size_t)l * BH);
            gate_kernel<<<(Bsz * Hn / 2 + 255) / 256, 256>>>(
                GI + (size_t)t * BH3, GH, hpF, hseqF + (size_t)t * BH,
                Oh + (size_t)t * BH, Ol + (size_t)t * BH);
        }
        copyf4_kernel<<<((int)(BH / 4) + 255) / 256, 256>>>(
            hseqF + (size_t)16 * BH, outFinal + (size_t)l * BH);
        __half* tp;
        tp = Uh; Uh = Oh; Oh = tp;
        tp = Ul; Ul = Ol; Ol = tp;
    }

    // ---- logits over scan slots 1..16 (layer-2 output planes) ----
    gemm_h2<2><<<dim3(4, 512), 256, GEMM_SMEM>>>(
        Uh + BH, Ul + BH, wo, b_out, outLogits, 0);

    // ---- reward / done heads from layer-2 fp32 state at slot 0 ----
    heads_kernel<<<(Bsz * 32 + 255) / 256, 256>>>(
        hseqF, W_r, b_r, W_d, b_d, outReward, outDone);
}

// round 6
// speedup vs baseline: 3.1874x; 1.0382x over previous
#include <cuda_runtime.h>
#include <cuda_fp16.h>
#include <cstdint>
#include <math.h>

// ---------------- problem constants ----------------
#define Bsz   4096
#define Hn    512
#define H3    1536
#define Ln    3
#define Tn    16
#define Cn    512
#define NSTEP 17
#define KDIM  512
#define NCH   8            // K chunks of 64 fp16 (128B rows)

static const size_t BH  = (size_t)Bsz * Hn;    // 2,097,152
static const size_t BH3 = (size_t)Bsz * H3;    // 6,291,456

// ---------------- persistent device scratch ----------------
__device__ __align__(128) __half g_uA_hi[(size_t)NSTEP * Bsz * Hn];
__device__ __align__(128) __half g_uA_lo[(size_t)NSTEP * Bsz * Hn];
__device__ __align__(128) __half g_uB_hi[(size_t)NSTEP * Bsz * Hn];
__device__ __align__(128) __half g_uB_lo[(size_t)NSTEP * Bsz * Hn];
__device__ __align__(128) __half g_pq_hi[(size_t)Ln * Bsz * Hn];
__device__ __align__(128) __half g_pq_lo[(size_t)Ln * Bsz * Hn];
__device__ __align__(128) float  g_hseqF[(size_t)NSTEP * Bsz * Hn];
__device__ __align__(128) float  g_GI[(size_t)NSTEP * Bsz * H3];
__device__ __align__(128) float  g_GH[(size_t)Bsz * H3];
__device__ __align__(128) __half g_wih[(size_t)Ln * H3 * Hn];
__device__ __align__(128) __half g_whh[(size_t)Ln * H3 * Hn];
__device__ __align__(128) __half g_wo[(size_t)Cn * Hn];
__device__ __align__(128) __half g_wt[(size_t)Hn * Hn];
__device__ __align__(128) __half g_embh[(size_t)Cn * Hn];
__device__ __align__(128) __half g_embl[(size_t)Cn * Hn];
__device__ __align__(128) float  g_P[(size_t)Cn * Hn];     // proj table fp32 [tok, H]
__device__ __align__(128) __half g_Pqh[(size_t)Cn * Hn];   // proj table planes
__device__ __align__(128) __half g_Pql[(size_t)Cn * Hn];
__device__ __align__(128) float  g_Gtab[(size_t)Cn * H3];  // gi table [tok, 3H]

// ---------------- PTX helpers (baseline features only) ----------------
__device__ __forceinline__ uint32_t smem_u32(const void* p) {
    uint32_t a;
    asm("{ .reg .u64 t; cvta.to.shared.u64 t, %1; cvt.u32.u64 %0, t; }" : "=r"(a) : "l"(p));
    return a;
}
__device__ __forceinline__ void cpasync16(uint32_t s, const void* g) {
    asm volatile("cp.async.cg.shared.global [%0], [%1], 16;" :: "r"(s), "l"(g));
}
__device__ __forceinline__ void cp_commit() {
    asm volatile("cp.async.commit_group;" ::: "memory");
}
template <int N> __device__ __forceinline__ void cp_wait() {
    asm volatile("cp.async.wait_group %0;" :: "n"(N) : "memory");
}
__device__ __forceinline__ void ldsm4(uint32_t& r0, uint32_t& r1, uint32_t& r2, uint32_t& r3,
                                      uint32_t addr) {
    asm volatile("ldmatrix.sync.aligned.m8n8.x4.shared.b16 {%0,%1,%2,%3}, [%4];"
                 : "=r"(r0), "=r"(r1), "=r"(r2), "=r"(r3) : "r"(addr));
}
__device__ __forceinline__ void hmma16816(float* d, const uint32_t* a, uint32_t b0, uint32_t b1) {
    asm volatile(
        "mma.sync.aligned.m16n8k16.row.col.f32.f16.f16.f32 "
        "{%0,%1,%2,%3}, {%4,%5,%6,%7}, {%8,%9}, {%0,%1,%2,%3};"
        : "+f"(d[0]), "+f"(d[1]), "+f"(d[2]), "+f"(d[3])
        : "r"(a[0]), "r"(a[1]), "r"(a[2]), "r"(a[3]), "r"(b0), "r"(b1));
}

#define GEMM_SMEM     (2 * 49152)   // 128x128: 2 stages x 48KB
#define GEMM_SMEM_N64 (2 * 40960)   // 128x64:  2 stages x 40KB

// ---------------------------------------------------------------------------
// fp16x2 GEMM, 128x128 tile (for big batched GEMMs).
// C[m,n] = sum_k (Ah+Al)[m,k]*Bh[n,k] + bias[n]
// MODE 0: row-major C (ld=ldc). MODE 2: logits scatter [B,T,C].
// ---------------------------------------------------------------------------
template <int MODE>
__global__ void __launch_bounds__(256, 2)
gemm_h2(const __half* __restrict__ Ahi, const __half* __restrict__ Alo,
        const __half* __restrict__ Bh,
        const float* __restrict__ bias, float* __restrict__ C, int ldc)
{
    extern __shared__ __align__(128) char smem[];
    const uint32_t sb = smem_u32(smem);
    const int tid  = threadIdx.x;
    const int wid  = tid >> 5, lane = tid & 31;
    const int wM   = wid >> 1;
    const int wN   = wid & 1;
    const int m0   = blockIdx.y << 7, n0 = blockIdx.x << 7;

    const char* gAh = (const char*)(Ahi + (size_t)m0 * KDIM);
    const char* gAl = (const char*)(Alo + (size_t)m0 * KDIM);
    const char* gB  = (const char*)(Bh  + (size_t)n0 * KDIM);

    int srow[4], soff[4]; uint32_t sso[4];
#pragma unroll
    for (int q = 0; q < 4; q++) {
        int id = tid * 4 + q;
        srow[q] = id >> 3;
        soff[q] = (id & 7) << 4;
        sso[q]  = (uint32_t)((srow[q] << 7) | (soff[q] ^ ((srow[q] & 7) << 4)));
    }

    const int lr16 = lane & 15;
    const int lhi  = (lane >> 4) << 4;
    uint32_t aBase[2], aXr[2];
#pragma unroll
    for (int mt = 0; mt < 2; mt++) {
        int r = wM * 32 + mt * 16 + lr16;
        aBase[mt] = (uint32_t)(r << 7);
        aXr[mt]   = ((r & 7) << 4);
    }
    uint32_t bBase[4], bXr[4];
#pragma unroll
    for (int nt = 0; nt < 4; nt++) {
        int r = wN * 64 + nt * 16 + lr16;
        bBase[nt] = (uint32_t)(r << 7);
        bXr[nt]   = ((r & 7) << 4);
    }

    float acc[2][8][4];
#pragma unroll
    for (int i = 0; i < 2; i++)
#pragma unroll
        for (int j = 0; j < 8; j++)
#pragma unroll
            for (int v = 0; v < 4; v++) acc[i][j][v] = 0.f;

    auto load_chunk = [&](int s, int c) {
        const uint32_t st = sb + s * 49152;
        const int cb = c * 128;
#pragma unroll
        for (int q = 0; q < 4; q++) {
            int go = srow[q] * 1024 + cb + soff[q];
            cpasync16(st +         sso[q], gAh + go);
            cpasync16(st + 16384 + sso[q], gAl + go);
            cpasync16(st + 32768 + sso[q], gB  + go);
        }
        cp_commit();
    };

    load_chunk(0, 0);

    for (int c = 0; c < NCH; c++) {
        const int s = c & 1;
        if (c + 1 < NCH) { load_chunk(s ^ 1, c + 1); cp_wait<1>(); }
        else             { cp_wait<0>(); }
        __syncthreads();

        const uint32_t stA0 = sb + s * 49152;
        const uint32_t stA1 = stA0 + 16384;
        const uint32_t stB0 = stA0 + 32768;

#pragma unroll
        for (int k16 = 0; k16 < 4; k16++) {
            const uint32_t ko = (uint32_t)(k16 * 32 + lhi);
            uint32_t ah[2][4], al[2][4];
#pragma unroll
            for (int mt = 0; mt < 2; mt++) {
                ldsm4(ah[mt][0], ah[mt][1], ah[mt][2], ah[mt][3],
                      stA0 + aBase[mt] + (ko ^ aXr[mt]));
                ldsm4(al[mt][0], al[mt][1], al[mt][2], al[mt][3],
                      stA1 + aBase[mt] + (ko ^ aXr[mt]));
            }
            uint32_t bh[4][4];
#pragma unroll
            for (int nt = 0; nt < 4; nt++)
                ldsm4(bh[nt][0], bh[nt][1], bh[nt][2], bh[nt][3],
                      stB0 + bBase[nt] + (ko ^ bXr[nt]));
#pragma unroll
            for (int mt = 0; mt < 2; mt++)
#pragma unroll
                for (int nt = 0; nt < 4; nt++) {
                    hmma16816(acc[mt][2 * nt + 0], ah[mt], bh[nt][0], bh[nt][2]);
                    hmma16816(acc[mt][2 * nt + 1], ah[mt], bh[nt][1], bh[nt][3]);
                    hmma16816(acc[mt][2 * nt + 0], al[mt], bh[nt][0], bh[nt][2]);
                    hmma16816(acc[mt][2 * nt + 1], al[mt], bh[nt][1], bh[nt][3]);
                }
        }
        __syncthreads();
    }

    const int lr = lane >> 2;
    const int lc = (lane & 3) << 1;
#pragma unroll
    for (int mt = 0; mt < 2; mt++) {
        const int mBase = m0 + wM * 32 + mt * 16 + lr;
#pragma unroll
        for (int nt = 0; nt < 8; nt++) {
            const int n = n0 + wN * 64 + nt * 8 + lc;
            const float b0 = bias[n], b1 = bias[n + 1];
            float2 v0 = make_float2(acc[mt][nt][0] + b0, acc[mt][nt][1] + b1);
            float2 v1 = make_float2(acc[mt][nt][2] + b0, acc[mt][nt][3] + b1);
            size_t o0, o1;
            if (MODE == 2) {
                int bb0 = mBase & (Bsz - 1),       t0 = mBase >> 12;
                int bb1 = (mBase + 8) & (Bsz - 1), t1 = (mBase + 8) >> 12;
                o0 = (size_t)bb0 * (Tn * Cn) + (size_t)t0 * Cn + n;
                o1 = (size_t)bb1 * (Tn * Cn) + (size_t)t1 * Cn + n;
            } else {
                o0 = (size_t)mBase * ldc + n;
                o1 = (size_t)(mBase + 8) * ldc + n;
            }
            *(float2*)(C + o0) = v0;
            *(float2*)(C + o1) = v1;
        }
    }
}

// ---------------------------------------------------------------------------
// fp16x2 GEMM, 128x64 tile — serial hidden-path GEMM (better wave balance).
// ---------------------------------------------------------------------------
__global__ void __launch_bounds__(256, 2)
gemm_h2_n64(const __half* __restrict__ Ahi, const __half* __restrict__ Alo,
            const __half* __restrict__ Bh,
            const float* __restrict__ bias, float* __restrict__ C, int ldc)
{
    extern __shared__ __align__(128) char smem[];
    const uint32_t sb = smem_u32(smem);
    const int tid  = threadIdx.x;
    const int wid  = tid >> 5, lane = tid & 31;
    const int wM   = wid >> 1;             // 0..3  (m offset 32)
    const int wN   = wid & 1;              // 0..1  (n offset 32)
    const int m0   = blockIdx.y << 7, n0 = blockIdx.x << 6;

    const char* gAh = (const char*)(Ahi + (size_t)m0 * KDIM);
    const char* gAl = (const char*)(Alo + (size_t)m0 * KDIM);
    const char* gB  = (const char*)(Bh  + (size_t)n0 * KDIM);

    int arow[4], aoff[4]; uint32_t aso[4];
#pragma unroll
    for (int q = 0; q < 4; q++) {
        int id = tid * 4 + q;              // 0..1023
        arow[q] = id >> 3;
        aoff[q] = (id & 7) << 4;
        aso[q]  = (uint32_t)((arow[q] << 7) | (aoff[q] ^ ((arow[q] & 7) << 4)));
    }
    int brow[2], boff[2]; uint32_t bso[2];
#pragma unroll
    for (int q = 0; q < 2; q++) {
        int id = tid * 2 + q;              // 0..511
        brow[q] = id >> 3;
        boff[q] = (id & 7) << 4;
        bso[q]  = (uint32_t)((brow[q] << 7) | (boff[q] ^ ((brow[q] & 7) << 4)));
    }

    const int lr16 = lane & 15;
    const int lhi  = (lane >> 4) << 4;
    uint32_t aBase[2], aXr[2];
#pragma unroll
    for (int mt = 0; mt < 2; mt++) {
        int r = wM * 32 + mt * 16 + lr16;
        aBase[mt] = (uint32_t)(r << 7);
        aXr[mt]   = ((r & 7) << 4);
    }
    uint32_t bBase[2], bXr[2];
#pragma unroll
    for (int nt = 0; nt < 2; nt++) {
        int r = wN * 32 + nt * 16 + lr16;
        bBase[nt] = (uint32_t)(r << 7);
        bXr[nt]   = ((r & 7) << 4);
    }

    float acc[2][4][4];
#pragma unroll
    for (int i = 0; i < 2; i++)
#pragma unroll
        for (int j = 0; j < 4; j++)
#pragma unroll
            for (int v = 0; v < 4; v++) acc[i][j][v] = 0.f;

    auto load_chunk = [&](int s, int c) {
        const uint32_t st = sb + s * 40960;
        const int cb = c * 128;
#pragma unroll
        for (int q = 0; q < 4; q++) {
            int go = arow[q] * 1024 + cb + aoff[q];
            cpasync16(st +         aso[q], gAh + go);
            cpasync16(st + 16384 + aso[q], gAl + go);
        }
#pragma unroll
        for (int q = 0; q < 2; q++) {
            int go = brow[q] * 1024 + cb + boff[q];
            cpasync16(st + 32768 + bso[q], gB + go);
        }
        cp_commit();
    };

    load_chunk(0, 0);

    for (int c = 0; c < NCH; c++) {
        const int s = c & 1;
        if (c + 1 < NCH) { load_chunk(s ^ 1, c + 1); cp_wait<1>(); }
        else             { cp_wait<0>(); }
        __syncthreads();

        const uint32_t stA0 = sb + s * 40960;
        const uint32_t stA1 = stA0 + 16384;
        const uint32_t stB0 = stA0 + 32768;

#pragma unroll
        for (int k16 = 0; k16 < 4; k16++) {
            const uint32_t ko = (uint32_t)(k16 * 32 + lhi);
            uint32_t ah[2][4], al[2][4];
#pragma unroll
            for (int mt = 0; mt < 2; mt++) {
                ldsm4(ah[mt][0], ah[mt][1], ah[mt][2], ah[mt][3],
                      stA0 + aBase[mt] + (ko ^ aXr[mt]));
                ldsm4(al[mt][0], al[mt][1], al[mt][2], al[mt][3],
                      stA1 + aBase[mt] + (ko ^ aXr[mt]));
            }
            uint32_t bh[2][4];
#pragma unroll
            for (int nt = 0; nt < 2; nt++)
                ldsm4(bh[nt][0], bh[nt][1], bh[nt][2], bh[nt][3],
                      stB0 + bBase[nt] + (ko ^ bXr[nt]));
#pragma unroll
            for (int mt = 0; mt < 2; mt++)
#pragma unroll
                for (int nt = 0; nt < 2; nt++) {
                    hmma16816(acc[mt][2 * nt + 0], ah[mt], bh[nt][0], bh[nt][2]);
                    hmma16816(acc[mt][2 * nt + 1], ah[mt], bh[nt][1], bh[nt][3]);
                    hmma16816(acc[mt][2 * nt + 0], al[mt], bh[nt][0], bh[nt][2]);
                    hmma16816(acc[mt][2 * nt + 1], al[mt], bh[nt][1], bh[nt][3]);
                }
        }
        __syncthreads();
    }

    const int lr = lane >> 2;
    const int lc = (lane & 3) << 1;
#pragma unroll
    for (int mt = 0; mt < 2; mt++) {
        const int mBase = m0 + wM * 32 + mt * 16 + lr;
#pragma unroll
        for (int nt = 0; nt < 4; nt++) {
            const int n = n0 + wN * 32 + nt * 8 + lc;
            const float b0 = bias[n], b1 = bias[n + 1];
            float2 v0 = make_float2(acc[mt][nt][0] + b0, acc[mt][nt][1] + b1);
            float2 v1 = make_float2(acc[mt][nt][2] + b0, acc[mt][nt][3] + b1);
            *(float2*)(C + (size_t)mBase * ldc + n)       = v0;
            *(float2*)(C + (size_t)(mBase + 8) * ldc + n) = v1;
        }
    }
}

// ---------------- elementwise kernels ----------------
__device__ __forceinline__ void split1h(float x, __half& h, __half& l) {
    h = __float2half_rn(x);
    l = __float2half_rn(x - __half2float(h));
}

__global__ void convW(const float* __restrict__ W_ih, const float* __restrict__ W_hh,
                      const float* __restrict__ W_out, const float* __restrict__ W_tp,
                      const float* __restrict__ emb,
                      __half* __restrict__ wih, __half* __restrict__ whh,
                      __half* __restrict__ wo,  __half* __restrict__ wt,
                      __half* __restrict__ embh, __half* __restrict__ embl)
{
    int i = blockIdx.x * blockDim.x + threadIdx.x;
    if (i >= 1376256) return;
    if (i < 1310720) {
        const float* s; __half* d; int j;
        if (i < 589824)       { s = W_ih;  d = wih; j = i; }
        else if (i < 1179648) { s = W_hh;  d = whh; j = i - 589824; }
        else if (i < 1245184) { s = W_out; d = wo;  j = i - 1179648; }
        else                  { s = W_tp;  d = wt;  j = i - 1245184; }
        float4 v = ((const float4*)s)[j];
        ((__half2*)d)[2 * j + 0] = __floats2half2_rn(v.x, v.y);
        ((__half2*)d)[2 * j + 1] = __floats2half2_rn(v.z, v.w);
    } else {
        int j = i - 1310720;
        float4 v = ((const float4*)emb)[j];
        __half h0, h1, h2, h3, l0, l1, l2, l3;
        split1h(v.x, h0, l0); split1h(v.y, h1, l1);
        split1h(v.z, h2, l2); split1h(v.w, h3, l3);
        ((__half2*)embh)[2 * j + 0] = __halves2half2(h0, h1);
        ((__half2*)embh)[2 * j + 1] = __halves2half2(h2, h3);
        ((__half2*)embl)[2 * j + 0] = __halves2half2(l0, l1);
        ((__half2*)embl)[2 * j + 1] = __halves2half2(l2, l3);
    }
}

__global__ void split2_kernel(const float* __restrict__ src,
                              __half* __restrict__ hi, __half* __restrict__ lo, int n4)
{
    int i = blockIdx.x * blockDim.x + threadIdx.x;
    if (i >= n4) return;
    float4 v = ((const float4*)src)[i];
    __half h0, h1, h2, h3, l0, l1, l2, l3;
    split1h(v.x, h0, l0); split1h(v.y, h1, l1);
    split1h(v.z, h2, l2); split1h(v.w, h3, l3);
    ((__half2*)hi)[2 * i + 0] = __halves2half2(h0, h1);
    ((__half2*)hi)[2 * i + 1] = __halves2half2(h2, h3);
    ((__half2*)lo)[2 * i + 0] = __halves2half2(l0, l1);
    ((__half2*)lo)[2 * i + 1] = __halves2half2(l2, l3);
}

// x0 planes (slot0 only)
__global__ void u0_kernel(const float* __restrict__ action, const float* __restrict__ W_a,
                          const float* __restrict__ b_a,
                          __half* __restrict__ hi, __half* __restrict__ lo)
{
    int i = blockIdx.x * blockDim.x + threadIdx.x;
    if (i >= Bsz * Hn) return;
    int b = i >> 9, j = i & 511;
    float s = b_a[j];
    s = fmaf(action[b * 3 + 0], W_a[j * 3 + 0], s);
    s = fmaf(action[b * 3 + 1], W_a[j * 3 + 1], s);
    s = fmaf(action[b * 3 + 2], W_a[j * 3 + 2], s);
    __half h, l;
    split1h(s, h, l);
    hi[i] = h; lo[i] = l;
}

__device__ __forceinline__ float sigf(float x) { return 1.f / (1.f + __expf(-x)); }

// GRU gate: h' = (1-z)*n + z*h.  GIMODE: 0 = GI slice [B,3H]; 1 = bias-only
// row (GIt = b_ih, no row stride); 2 = token table (GIt = Gtab, tok via gt).
// One thread = 4 columns of one batch row (float4).
template <int GIMODE>
__global__ void gate_kernel(const float* __restrict__ GIt, const float* __restrict__ GH,
                            const float* __restrict__ hprev, float* __restrict__ houtF,
                            __half* __restrict__ hi, __half* __restrict__ lo,
                            const int* __restrict__ gt, int step)
{
    int i = blockIdx.x * blockDim.x + threadIdx.x;   // over B*H/4
    if (i >= Bsz * Hn / 4) return;
    int b  = i >> 7;
    int j4 = (i & 127) << 2;
    const float* gi;
    if (GIMODE == 0)      gi = GIt + (size_t)b * H3 + j4;
    else if (GIMODE == 1) gi = GIt + j4;
    else {
        int tok = gt[b * Tn + (step - 2)];
        gi = GIt + (size_t)tok * H3 + j4;
    }
    size_t o  = (size_t)b * H3 + j4;
    size_t ih = (size_t)b * Hn + j4;
    float4 gir = *(const float4*)(gi);
    float4 giz = *(const float4*)(gi + 512);
    float4 gin = *(const float4*)(gi + 1024);
    float4 ghr = *(const float4*)(GH + o);
    float4 ghz = *(const float4*)(GH + o + 512);
    float4 ghn = *(const float4*)(GH + o + 1024);
    float4 hp  = *(const float4*)(hprev + ih);
    float h[4];
    {
        float r0 = sigf(gir.x + ghr.x), r1 = sigf(gir.y + ghr.y);
        float r2 = sigf(gir.z + ghr.z), r3 = sigf(gir.w + ghr.w);
        float z0 = sigf(giz.x + ghz.x), z1 = sigf(giz.y + ghz.y);
        float z2 = sigf(giz.z + ghz.z), z3 = sigf(giz.w + ghz.w);
        float n0 = tanhf(gin.x + r0 * ghn.x), n1 = tanhf(gin.y + r1 * ghn.y);
        float n2 = tanhf(gin.z + r2 * ghn.z), n3 = tanhf(gin.w + r3 * ghn.w);
        h[0] = (1.f - z0) * n0 + z0 * hp.x;
        h[1] = (1.f - z1) * n1 + z1 * hp.y;
        h[2] = (1.f - z2) * n2 + z2 * hp.z;
        h[3] = (1.f - z3) * n3 + z3 * hp.w;
    }
    *(float4*)(houtF + ih) = make_float4(h[0], h[1], h[2], h[3]);
    __half h0, h1, h2, h3, l0, l1, l2, l3;
    split1h(h[0], h0, l0); split1h(h[1], h1, l1);
    split1h(h[2], h2, l2); split1h(h[3], h3, l3);
    __half2 hh01 = __halves2half2(h0, h1), hh23 = __halves2half2(h2, h3);
    __half2 ll01 = __halves2half2(l0, l1), ll23 = __halves2half2(l2, l3);
    *(__half2*)(hi + ih)     = hh01;
    *(__half2*)(hi + ih + 2) = hh23;
    *(__half2*)(lo + ih)     = ll01;
    *(__half2*)(lo + ih + 2) = ll23;
}

__global__ void copyf4_kernel(const float* __restrict__ src, float* __restrict__ dst)
{
    int i = blockIdx.x * blockDim.x + threadIdx.x;
    if (i >= (int)(BH / 4)) return;
    ((float4*)dst)[i] = ((const float4*)src)[i];
}

__global__ void heads_kernel(const float* __restrict__ h2, const float* __restrict__ W_r,
                             const float* __restrict__ b_r, const float* __restrict__ W_d,
                             const float* __restrict__ b_d,
                             float* __restrict__ outr, float* __restrict__ outd)
{
    int gw = (blockIdx.x * blockDim.x + threadIdx.x) >> 5;
    int lane = threadIdx.x & 31;
    if (gw >= Bsz) return;
    const float* hb = h2 + (size_t)gw * Hn;
    float sr = 0.f, sd = 0.f;
#pragma unroll
    for (int k = lane; k < Hn; k += 32) {
        float v = hb[k];
        sr = fmaf(v, W_r[k], sr);
        sd = fmaf(v, W_d[k], sd);
    }
#pragma unroll
    for (int o = 16; o > 0; o >>= 1) {
        sr += __shfl_down_sync(0xffffffffu, sr, o);
        sd += __shfl_down_sync(0xffffffffu, sd, o);
    }
    if (lane == 0) { outr[gw] = sr + b_r[0]; outd[gw] = sd + b_d[0]; }
}

// ---------------------------------------------------------------------------
extern "C" void kernel_launch(void* const* d_in, const int* in_sizes, int n_in,
                              void* d_out, int out_size)
{
    const float* action      = (const float*)d_in[0];
    const float* prev_hidden = (const float*)d_in[1];
    const int*   gt          = (const int*)d_in[2];
    const float* W_a         = (const float*)d_in[3];
    const float* b_a         = (const float*)d_in[4];
    const float* emb         = (const float*)d_in[5];
    const float* W_tp        = (const float*)d_in[6];
    const float* b_tp        = (const float*)d_in[7];
    const float* W_ih        = (const float*)d_in[8];
    const float* W_hh        = (const float*)d_in[9];
    const float* b_ih        = (const float*)d_in[10];
    const float* b_hh        = (const float*)d_in[11];
    const float* W_out       = (const float*)d_in[12];
    const float* b_out       = (const float*)d_in[13];
    const float* W_r         = (const float*)d_in[14];
    const float* b_r         = (const float*)d_in[15];
    const float* W_d         = (const float*)d_in[16];
    const float* b_d         = (const float*)d_in[17];
    float* out = (float*)d_out;

    static bool attr_done = false;
    if (!attr_done) {
        cudaFuncSetAttribute(gemm_h2<0>, cudaFuncAttributeMaxDynamicSharedMemorySize, GEMM_SMEM);
        cudaFuncSetAttribute(gemm_h2<2>, cudaFuncAttributeMaxDynamicSharedMemorySize, GEMM_SMEM);
        cudaFuncSetAttribute(gemm_h2_n64, cudaFuncAttributeMaxDynamicSharedMemorySize, GEMM_SMEM_N64);
        attr_done = true;
    }

    __half *uAh, *uAl, *uBh, *uBl, *pqh, *pql;
    __half *wih, *whh, *wo, *wt, *embh, *embl, *Pqh, *Pql;
    float *hseqF, *GI, *GH, *P, *Gtab;
    cudaGetSymbolAddress((void**)&uAh, g_uA_hi);  cudaGetSymbolAddress((void**)&uAl, g_uA_lo);
    cudaGetSymbolAddress((void**)&uBh, g_uB_hi);  cudaGetSymbolAddress((void**)&uBl, g_uB_lo);
    cudaGetSymbolAddress((void**)&pqh, g_pq_hi);  cudaGetSymbolAddress((void**)&pql, g_pq_lo);
    cudaGetSymbolAddress((void**)&wih, g_wih);    cudaGetSymbolAddress((void**)&whh, g_whh);
    cudaGetSymbolAddress((void**)&wo,  g_wo);     cudaGetSymbolAddress((void**)&wt,  g_wt);
    cudaGetSymbolAddress((void**)&embh, g_embh);  cudaGetSymbolAddress((void**)&embl, g_embl);
    cudaGetSymbolAddress((void**)&Pqh, g_Pqh);    cudaGetSymbolAddress((void**)&Pql, g_Pql);
    cudaGetSymbolAddress((void**)&hseqF, g_hseqF);
    cudaGetSymbolAddress((void**)&GI, g_GI);
    cudaGetSymbolAddress((void**)&GH, g_GH);
    cudaGetSymbolAddress((void**)&P, g_P);
    cudaGetSymbolAddress((void**)&Gtab, g_Gtab);

    float* outLogits = out;
    float* outReward = out + (size_t)Bsz * Tn * Cn;
    float* outDone   = outReward + Bsz;
    float* outFinal  = outDone + Bsz;

    const int gateGrid = (Bsz * Hn / 4 + 255) / 256;

    // [0] all weight conversions
    convW<<<(1376256 + 255) / 256, 256>>>(W_ih, W_hh, W_out, W_tp, emb,
                                          wih, whh, wo, wt, embh, embl);
    // [1] prev hidden -> fp16 planes
    split2_kernel<<<((int)(Ln * BH / 4) + 255) / 256, 256>>>(
        prev_hidden, pqh, pql, (int)(Ln * BH / 4));
    // [2] x0 -> planes (slot 0)
    u0_kernel<<<(Bsz * Hn + 255) / 256, 256>>>(action, W_a, b_a, uAh, uAl);
    // [3] P = emb @ W_tp.T + b_tp
    gemm_h2<0><<<dim3(4, 4), 256, GEMM_SMEM>>>(embh, embl, wt, b_tp, P, Hn);
    // [4] P -> fp16 planes
    split2_kernel<<<((Cn * Hn / 4) + 255) / 256, 256>>>(P, Pqh, Pql, Cn * Hn / 4);
    // [5] hidden GEMM (l=0, t=0)  <-- ncu -s 5 captures this
    gemm_h2_n64<<<dim3(24, 32), 256, GEMM_SMEM_N64>>>(
        pqh, pql, whh, b_hh, GH, H3);
    // [6] Gtab = Pq @ W_ih0.T + b_ih0   [512 x 1536]
    gemm_h2<0><<<dim3(12, 4), 256, GEMM_SMEM>>>(Pqh, Pql, wih, b_ih, Gtab, H3);
    // [7] GI slot0 = x0 @ W_ih0.T + b_ih0
    gemm_h2<0><<<dim3(12, 32), 256, GEMM_SMEM>>>(uAh, uAl, wih, b_ih, GI, H3);

    // ---- layer 0 (token-table GI path) ----
    __half *Uh = uAh, *Ul = uAl, *Oh = uBh, *Ol = uBl;
    for (int t = 0; t < NSTEP; t++) {
        if (t > 0) {    // t=0 hidden GEMM already launched at [5]
            gemm_h2_n64<<<dim3(24, 32), 256, GEMM_SMEM_N64>>>(
                Oh + (size_t)(t - 1) * BH, Ol + (size_t)(t - 1) * BH,
                whh, b_hh, GH, H3);
        }
        const float* hpF = t ? (hseqF + (size_t)(t - 1) * BH) : prev_hidden;
        float* hF = hseqF + (size_t)t * BH;
        __half* oh = Oh + (size_t)t * BH;
        __half* ol = Ol + (size_t)t * BH;
        if (t == 0)
            gate_kernel<0><<<gateGrid, 256>>>(GI, GH, hpF, hF, oh, ol, gt, t);
        else if (t == 1)
            gate_kernel<1><<<gateGrid, 256>>>(b_ih, GH, hpF, hF, oh, ol, gt, t);
        else
            gate_kernel<2><<<gateGrid, 256>>>(Gtab, GH, hpF, hF, oh, ol, gt, t);
    }
    copyf4_kernel<<<((int)(BH / 4) + 255) / 256, 256>>>(
        hseqF + (size_t)16 * BH, outFinal);
    { __half* tp = Uh; Uh = Oh; Oh = tp; tp = Ul; Ul = Ol; Ol = tp; }

    // ---- layers 1, 2 (batched GI) ----
    for (int l = 1; l < Ln; l++) {
        gemm_h2<0><<<dim3(12, 544), 256, GEMM_SMEM>>>(
            Uh, Ul, wih + (size_t)l * H3 * Hn, b_ih + l * H3, GI, H3);
        for (int t = 0; t < NSTEP; t++) {
            const __half* ph = t ? (Oh + (size_t)(t - 1) * BH) : (pqh + (size_t)l * BH);
            const __half* pl = t ? (Ol + (size_t)(t - 1) * BH) : (pql + (size_t)l * BH);
            gemm_h2_n64<<<dim3(24, 32), 256, GEMM_SMEM_N64>>>(
                ph, pl, whh + (size_t)l * H3 * Hn, b_hh + l * H3, GH, H3);
            const float* hpF = t ? (hseqF + (size_t)(t - 1) * BH)
                                 : (prev_hidden + (size_t)l * BH);
            gate_kernel<0><<<gateGrid, 256>>>(
                GI + (size_t)t * BH3, GH, hpF, hseqF + (size_t)t * BH,
                Oh + (size_t)t * BH, Ol + (size_t)t * BH, gt, t);
        }
        copyf4_kernel<<<((int)(BH / 4) + 255) / 256, 256>>>(
            hseqF + (size_t)16 * BH, outFinal + (size_t)l * BH);
        __half* tp;
        tp = Uh; Uh = Oh; Oh = tp;
        tp = Ul; Ul = Ol; Ol = tp;
    }

    // ---- logits over scan slots 1..16 ----
    gemm_h2<2><<<dim3(4, 512), 256, GEMM_SMEM>>>(
        Uh + BH, Ul + BH, wo, b_out, outLogits, 0);

    // ---- reward / done heads ----
    heads_kernel<<<(Bsz * 32 + 255) / 256, 256>>>(
        hseqF, W_r, b_r, W_d, b_d, outReward, outDone);
}

// round 7
// speedup vs baseline: 3.3033x; 1.0364x over previous
#include <cuda_runtime.h>
#include <cuda_fp16.h>
#include <cstdint>
#include <math.h>

// ---------------- problem constants ----------------
#define Bsz   4096
#define Hn    512
#define H3    1536
#define Ln    3
#define Tn    16
#define Cn    512
#define NSTEP 17
#define KDIM  512
#define NCH   8            // K chunks of 64 fp16 (128B rows)

static const size_t BH  = (size_t)Bsz * Hn;
static const size_t BH3 = (size_t)Bsz * H3;

// ---------------- persistent device scratch ----------------
__device__ __align__(128) __half g_uA_hi[(size_t)NSTEP * Bsz * Hn];
__device__ __align__(128) __half g_uA_lo[(size_t)NSTEP * Bsz * Hn];
__device__ __align__(128) __half g_uB_hi[(size_t)NSTEP * Bsz * Hn];
__device__ __align__(128) __half g_uB_lo[(size_t)NSTEP * Bsz * Hn];
__device__ __align__(128) __half g_pq_hi[(size_t)Ln * Bsz * Hn];
__device__ __align__(128) __half g_pq_lo[(size_t)Ln * Bsz * Hn];
__device__ __align__(128) float  g_hseqF[(size_t)NSTEP * Bsz * Hn];
__device__ __align__(128) float  g_GI[(size_t)NSTEP * Bsz * H3];
__device__ __align__(128) __half g_wih[(size_t)Ln * H3 * Hn];
__device__ __align__(128) __half g_whh[(size_t)Ln * H3 * Hn];
__device__ __align__(128) __half g_wo[(size_t)Cn * Hn];
__device__ __align__(128) __half g_wt[(size_t)Hn * Hn];
__device__ __align__(128) __half g_embh[(size_t)Cn * Hn];
__device__ __align__(128) __half g_embl[(size_t)Cn * Hn];
__device__ __align__(128) float  g_P[(size_t)Cn * Hn];
__device__ __align__(128) __half g_Pqh[(size_t)Cn * Hn];
__device__ __align__(128) __half g_Pql[(size_t)Cn * Hn];
__device__ __align__(128) float  g_Gtab[(size_t)Cn * H3];

// ---------------- PTX helpers ----------------
__device__ __forceinline__ uint32_t smem_u32(const void* p) {
    uint32_t a;
    asm("{ .reg .u64 t; cvta.to.shared.u64 t, %1; cvt.u32.u64 %0, t; }" : "=r"(a) : "l"(p));
    return a;
}
__device__ __forceinline__ void cpasync16(uint32_t s, const void* g) {
    asm volatile("cp.async.cg.shared.global [%0], [%1], 16;" :: "r"(s), "l"(g));
}
__device__ __forceinline__ void cp_commit() {
    asm volatile("cp.async.commit_group;" ::: "memory");
}
template <int N> __device__ __forceinline__ void cp_wait() {
    asm volatile("cp.async.wait_group %0;" :: "n"(N) : "memory");
}
__device__ __forceinline__ void ldsm4(uint32_t& r0, uint32_t& r1, uint32_t& r2, uint32_t& r3,
                                      uint32_t addr) {
    asm volatile("ldmatrix.sync.aligned.m8n8.x4.shared.b16 {%0,%1,%2,%3}, [%4];"
                 : "=r"(r0), "=r"(r1), "=r"(r2), "=r"(r3) : "r"(addr));
}
__device__ __forceinline__ void hmma16816(float* d, const uint32_t* a, uint32_t b0, uint32_t b1) {
    asm volatile(
        "mma.sync.aligned.m16n8k16.row.col.f32.f16.f16.f32 "
        "{%0,%1,%2,%3}, {%4,%5,%6,%7}, {%8,%9}, {%0,%1,%2,%3};"
        : "+f"(d[0]), "+f"(d[1]), "+f"(d[2]), "+f"(d[3])
        : "r"(a[0]), "r"(a[1]), "r"(a[2]), "r"(a[3]), "r"(b0), "r"(b1));
}

#define GEMM_SMEM (2 * 49152)   // 128x128 gemm: 2 stages x 48KB
#define STEP_SMEM (2 * 45056)   // fused step: 2 stages x 44KB

__device__ __forceinline__ float sigf(float x) { return 1.f / (1.f + __expf(-x)); }
__device__ __forceinline__ void split1h(float x, __half& h, __half& l) {
    h = __float2half_rn(x);
    l = __float2half_rn(x - __half2float(h));
}

// ---------------------------------------------------------------------------
// fp16x2 GEMM, 128x128 tile (batched GEMMs: GI, P, Gtab, logits).
// ---------------------------------------------------------------------------
template <int MODE>
__global__ void __launch_bounds__(256, 2)
gemm_h2(const __half* __restrict__ Ahi, const __half* __restrict__ Alo,
        const __half* __restrict__ Bh,
        const float* __restrict__ bias, float* __restrict__ C, int ldc)
{
    extern __shared__ __align__(128) char smem[];
    const uint32_t sb = smem_u32(smem);
    const int tid  = threadIdx.x;
    const int wid  = tid >> 5, lane = tid & 31;
    const int wM   = wid >> 1;
    const int wN   = wid & 1;
    const int m0   = blockIdx.y << 7, n0 = blockIdx.x << 7;

    const char* gAh = (const char*)(Ahi + (size_t)m0 * KDIM);
    const char* gAl = (const char*)(Alo + (size_t)m0 * KDIM);
    const char* gB  = (const char*)(Bh  + (size_t)n0 * KDIM);

    int srow[4], soff[4]; uint32_t sso[4];
#pragma unroll
    for (int q = 0; q < 4; q++) {
        int id = tid * 4 + q;
        srow[q] = id >> 3;
        soff[q] = (id & 7) << 4;
        sso[q]  = (uint32_t)((srow[q] << 7) | (soff[q] ^ ((srow[q] & 7) << 4)));
    }

    const int lr16 = lane & 15;
    const int lhi  = (lane >> 4) << 4;
    uint32_t aBase[2], aXr[2];
#pragma unroll
    for (int mt = 0; mt < 2; mt++) {
        int r = wM * 32 + mt * 16 + lr16;
        aBase[mt] = (uint32_t)(r << 7);
        aXr[mt]   = ((r & 7) << 4);
    }
    uint32_t bBase[4], bXr[4];
#pragma unroll
    for (int nt = 0; nt < 4; nt++) {
        int r = wN * 64 + nt * 16 + lr16;
        bBase[nt] = (uint32_t)(r << 7);
        bXr[nt]   = ((r & 7) << 4);
    }

    float acc[2][8][4];
#pragma unroll
    for (int i = 0; i < 2; i++)
#pragma unroll
        for (int j = 0; j < 8; j++)
#pragma unroll
            for (int v = 0; v < 4; v++) acc[i][j][v] = 0.f;

    auto load_chunk = [&](int s, int c) {
        const uint32_t st = sb + s * 49152;
        const int cb = c * 128;
#pragma unroll
        for (int q = 0; q < 4; q++) {
            int go = srow[q] * 1024 + cb + soff[q];
            cpasync16(st +         sso[q], gAh + go);
            cpasync16(st + 16384 + sso[q], gAl + go);
            cpasync16(st + 32768 + sso[q], gB  + go);
        }
        cp_commit();
    };

    load_chunk(0, 0);

    for (int c = 0; c < NCH; c++) {
        const int s = c & 1;
        if (c + 1 < NCH) { load_chunk(s ^ 1, c + 1); cp_wait<1>(); }
        else             { cp_wait<0>(); }
        __syncthreads();

        const uint32_t stA0 = sb + s * 49152;
        const uint32_t stA1 = stA0 + 16384;
        const uint32_t stB0 = stA0 + 32768;

#pragma unroll
        for (int k16 = 0; k16 < 4; k16++) {
            const uint32_t ko = (uint32_t)(k16 * 32 + lhi);
            uint32_t ah[2][4], al[2][4];
#pragma unroll
            for (int mt = 0; mt < 2; mt++) {
                ldsm4(ah[mt][0], ah[mt][1], ah[mt][2], ah[mt][3],
                      stA0 + aBase[mt] + (ko ^ aXr[mt]));
                ldsm4(al[mt][0], al[mt][1], al[mt][2], al[mt][3],
                      stA1 + aBase[mt] + (ko ^ aXr[mt]));
            }
            uint32_t bh[4][4];
#pragma unroll
            for (int nt = 0; nt < 4; nt++)
                ldsm4(bh[nt][0], bh[nt][1], bh[nt][2], bh[nt][3],
                      stB0 + bBase[nt] + (ko ^ bXr[nt]));
#pragma unroll
            for (int mt = 0; mt < 2; mt++)
#pragma unroll
                for (int nt = 0; nt < 4; nt++) {
                    hmma16816(acc[mt][2 * nt + 0], ah[mt], bh[nt][0], bh[nt][2]);
                    hmma16816(acc[mt][2 * nt + 1], ah[mt], bh[nt][1], bh[nt][3]);
                    hmma16816(acc[mt][2 * nt + 0], al[mt], bh[nt][0], bh[nt][2]);
                    hmma16816(acc[mt][2 * nt + 1], al[mt], bh[nt][1], bh[nt][3]);
                }
        }
        __syncthreads();
    }

    const int lr = lane >> 2;
    const int lc = (lane & 3) << 1;
#pragma unroll
    for (int mt = 0; mt < 2; mt++) {
        const int mBase = m0 + wM * 32 + mt * 16 + lr;
#pragma unroll
        for (int nt = 0; nt < 8; nt++) {
            const int n = n0 + wN * 64 + nt * 8 + lc;
            const float b0 = bias[n], b1 = bias[n + 1];
            float2 v0 = make_float2(acc[mt][nt][0] + b0, acc[mt][nt][1] + b1);
            float2 v1 = make_float2(acc[mt][nt][2] + b0, acc[mt][nt][3] + b1);
            size_t o0, o1;
            if (MODE == 2) {
                int bb0 = mBase & (Bsz - 1),       t0 = mBase >> 12;
                int bb1 = (mBase + 8) & (Bsz - 1), t1 = (mBase + 8) >> 12;
                o0 = (size_t)bb0 * (Tn * Cn) + (size_t)t0 * Cn + n;
                o1 = (size_t)bb1 * (Tn * Cn) + (size_t)t1 * Cn + n;
            } else {
                o0 = (size_t)mBase * ldc + n;
                o1 = (size_t)(mBase + 8) * ldc + n;
            }
            *(float2*)(C + o0) = v0;
            *(float2*)(C + o1) = v1;
        }
    }
}

// ---------------------------------------------------------------------------
// FUSED GRU step: hidden GEMM (all 3 gates for a 32-wide j slice) + gate math.
// CTA tile: 128 batch rows x 32 j-cols -> 96 GH columns (r|z|n packed in smem).
// GIMODE: 0 = GI slice [B,3H]; 1 = bias-only row (GIt=b_ih); 2 = token table.
// Outputs: fp32 state houtF + fp16 hi/lo planes of h'.
// ---------------------------------------------------------------------------
template <int GIMODE>
__global__ void __launch_bounds__(256)
gru_step(const __half* __restrict__ Ahi, const __half* __restrict__ Alo,
         const __half* __restrict__ W, const float* __restrict__ bhh,
         const float* __restrict__ GIt, const int* __restrict__ gt, int step,
         const float* __restrict__ hprevF, float* __restrict__ houtF,
         __half* __restrict__ hi, __half* __restrict__ lo)
{
    extern __shared__ __align__(128) char smem[];
    const uint32_t sb = smem_u32(smem);
    const int tid  = threadIdx.x;
    const int wid  = tid >> 5, lane = tid & 31;
    const int wM   = wid >> 1;             // 0..3: m offset 32 each
    const int wN   = wid & 1;              // 0..1: j offset 16 each
    const int m0   = blockIdx.y << 7;      // batch tile
    const int j0   = blockIdx.x << 5;      // 32 j-cols

    const char* gAh = (const char*)(Ahi + (size_t)m0 * KDIM);
    const char* gAl = (const char*)(Alo + (size_t)m0 * KDIM);
    const char* gW  = (const char*)W;

    // A cp.async coords (4 segs per plane per thread)
    int srow[4], soff[4]; uint32_t sso[4];
#pragma unroll
    for (int q = 0; q < 4; q++) {
        int id = tid * 4 + q;
        srow[q] = id >> 3;
        soff[q] = (id & 7) << 4;
        sso[q]  = (uint32_t)((srow[q] << 7) | (soff[q] ^ ((srow[q] & 7) << 4)));
    }
    // B cp.async coords: 96 rows x 8 segs = 768 -> 3 per thread
    int bgr[3], boff[3]; uint32_t bso[3];
#pragma unroll
    for (int q = 0; q < 3; q++) {
        int id = tid * 3 + q;
        int rb = id >> 3;                      // 0..95
        boff[q] = (id & 7) << 4;
        bgr[q]  = j0 + (rb & 31) + (rb >> 5) * 512;   // global W row
        bso[q]  = (uint32_t)((rb << 7) | (boff[q] ^ ((rb & 7) << 4)));
    }

    const int lr16 = lane & 15;
    const int lhi  = (lane >> 4) << 4;
    uint32_t aBase[2], aXr[2];
#pragma unroll
    for (int mt = 0; mt < 2; mt++) {
        int r = wM * 32 + mt * 16 + lr16;
        aBase[mt] = (uint32_t)(r << 7);
        aXr[mt]   = ((r & 7) << 4);
    }
    uint32_t bBase[3], bXr[3];
#pragma unroll
    for (int g = 0; g < 3; g++) {
        int r = wN * 16 + g * 32 + lr16;       // row within 96-row B tile
        bBase[g] = (uint32_t)(r << 7);
        bXr[g]   = ((r & 7) << 4);
    }

    float acc[2][3][2][4];                     // [mt][gate][atom][quad]
#pragma unroll
    for (int i = 0; i < 2; i++)
#pragma unroll
        for (int g = 0; g < 3; g++)
#pragma unroll
            for (int a = 0; a < 2; a++)
#pragma unroll
                for (int v = 0; v < 4; v++) acc[i][g][a][v] = 0.f;

    auto load_chunk = [&](int s, int c) {
        const uint32_t st = sb + s * 45056;
        const int cb = c * 128;
#pragma unroll
        for (int q = 0; q < 4; q++) {
            int go = srow[q] * 1024 + cb + soff[q];
            cpasync16(st +         sso[q], gAh + go);
            cpasync16(st + 16384 + sso[q], gAl + go);
        }
#pragma unroll
        for (int q = 0; q < 3; q++) {
            int go = bgr[q] * 1024 + cb + boff[q];
            cpasync16(st + 32768 + bso[q], gW + go);
        }
        cp_commit();
    };

    load_chunk(0, 0);

    for (int c = 0; c < NCH; c++) {
        const int s = c & 1;
        if (c + 1 < NCH) { load_chunk(s ^ 1, c + 1); cp_wait<1>(); }
        else             { cp_wait<0>(); }
        __syncthreads();

        const uint32_t stA0 = sb + s * 45056;
        const uint32_t stA1 = stA0 + 16384;
        const uint32_t stB0 = stA0 + 32768;

#pragma unroll
        for (int k16 = 0; k16 < 4; k16++) {
            const uint32_t ko = (uint32_t)(k16 * 32 + lhi);
            uint32_t ah[2][4], al[2][4];
#pragma unroll
            for (int mt = 0; mt < 2; mt++) {
                ldsm4(ah[mt][0], ah[mt][1], ah[mt][2], ah[mt][3],
                      stA0 + aBase[mt] + (ko ^ aXr[mt]));
                ldsm4(al[mt][0], al[mt][1], al[mt][2], al[mt][3],
                      stA1 + aBase[mt] + (ko ^ aXr[mt]));
            }
            uint32_t bh[3][4];
#pragma unroll
            for (int g = 0; g < 3; g++)
                ldsm4(bh[g][0], bh[g][1], bh[g][2], bh[g][3],
                      stB0 + bBase[g] + (ko ^ bXr[g]));
#pragma unroll
            for (int mt = 0; mt < 2; mt++)
#pragma unroll
                for (int g = 0; g < 3; g++) {
                    hmma16816(acc[mt][g][0], ah[mt], bh[g][0], bh[g][2]);
                    hmma16816(acc[mt][g][1], ah[mt], bh[g][1], bh[g][3]);
                    hmma16816(acc[mt][g][0], al[mt], bh[g][0], bh[g][2]);
                    hmma16816(acc[mt][g][1], al[mt], bh[g][1], bh[g][3]);
                }
        }
        __syncthreads();
    }

    // ---- fused GRU gate epilogue ----
    const int lr = lane >> 2;
    const int lc = (lane & 3) << 1;
#pragma unroll
    for (int mt = 0; mt < 2; mt++) {
        const int mBase = m0 + wM * 32 + mt * 16 + lr;
#pragma unroll
        for (int a = 0; a < 2; a++) {
            const int j = j0 + wN * 16 + a * 8 + lc;
            const float2 bR = *(const float2*)(bhh + j);
            const float2 bZ = *(const float2*)(bhh + 512 + j);
            const float2 bN = *(const float2*)(bhh + 1024 + j);
#pragma unroll
            for (int hh = 0; hh < 2; hh++) {
                const int row = mBase + hh * 8;
                const int vi = hh * 2;
                const float* gi;
                if (GIMODE == 0)      gi = GIt + (size_t)row * H3 + j;
                else if (GIMODE == 1) gi = GIt + j;
                else {
                    int tok = gt[row * Tn + (step - 2)];
                    gi = GIt + (size_t)tok * H3 + j;
                }
                float2 gR = *(const float2*)(gi);
                float2 gZ = *(const float2*)(gi + 512);
                float2 gN = *(const float2*)(gi + 1024);
                float2 hp = *(const float2*)(hprevF + (size_t)row * Hn + j);
                float r0 = sigf(gR.x + acc[mt][0][a][vi]     + bR.x);
                float r1 = sigf(gR.y + acc[mt][0][a][vi + 1] + bR.y);
                float z0 = sigf(gZ.x + acc[mt][1][a][vi]     + bZ.x);
                float z1 = sigf(gZ.y + acc[mt][1][a][vi + 1] + bZ.y);
                float n0 = tanhf(gN.x + r0 * (acc[mt][2][a][vi]     + bN.x));
                float n1 = tanhf(gN.y + r1 * (acc[mt][2][a][vi + 1] + bN.y));
                float h0 = (1.f - z0) * n0 + z0 * hp.x;
                float h1 = (1.f - z1) * n1 + z1 * hp.y;
                size_t oh = (size_t)row * Hn + j;
                *(float2*)(houtF + oh) = make_float2(h0, h1);
                __half a0, a1, c0, c1;
                split1h(h0, a0, c0); split1h(h1, a1, c1);
                *(__half2*)(hi + oh) = __halves2half2(a0, a1);
                *(__half2*)(lo + oh) = __halves2half2(c0, c1);
            }
        }
    }
}

// ---------------- elementwise kernels ----------------
__global__ void convW(const float* __restrict__ W_ih, const float* __restrict__ W_hh,
                      const float* __restrict__ W_out, const float* __restrict__ W_tp,
                      const float* __restrict__ emb,
                      __half* __restrict__ wih, __half* __restrict__ whh,
                      __half* __restrict__ wo,  __half* __restrict__ wt,
                      __half* __restrict__ embh, __half* __restrict__ embl)
{
    int i = blockIdx.x * blockDim.x + threadIdx.x;
    if (i >= 1376256) return;
    if (i < 1310720) {
        const float* s; __half* d; int j;
        if (i < 589824)       { s = W_ih;  d = wih; j = i; }
        else if (i < 1179648) { s = W_hh;  d = whh; j = i - 589824; }
        else if (i < 1245184) { s = W_out; d = wo;  j = i - 1179648; }
        else                  { s = W_tp;  d = wt;  j = i - 1245184; }
        float4 v = ((const float4*)s)[j];
        ((__half2*)d)[2 * j + 0] = __floats2half2_rn(v.x, v.y);
        ((__half2*)d)[2 * j + 1] = __floats2half2_rn(v.z, v.w);
    } else {
        int j = i - 1310720;
        float4 v = ((const float4*)emb)[j];
        __half h0, h1, h2, h3, l0, l1, l2, l3;
        split1h(v.x, h0, l0); split1h(v.y, h1, l1);
        split1h(v.z, h2, l2); split1h(v.w, h3, l3);
        ((__half2*)embh)[2 * j + 0] = __halves2half2(h0, h1);
        ((__half2*)embh)[2 * j + 1] = __halves2half2(h2, h3);
        ((__half2*)embl)[2 * j + 0] = __halves2half2(l0, l1);
        ((__half2*)embl)[2 * j + 1] = __halves2half2(l2, l3);
    }
}

__global__ void split2_kernel(const float* __restrict__ src,
                              __half* __restrict__ hi, __half* __restrict__ lo, int n4)
{
    int i = blockIdx.x * blockDim.x + threadIdx.x;
    if (i >= n4) return;
    float4 v = ((const float4*)src)[i];
    __half h0, h1, h2, h3, l0, l1, l2, l3;
    split1h(v.x, h0, l0); split1h(v.y, h1, l1);
    split1h(v.z, h2, l2); split1h(v.w, h3, l3);
    ((__half2*)hi)[2 * i + 0] = __halves2half2(h0, h1);
    ((__half2*)hi)[2 * i + 1] = __halves2half2(h2, h3);
    ((__half2*)lo)[2 * i + 0] = __halves2half2(l0, l1);
    ((__half2*)lo)[2 * i + 1] = __halves2half2(l2, l3);
}

__global__ void u0_kernel(const float* __restrict__ action, const float* __restrict__ W_a,
                          const float* __restrict__ b_a,
                          __half* __restrict__ hi, __half* __restrict__ lo)
{
    int i = blockIdx.x * blockDim.x + threadIdx.x;
    if (i >= Bsz * Hn) return;
    int b = i >> 9, j = i & 511;
    float s = b_a[j];
    s = fmaf(action[b * 3 + 0], W_a[j * 3 + 0], s);
    s = fmaf(action[b * 3 + 1], W_a[j * 3 + 1], s);
    s = fmaf(action[b * 3 + 2], W_a[j * 3 + 2], s);
    __half h, l;
    split1h(s, h, l);
    hi[i] = h; lo[i] = l;
}

__global__ void copyf4_kernel(const float* __restrict__ src, float* __restrict__ dst)
{
    int i = blockIdx.x * blockDim.x + threadIdx.x;
    if (i >= (int)(BH / 4)) return;
    ((float4*)dst)[i] = ((const float4*)src)[i];
}

__global__ void heads_kernel(const float* __restrict__ h2, const float* __restrict__ W_r,
                             const float* __restrict__ b_r, const float* __restrict__ W_d,
                             const float* __restrict__ b_d,
                             float* __restrict__ outr, float* __restrict__ outd)
{
    int gw = (blockIdx.x * blockDim.x + threadIdx.x) >> 5;
    int lane = threadIdx.x & 31;
    if (gw >= Bsz) return;
    const float* hb = h2 + (size_t)gw * Hn;
    float sr = 0.f, sd = 0.f;
#pragma unroll
    for (int k = lane; k < Hn; k += 32) {
        float v = hb[k];
        sr = fmaf(v, W_r[k], sr);
        sd = fmaf(v, W_d[k], sd);
    }
#pragma unroll
    for (int o = 16; o > 0; o >>= 1) {
        sr += __shfl_down_sync(0xffffffffu, sr, o);
        sd += __shfl_down_sync(0xffffffffu, sd, o);
    }
    if (lane == 0) { outr[gw] = sr + b_r[0]; outd[gw] = sd + b_d[0]; }
}

// ---------------------------------------------------------------------------
extern "C" void kernel_launch(void* const* d_in, const int* in_sizes, int n_in,
                              void* d_out, int out_size)
{
    const float* action      = (const float*)d_in[0];
    const float* prev_hidden = (const float*)d_in[1];
    const int*   gt          = (const int*)d_in[2];
    const float* W_a         = (const float*)d_in[3];
    const float* b_a         = (const float*)d_in[4];
    const float* emb         = (const float*)d_in[5];
    const float* W_tp        = (const float*)d_in[6];
    const float* b_tp        = (const float*)d_in[7];
    const float* W_ih        = (const float*)d_in[8];
    const float* W_hh        = (const float*)d_in[9];
    const float* b_ih        = (const float*)d_in[10];
    const float* b_hh        = (const float*)d_in[11];
    const float* W_out       = (const float*)d_in[12];
    const float* b_out       = (const float*)d_in[13];
    const float* W_r         = (const float*)d_in[14];
    const float* b_r         = (const float*)d_in[15];
    const float* W_d         = (const float*)d_in[16];
    const float* b_d         = (const float*)d_in[17];
    float* out = (float*)d_out;

    static bool attr_done = false;
    if (!attr_done) {
        cudaFuncSetAttribute(gemm_h2<0>, cudaFuncAttributeMaxDynamicSharedMemorySize, GEMM_SMEM);
        cudaFuncSetAttribute(gemm_h2<2>, cudaFuncAttributeMaxDynamicSharedMemorySize, GEMM_SMEM);
        cudaFuncSetAttribute(gru_step<0>, cudaFuncAttributeMaxDynamicSharedMemorySize, STEP_SMEM);
        cudaFuncSetAttribute(gru_step<1>, cudaFuncAttributeMaxDynamicSharedMemorySize, STEP_SMEM);
        cudaFuncSetAttribute(gru_step<2>, cudaFuncAttributeMaxDynamicSharedMemorySize, STEP_SMEM);
        attr_done = true;
    }

    __half *uAh, *uAl, *uBh, *uBl, *pqh, *pql;
    __half *wih, *whh, *wo, *wt, *embh, *embl, *Pqh, *Pql;
    float *hseqF, *GI, *P, *Gtab;
    cudaGetSymbolAddress((void**)&uAh, g_uA_hi);  cudaGetSymbolAddress((void**)&uAl, g_uA_lo);
    cudaGetSymbolAddress((void**)&uBh, g_uB_hi);  cudaGetSymbolAddress((void**)&uBl, g_uB_lo);
    cudaGetSymbolAddress((void**)&pqh, g_pq_hi);  cudaGetSymbolAddress((void**)&pql, g_pq_lo);
    cudaGetSymbolAddress((void**)&wih, g_wih);    cudaGetSymbolAddress((void**)&whh, g_whh);
    cudaGetSymbolAddress((void**)&wo,  g_wo);     cudaGetSymbolAddress((void**)&wt,  g_wt);
    cudaGetSymbolAddress((void**)&embh, g_embh);  cudaGetSymbolAddress((void**)&embl, g_embl);
    cudaGetSymbolAddress((void**)&Pqh, g_Pqh);    cudaGetSymbolAddress((void**)&Pql, g_Pql);
    cudaGetSymbolAddress((void**)&hseqF, g_hseqF);
    cudaGetSymbolAddress((void**)&GI, g_GI);
    cudaGetSymbolAddress((void**)&P, g_P);
    cudaGetSymbolAddress((void**)&Gtab, g_Gtab);

    float* outLogits = out;
    float* outReward = out + (size_t)Bsz * Tn * Cn;
    float* outDone   = outReward + Bsz;
    float* outFinal  = outDone + Bsz;

    // [0] weights -> fp16
    convW<<<(1376256 + 255) / 256, 256>>>(W_ih, W_hh, W_out, W_tp, emb,
                                          wih, whh, wo, wt, embh, embl);
    // [1] prev hidden -> fp16 planes
    split2_kernel<<<((int)(Ln * BH / 4) + 255) / 256, 256>>>(
        prev_hidden, pqh, pql, (int)(Ln * BH / 4));
    // [2] x0 -> planes
    u0_kernel<<<(Bsz * Hn + 255) / 256, 256>>>(action, W_a, b_a, uAh, uAl);
    // [3] GI slot0 = x0 @ W_ih0.T + b_ih0  <-- ncu captures launch index 3
    gemm_h2<0><<<dim3(12, 32), 256, GEMM_SMEM>>>(uAh, uAl, wih, b_ih, GI, H3);
    // [4] P = emb @ W_tp.T + b_tp
    gemm_h2<0><<<dim3(4, 4), 256, GEMM_SMEM>>>(embh, embl, wt, b_tp, P, Hn);
    // [5] P -> fp16 planes
    split2_kernel<<<((Cn * Hn / 4) + 255) / 256, 256>>>(P, Pqh, Pql, Cn * Hn / 4);
    // [6] Gtab = Pq @ W_ih0.T + b_ih0   [512 x 1536]
    gemm_h2<0><<<dim3(12, 4), 256, GEMM_SMEM>>>(Pqh, Pql, wih, b_ih, Gtab, H3);

    const dim3 stepGrid(16, 32);

    // ---- layer 0 (token-table GI path), fused steps ----
    __half *Uh = uAh, *Ul = uAl, *Oh = uBh, *Ol = uBl;
    for (int t = 0; t < NSTEP; t++) {
        const __half* ph = t ? (Oh + (size_t)(t - 1) * BH) : pqh;
        const __half* pl = t ? (Ol + (size_t)(t - 1) * BH) : pql;
        const float* hpF = t ? (hseqF + (size_t)(t - 1) * BH) : prev_hidden;
        float*  hF = hseqF + (size_t)t * BH;
        __half* oh = Oh + (size_t)t * BH;
        __half* ol = Ol + (size_t)t * BH;
        if (t == 0)
            gru_step<0><<<stepGrid, 256, STEP_SMEM>>>(ph, pl, whh, b_hh,
                                                      GI, gt, t, hpF, hF, oh, ol);
        else if (t == 1)
            gru_step<1><<<stepGrid, 256, STEP_SMEM>>>(ph, pl, whh, b_hh,
                                                      b_ih, gt, t, hpF, hF, oh, ol);
        else
            gru_step<2><<<stepGrid, 256, STEP_SMEM>>>(ph, pl, whh, b_hh,
                                                      Gtab, gt, t, hpF, hF, oh, ol);
    }
    copyf4_kernel<<<((int)(BH / 4) + 255) / 256, 256>>>(
        hseqF + (size_t)16 * BH, outFinal);
    { __half* tp = Uh; Uh = Oh; Oh = tp; tp = Ul; Ul = Ol; Ol = tp; }

    // ---- layers 1, 2 (batched GI + fused steps) ----
    for (int l = 1; l < Ln; l++) {
        gemm_h2<0><<<dim3(12, 544), 256, GEMM_SMEM>>>(
            Uh, Ul, wih + (size_t)l * H3 * Hn, b_ih + l * H3, GI, H3);
        for (int t = 0; t < NSTEP; t++) {
            const __half* ph = t ? (Oh + (size_t)(t - 1) * BH) : (pqh + (size_t)l * BH);
            const __half* pl = t ? (Ol + (size_t)(t - 1) * BH) : (pql + (size_t)l * BH);
            const float* hpF = t ? (hseqF + (size_t)(t - 1) * BH)
                                 : (prev_hidden + (size_t)l * BH);
            gru_step<0><<<stepGrid, 256, STEP_SMEM>>>(
                ph, pl, whh + (size_t)l * H3 * Hn, b_hh + l * H3,
                GI + (size_t)t * BH3, gt, t,
                hpF, hseqF + (size_t)t * BH,
                Oh + (size_t)t * BH, Ol + (size_t)t * BH);
        }
        copyf4_kernel<<<((int)(BH / 4) + 255) / 256, 256>>>(
            hseqF + (size_t)16 * BH, outFinal + (size_t)l * BH);
        __half* tp;
        tp = Uh; Uh = Oh; Oh = tp;
        tp = Ul; Ul = Ol; Ol = tp;
    }

    // ---- logits over scan slots 1..16 ----
    gemm_h2<2><<<dim3(4, 512), 256, GEMM_SMEM>>>(
        Uh + BH, Ul + BH, wo, b_out, outLogits, 0);

    // ---- reward / done heads ----
    heads_kernel<<<(Bsz * 32 + 255) / 256, 256>>>(
        hseqF, W_r, b_r, W_d, b_d, outReward, outDone);
}

// round 8
// speedup vs baseline: 3.7618x; 1.1388x over previous
#include <cuda_runtime.h>
#include <cuda_fp16.h>
#include <cstdint>
#include <math.h>

// ---------------- problem constants ----------------
#define Bsz   4096
#define Hn    512
#define H3    1536
#define Ln    3
#define Tn    16
#define Cn    512
#define NSTEP 17
#define KDIM  512
#define NCH   8            // K chunks of 64 fp16 (128B rows)

static const size_t BH  = (size_t)Bsz * Hn;
static const size_t BH3 = (size_t)Bsz * H3;

// ---------------- persistent device scratch ----------------
__device__ __align__(128) __half g_uA_hi[(size_t)NSTEP * Bsz * Hn];
__device__ __align__(128) __half g_uA_lo[(size_t)NSTEP * Bsz * Hn];
__device__ __align__(128) __half g_uB_hi[(size_t)NSTEP * Bsz * Hn];
__device__ __align__(128) __half g_uB_lo[(size_t)NSTEP * Bsz * Hn];
__device__ __align__(128) __half g_pq_hi[(size_t)Ln * Bsz * Hn];
__device__ __align__(128) __half g_pq_lo[(size_t)Ln * Bsz * Hn];
__device__ __align__(128) float  g_hseqF[(size_t)NSTEP * Bsz * Hn];
__device__ __align__(128) float  g_GI[(size_t)NSTEP * Bsz * H3];
__device__ __align__(128) __half g_wih[(size_t)Ln * H3 * Hn];
__device__ __align__(128) __half g_whh[(size_t)Ln * H3 * Hn];
__device__ __align__(128) __half g_wo[(size_t)Cn * Hn];
__device__ __align__(128) __half g_wt[(size_t)Hn * Hn];
__device__ __align__(128) __half g_embh[(size_t)Cn * Hn];
__device__ __align__(128) __half g_embl[(size_t)Cn * Hn];
__device__ __align__(128) float  g_P[(size_t)Cn * Hn];
__device__ __align__(128) __half g_Pqh[(size_t)Cn * Hn];
__device__ __align__(128) __half g_Pql[(size_t)Cn * Hn];
__device__ __align__(128) float  g_Gtab[(size_t)Cn * H3];

// ---------------- PTX helpers ----------------
__device__ __forceinline__ uint32_t smem_u32(const void* p) {
    uint32_t a;
    asm("{ .reg .u64 t; cvta.to.shared.u64 t, %1; cvt.u32.u64 %0, t; }" : "=r"(a) : "l"(p));
    return a;
}
__device__ __forceinline__ void cpasync16(uint32_t s, const void* g) {
    asm volatile("cp.async.cg.shared.global [%0], [%1], 16;" :: "r"(s), "l"(g));
}
__device__ __forceinline__ void cp_commit() {
    asm volatile("cp.async.commit_group;" ::: "memory");
}
template <int N> __device__ __forceinline__ void cp_wait() {
    asm volatile("cp.async.wait_group %0;" :: "n"(N) : "memory");
}
__device__ __forceinline__ void ldsm4(uint32_t& r0, uint32_t& r1, uint32_t& r2, uint32_t& r3,
                                      uint32_t addr) {
    asm volatile("ldmatrix.sync.aligned.m8n8.x4.shared.b16 {%0,%1,%2,%3}, [%4];"
                 : "=r"(r0), "=r"(r1), "=r"(r2), "=r"(r3) : "r"(addr));
}
__device__ __forceinline__ void hmma16816(float* d, const uint32_t* a, uint32_t b0, uint32_t b1) {
    asm volatile(
        "mma.sync.aligned.m16n8k16.row.col.f32.f16.f16.f32 "
        "{%0,%1,%2,%3}, {%4,%5,%6,%7}, {%8,%9}, {%0,%1,%2,%3};"
        : "+f"(d[0]), "+f"(d[1]), "+f"(d[2]), "+f"(d[3])
        : "r"(a[0]), "r"(a[1]), "r"(a[2]), "r"(a[3]), "r"(b0), "r"(b1));
}

#define GEMM_SMEM2 (2 * 49152)   // 2-plane 128x128 gemm
#define GEMM_SMEM1 (2 * 32768)   // 1-plane 128x128 gemm
#define STEP_SMEM  (2 * 45056)   // fused step

__device__ __forceinline__ float sigf(float x) { return 1.f / (1.f + __expf(-x)); }
__device__ __forceinline__ void split1h(float x, __half& h, __half& l) {
    h = __float2half_rn(x);
    l = __float2half_rn(x - __half2float(h));
}

// ---------------------------------------------------------------------------
// fp16 GEMM, 128x128 tile. PLANES = number of A planes (2: hi+lo, 1: hi only).
// C[m,n] = sum_k A[m,k]*Bh[n,k] + bias[n]
// MODE 0: row-major C. MODE 2: logits scatter [B,T,C].
// ---------------------------------------------------------------------------
template <int MODE, int PLANES>
__global__ void __launch_bounds__(256, 2)
gemm_h2(const __half* __restrict__ Ahi, const __half* __restrict__ Alo,
        const __half* __restrict__ Bh,
        const float* __restrict__ bias, float* __restrict__ C, int ldc)
{
    constexpr int STAGE = (PLANES == 2) ? 49152 : 32768;
    constexpr int BOFF  = PLANES * 16384;
    extern __shared__ __align__(128) char smem[];
    const uint32_t sb = smem_u32(smem);
    const int tid  = threadIdx.x;
    const int wid  = tid >> 5, lane = tid & 31;
    const int wM   = wid >> 1;
    const int wN   = wid & 1;
    const int m0   = blockIdx.y << 7, n0 = blockIdx.x << 7;

    const char* gAh = (const char*)(Ahi + (size_t)m0 * KDIM);
    const char* gAl = (const char*)(Alo + (size_t)m0 * KDIM);
    const char* gB  = (const char*)(Bh  + (size_t)n0 * KDIM);

    int srow[4], soff[4]; uint32_t sso[4];
#pragma unroll
    for (int q = 0; q < 4; q++) {
        int id = tid * 4 + q;
        srow[q] = id >> 3;
        soff[q] = (id & 7) << 4;
        sso[q]  = (uint32_t)((srow[q] << 7) | (soff[q] ^ ((srow[q] & 7) << 4)));
    }

    const int lr16 = lane & 15;
    const int lhi  = (lane >> 4) << 4;
    uint32_t aBase[2], aXr[2];
#pragma unroll
    for (int mt = 0; mt < 2; mt++) {
        int r = wM * 32 + mt * 16 + lr16;
        aBase[mt] = (uint32_t)(r << 7);
        aXr[mt]   = ((r & 7) << 4);
    }
    uint32_t bBase[4], bXr[4];
#pragma unroll
    for (int nt = 0; nt < 4; nt++) {
        int r = wN * 64 + nt * 16 + lr16;
        bBase[nt] = (uint32_t)(r << 7);
        bXr[nt]   = ((r & 7) << 4);
    }

    float acc[2][8][4];
#pragma unroll
    for (int i = 0; i < 2; i++)
#pragma unroll
        for (int j = 0; j < 8; j++)
#pragma unroll
            for (int v = 0; v < 4; v++) acc[i][j][v] = 0.f;

    auto load_chunk = [&](int s, int c) {
        const uint32_t st = sb + s * STAGE;
        const int cb = c * 128;
#pragma unroll
        for (int q = 0; q < 4; q++) {
            int go = srow[q] * 1024 + cb + soff[q];
            cpasync16(st + sso[q], gAh + go);
            if (PLANES == 2) cpasync16(st + 16384 + sso[q], gAl + go);
            cpasync16(st + BOFF + sso[q], gB + go);
        }
        cp_commit();
    };

    load_chunk(0, 0);

    for (int c = 0; c < NCH; c++) {
        const int s = c & 1;
        if (c + 1 < NCH) { load_chunk(s ^ 1, c + 1); cp_wait<1>(); }
        else             { cp_wait<0>(); }
        __syncthreads();

        const uint32_t stA0 = sb + s * STAGE;
        const uint32_t stA1 = stA0 + 16384;
        const uint32_t stB0 = stA0 + BOFF;

#pragma unroll
        for (int k16 = 0; k16 < 4; k16++) {
            const uint32_t ko = (uint32_t)(k16 * 32 + lhi);
            uint32_t ah[2][4], al[2][4];
#pragma unroll
            for (int mt = 0; mt < 2; mt++) {
                ldsm4(ah[mt][0], ah[mt][1], ah[mt][2], ah[mt][3],
                      stA0 + aBase[mt] + (ko ^ aXr[mt]));
                if (PLANES == 2)
                    ldsm4(al[mt][0], al[mt][1], al[mt][2], al[mt][3],
                          stA1 + aBase[mt] + (ko ^ aXr[mt]));
            }
            uint32_t bh[4][4];
#pragma unroll
            for (int nt = 0; nt < 4; nt++)
                ldsm4(bh[nt][0], bh[nt][1], bh[nt][2], bh[nt][3],
                      stB0 + bBase[nt] + (ko ^ bXr[nt]));
#pragma unroll
            for (int mt = 0; mt < 2; mt++)
#pragma unroll
                for (int nt = 0; nt < 4; nt++) {
                    hmma16816(acc[mt][2 * nt + 0], ah[mt], bh[nt][0], bh[nt][2]);
                    hmma16816(acc[mt][2 * nt + 1], ah[mt], bh[nt][1], bh[nt][3]);
                    if (PLANES == 2) {
                        hmma16816(acc[mt][2 * nt + 0], al[mt], bh[nt][0], bh[nt][2]);
                        hmma16816(acc[mt][2 * nt + 1], al[mt], bh[nt][1], bh[nt][3]);
                    }
                }
        }
        __syncthreads();
    }

    const int lr = lane >> 2;
    const int lc = (lane & 3) << 1;
#pragma unroll
    for (int mt = 0; mt < 2; mt++) {
        const int mBase = m0 + wM * 32 + mt * 16 + lr;
#pragma unroll
        for (int nt = 0; nt < 8; nt++) {
            const int n = n0 + wN * 64 + nt * 8 + lc;
            const float b0 = bias[n], b1 = bias[n + 1];
            float2 v0 = make_float2(acc[mt][nt][0] + b0, acc[mt][nt][1] + b1);
            float2 v1 = make_float2(acc[mt][nt][2] + b0, acc[mt][nt][3] + b1);
            size_t o0, o1;
            if (MODE == 2) {
                int bb0 = mBase & (Bsz - 1),       t0 = mBase >> 12;
                int bb1 = (mBase + 8) & (Bsz - 1), t1 = (mBase + 8) >> 12;
                o0 = (size_t)bb0 * (Tn * Cn) + (size_t)t0 * Cn + n;
                o1 = (size_t)bb1 * (Tn * Cn) + (size_t)t1 * Cn + n;
            } else {
                o0 = (size_t)mBase * ldc + n;
                o1 = (size_t)(mBase + 8) * ldc + n;
            }
            *(float2*)(C + o0) = v0;
            *(float2*)(C + o1) = v1;
        }
    }
}

// ---------------------------------------------------------------------------
// FUSED GRU step: hidden GEMM (3 gates for a 32-wide j slice) + gate math.
// ---------------------------------------------------------------------------
template <int GIMODE>
__global__ void __launch_bounds__(256)
gru_step(const __half* __restrict__ Ahi, const __half* __restrict__ Alo,
         const __half* __restrict__ W, const float* __restrict__ bhh,
         const float* __restrict__ GIt, const int* __restrict__ gt, int step,
         const float* __restrict__ hprevF, float* __restrict__ houtF,
         __half* __restrict__ hi, __half* __restrict__ lo)
{
    extern __shared__ __align__(128) char smem[];
    const uint32_t sb = smem_u32(smem);
    const int tid  = threadIdx.x;
    const int wid  = tid >> 5, lane = tid & 31;
    const int wM   = wid >> 1;
    const int wN   = wid & 1;
    const int m0   = blockIdx.y << 7;
    const int j0   = blockIdx.x << 5;

    const char* gAh = (const char*)(Ahi + (size_t)m0 * KDIM);
    const char* gAl = (const char*)(Alo + (size_t)m0 * KDIM);
    const char* gW  = (const char*)W;

    int srow[4], soff[4]; uint32_t sso[4];
#pragma unroll
    for (int q = 0; q < 4; q++) {
        int id = tid * 4 + q;
        srow[q] = id >> 3;
        soff[q] = (id & 7) << 4;
        sso[q]  = (uint32_t)((srow[q] << 7) | (soff[q] ^ ((srow[q] & 7) << 4)));
    }
    int bgr[3], boff[3]; uint32_t bso[3];
#pragma unroll
    for (int q = 0; q < 3; q++) {
        int id = tid * 3 + q;
        int rb = id >> 3;
        boff[q] = (id & 7) << 4;
        bgr[q]  = j0 + (rb & 31) + (rb >> 5) * 512;
        bso[q]  = (uint32_t)((rb << 7) | (boff[q] ^ ((rb & 7) << 4)));
    }

    const int lr16 = lane & 15;
    const int lhi  = (lane >> 4) << 4;
    uint32_t aBase[2], aXr[2];
#pragma unroll
    for (int mt = 0; mt < 2; mt++) {
        int r = wM * 32 + mt * 16 + lr16;
        aBase[mt] = (uint32_t)(r << 7);
        aXr[mt]   = ((r & 7) << 4);
    }
    uint32_t bBase[3], bXr[3];
#pragma unroll
    for (int g = 0; g < 3; g++) {
        int r = wN * 16 + g * 32 + lr16;
        bBase[g] = (uint32_t)(r << 7);
        bXr[g]   = ((r & 7) << 4);
    }

    float acc[2][3][2][4];
#pragma unroll
    for (int i = 0; i < 2; i++)
#pragma unroll
        for (int g = 0; g < 3; g++)
#pragma unroll
            for (int a = 0; a < 2; a++)
#pragma unroll
                for (int v = 0; v < 4; v++) acc[i][g][a][v] = 0.f;

    auto load_chunk = [&](int s, int c) {
        const uint32_t st = sb + s * 45056;
        const int cb = c * 128;
#pragma unroll
        for (int q = 0; q < 4; q++) {
            int go = srow[q] * 1024 + cb + soff[q];
            cpasync16(st +         sso[q], gAh + go);
            cpasync16(st + 16384 + sso[q], gAl + go);
        }
#pragma unroll
        for (int q = 0; q < 3; q++) {
            int go = bgr[q] * 1024 + cb + boff[q];
            cpasync16(st + 32768 + bso[q], gW + go);
        }
        cp_commit();
    };

    load_chunk(0, 0);

    for (int c = 0; c < NCH; c++) {
        const int s = c & 1;
        if (c + 1 < NCH) { load_chunk(s ^ 1, c + 1); cp_wait<1>(); }
        else             { cp_wait<0>(); }
        __syncthreads();

        const uint32_t stA0 = sb + s * 45056;
        const uint32_t stA1 = stA0 + 16384;
        const uint32_t stB0 = stA0 + 32768;

#pragma unroll
        for (int k16 = 0; k16 < 4; k16++) {
            const uint32_t ko = (uint32_t)(k16 * 32 + lhi);
            uint32_t ah[2][4], al[2][4];
#pragma unroll
            for (int mt = 0; mt < 2; mt++) {
                ldsm4(ah[mt][0], ah[mt][1], ah[mt][2], ah[mt][3],
                      stA0 + aBase[mt] + (ko ^ aXr[mt]));
                ldsm4(al[mt][0], al[mt][1], al[mt][2], al[mt][3],
                      stA1 + aBase[mt] + (ko ^ aXr[mt]));
            }
            uint32_t bh[3][4];
#pragma unroll
            for (int g = 0; g < 3; g++)
                ldsm4(bh[g][0], bh[g][1], bh[g][2], bh[g][3],
                      stB0 + bBase[g] + (ko ^ bXr[g]));
#pragma unroll
            for (int mt = 0; mt < 2; mt++)
#pragma unroll
                for (int g = 0; g < 3; g++) {
                    hmma16816(acc[mt][g][0], ah[mt], bh[g][0], bh[g][2]);
                    hmma16816(acc[mt][g][1], ah[mt], bh[g][1], bh[g][3]);
                    hmma16816(acc[mt][g][0], al[mt], bh[g][0], bh[g][2]);
                    hmma16816(acc[mt][g][1], al[mt], bh[g][1], bh[g][3]);
                }
        }
        __syncthreads();
    }

    const int lr = lane >> 2;
    const int lc = (lane & 3) << 1;
#pragma unroll
    for (int mt = 0; mt < 2; mt++) {
        const int mBase = m0 + wM * 32 + mt * 16 + lr;
#pragma unroll
        for (int a = 0; a < 2; a++) {
            const int j = j0 + wN * 16 + a * 8 + lc;
            const float2 bR = *(const float2*)(bhh + j);
            const float2 bZ = *(const float2*)(bhh + 512 + j);
            const float2 bN = *(const float2*)(bhh + 1024 + j);
#pragma unroll
            for (int hh = 0; hh < 2; hh++) {
                const int row = mBase + hh * 8;
                const int vi = hh * 2;
                const float* gi;
                if (GIMODE == 0)      gi = GIt + (size_t)row * H3 + j;
                else if (GIMODE == 1) gi = GIt + j;
                else {
                    int tok = gt[row * Tn + (step - 2)];
                    gi = GIt + (size_t)tok * H3 + j;
                }
                float2 gR = *(const float2*)(gi);
                float2 gZ = *(const float2*)(gi + 512);
                float2 gN = *(const float2*)(gi + 1024);
                float2 hp = *(const float2*)(hprevF + (size_t)row * Hn + j);
                float r0 = sigf(gR.x + acc[mt][0][a][vi]     + bR.x);
                float r1 = sigf(gR.y + acc[mt][0][a][vi + 1] + bR.y);
                float z0 = sigf(gZ.x + acc[mt][1][a][vi]     + bZ.x);
                float z1 = sigf(gZ.y + acc[mt][1][a][vi + 1] + bZ.y);
                float n0 = tanhf(gN.x + r0 * (acc[mt][2][a][vi]     + bN.x));
                float n1 = tanhf(gN.y + r1 * (acc[mt][2][a][vi + 1] + bN.y));
                float h0 = (1.f - z0) * n0 + z0 * hp.x;
                float h1 = (1.f - z1) * n1 + z1 * hp.y;
                size_t oh = (size_t)row * Hn + j;
                *(float2*)(houtF + oh) = make_float2(h0, h1);
                __half a0, a1, c0, c1;
                split1h(h0, a0, c0); split1h(h1, a1, c1);
                *(__half2*)(hi + oh) = __halves2half2(a0, a1);
                *(__half2*)(lo + oh) = __halves2half2(c0, c1);
            }
        }
    }
}

// ---------------- elementwise kernels ----------------
__global__ void convW(const float* __restrict__ W_ih, const float* __restrict__ W_hh,
                      const float* __restrict__ W_out, const float* __restrict__ W_tp,
                      const float* __restrict__ emb,
                      __half* __restrict__ wih, __half* __restrict__ whh,
                      __half* __restrict__ wo,  __half* __restrict__ wt,
                      __half* __restrict__ embh, __half* __restrict__ embl)
{
    int i = blockIdx.x * blockDim.x + threadIdx.x;
    if (i >= 1376256) return;
    if (i < 1310720) {
        const float* s; __half* d; int j;
        if (i < 589824)       { s = W_ih;  d = wih; j = i; }
        else if (i < 1179648) { s = W_hh;  d = whh; j = i - 589824; }
        else if (i < 1245184) { s = W_out; d = wo;  j = i - 1179648; }
        else                  { s = W_tp;  d = wt;  j = i - 1245184; }
        float4 v = ((const float4*)s)[j];
        ((__half2*)d)[2 * j + 0] = __floats2half2_rn(v.x, v.y);
        ((__half2*)d)[2 * j + 1] = __floats2half2_rn(v.z, v.w);
    } else {
        int j = i - 1310720;
        float4 v = ((const float4*)emb)[j];
        __half h0, h1, h2, h3, l0, l1, l2, l3;
        split1h(v.x, h0, l0); split1h(v.y, h1, l1);
        split1h(v.z, h2, l2); split1h(v.w, h3, l3);
        ((__half2*)embh)[2 * j + 0] = __halves2half2(h0, h1);
        ((__half2*)embh)[2 * j + 1] = __halves2half2(h2, h3);
        ((__half2*)embl)[2 * j + 0] = __halves2half2(l0, l1);
        ((__half2*)embl)[2 * j + 1] = __halves2half2(l2, l3);
    }
}

// prev hidden split + x0 compute+split in ONE kernel (stable launch indexing)
__global__ void prep_kernel(const float* __restrict__ prev,
                            const float* __restrict__ action,
                            const float* __restrict__ W_a, const float* __restrict__ b_a,
                            __half* __restrict__ pqh, __half* __restrict__ pql,
                            __half* __restrict__ x0h, __half* __restrict__ x0l)
{
    const int NPREV = (int)(Ln * BH / 4);
    int i = blockIdx.x * blockDim.x + threadIdx.x;
    if (i < NPREV) {
        float4 v = ((const float4*)prev)[i];
        __half h0, h1, h2, h3, l0, l1, l2, l3;
        split1h(v.x, h0, l0); split1h(v.y, h1, l1);
        split1h(v.z, h2, l2); split1h(v.w, h3, l3);
        ((__half2*)pqh)[2 * i + 0] = __halves2half2(h0, h1);
        ((__half2*)pqh)[2 * i + 1] = __halves2half2(h2, h3);
        ((__half2*)pql)[2 * i + 0] = __halves2half2(l0, l1);
        ((__half2*)pql)[2 * i + 1] = __halves2half2(l2, l3);
    } else if (i < NPREV + (int)(BH / 4)) {
        int j = i - NPREV;
        int e0 = j * 4;
        int b = e0 >> 9, c = e0 & 511;
        float a0 = action[b * 3 + 0], a1 = action[b * 3 + 1], a2 = action[b * 3 + 2];
        __half hs[4], ls[4];
#pragma unroll
        for (int q = 0; q < 4; q++) {
            int jj = c + q;
            float s = b_a[jj] + a0 * W_a[jj * 3 + 0] + a1 * W_a[jj * 3 + 1]
                              + a2 * W_a[jj * 3 + 2];
            split1h(s, hs[q], ls[q]);
        }
        ((__half2*)x0h)[2 * j + 0] = __halves2half2(hs[0], hs[1]);
        ((__half2*)x0h)[2 * j + 1] = __halves2half2(hs[2], hs[3]);
        ((__half2*)x0l)[2 * j + 0] = __halves2half2(ls[0], ls[1]);
        ((__half2*)x0l)[2 * j + 1] = __halves2half2(ls[2], ls[3]);
    }
}

__global__ void split2_kernel(const float* __restrict__ src,
                              __half* __restrict__ hi, __half* __restrict__ lo, int n4)
{
    int i = blockIdx.x * blockDim.x + threadIdx.x;
    if (i >= n4) return;
    float4 v = ((const float4*)src)[i];
    __half h0, h1, h2, h3, l0, l1, l2, l3;
    split1h(v.x, h0, l0); split1h(v.y, h1, l1);
    split1h(v.z, h2, l2); split1h(v.w, h3, l3);
    ((__half2*)hi)[2 * i + 0] = __halves2half2(h0, h1);
    ((__half2*)hi)[2 * i + 1] = __halves2half2(h2, h3);
    ((__half2*)lo)[2 * i + 0] = __halves2half2(l0, l1);
    ((__half2*)lo)[2 * i + 1] = __halves2half2(l2, l3);
}

__global__ void copyf4_kernel(const float* __restrict__ src, float* __restrict__ dst)
{
    int i = blockIdx.x * blockDim.x + threadIdx.x;
    if (i >= (int)(BH / 4)) return;
    ((float4*)dst)[i] = ((const float4*)src)[i];
}

__global__ void heads_kernel(const float* __restrict__ h2, const float* __restrict__ W_r,
                             const float* __restrict__ b_r, const float* __restrict__ W_d,
                             const float* __restrict__ b_d,
                             float* __restrict__ outr, float* __restrict__ outd)
{
    int gw = (blockIdx.x * blockDim.x + threadIdx.x) >> 5;
    int lane = threadIdx.x & 31;
    if (gw >= Bsz) return;
    const float* hb = h2 + (size_t)gw * Hn;
    float sr = 0.f, sd = 0.f;
#pragma unroll
    for (int k = lane; k < Hn; k += 32) {
        float v = hb[k];
        sr = fmaf(v, W_r[k], sr);
        sd = fmaf(v, W_d[k], sd);
    }
#pragma unroll
    for (int o = 16; o > 0; o >>= 1) {
        sr += __shfl_down_sync(0xffffffffu, sr, o);
        sd += __shfl_down_sync(0xffffffffu, sd, o);
    }
    if (lane == 0) { outr[gw] = sr + b_r[0]; outd[gw] = sd + b_d[0]; }
}

// ---------------------------------------------------------------------------
extern "C" void kernel_launch(void* const* d_in, const int* in_sizes, int n_in,
                              void* d_out, int out_size)
{
    const float* action      = (const float*)d_in[0];
    const float* prev_hidden = (const float*)d_in[1];
    const int*   gt          = (const int*)d_in[2];
    const float* W_a         = (const float*)d_in[3];
    const float* b_a         = (const float*)d_in[4];
    const float* emb         = (const float*)d_in[5];
    const float* W_tp        = (const float*)d_in[6];
    const float* b_tp        = (const float*)d_in[7];
    const float* W_ih        = (const float*)d_in[8];
    const float* W_hh        = (const float*)d_in[9];
    const float* b_ih        = (const float*)d_in[10];
    const float* b_hh        = (const float*)d_in[11];
    const float* W_out       = (const float*)d_in[12];
    const float* b_out       = (const float*)d_in[13];
    const float* W_r         = (const float*)d_in[14];
    const float* b_r         = (const float*)d_in[15];
    const float* W_d         = (const float*)d_in[16];
    const float* b_d         = (const float*)d_in[17];
    float* out = (float*)d_out;

    static bool attr_done = false;
    if (!attr_done) {
        cudaFuncSetAttribute((const void*)gemm_h2<0, 2>, cudaFuncAttributeMaxDynamicSharedMemorySize, GEMM_SMEM2);
        cudaFuncSetAttribute((const void*)gemm_h2<0, 1>, cudaFuncAttributeMaxDynamicSharedMemorySize, GEMM_SMEM1);
        cudaFuncSetAttribute((const void*)gemm_h2<2, 1>, cudaFuncAttributeMaxDynamicSharedMemorySize, GEMM_SMEM1);
        cudaFuncSetAttribute((const void*)gru_step<0>, cudaFuncAttributeMaxDynamicSharedMemorySize, STEP_SMEM);
        cudaFuncSetAttribute((const void*)gru_step<1>, cudaFuncAttributeMaxDynamicSharedMemorySize, STEP_SMEM);
        cudaFuncSetAttribute((const void*)gru_step<2>, cudaFuncAttributeMaxDynamicSharedMemorySize, STEP_SMEM);
        attr_done = true;
    }

    __half *uAh, *uAl, *uBh, *uBl, *pqh, *pql;
    __half *wih, *whh, *wo, *wt, *embh, *embl, *Pqh, *Pql;
    float *hseqF, *GI, *P, *Gtab;
    cudaGetSymbolAddress((void**)&uAh, g_uA_hi);  cudaGetSymbolAddress((void**)&uAl, g_uA_lo);
    cudaGetSymbolAddress((void**)&uBh, g_uB_hi);  cudaGetSymbolAddress((void**)&uBl, g_uB_lo);
    cudaGetSymbolAddress((void**)&pqh, g_pq_hi);  cudaGetSymbolAddress((void**)&pql, g_pq_lo);
    cudaGetSymbolAddress((void**)&wih, g_wih);    cudaGetSymbolAddress((void**)&whh, g_whh);
    cudaGetSymbolAddress((void**)&wo,  g_wo);     cudaGetSymbolAddress((void**)&wt,  g_wt);
    cudaGetSymbolAddress((void**)&embh, g_embh);  cudaGetSymbolAddress((void**)&embl, g_embl);
    cudaGetSymbolAddress((void**)&Pqh, g_Pqh);    cudaGetSymbolAddress((void**)&Pql, g_Pql);
    cudaGetSymbolAddress((void**)&hseqF, g_hseqF);
    cudaGetSymbolAddress((void**)&GI, g_GI);
    cudaGetSymbolAddress((void**)&P, g_P);
    cudaGetSymbolAddress((void**)&Gtab, g_Gtab);

    float* outLogits = out;
    float* outReward = out + (size_t)Bsz * Tn * Cn;
    float* outDone   = outReward + Bsz;
    float* outFinal  = outDone + Bsz;

    const dim3 stepGrid(16, 32);
    __half *Uh = uAh, *Ul = uAl, *Oh = uBh, *Ol = uBl;

    // [0] weights -> fp16
    convW<<<(1376256 + 255) / 256, 256>>>(W_ih, W_hh, W_out, W_tp, emb,
                                          wih, whh, wo, wt, embh, embl);
    // [1] prev hidden split + x0 compute+split
    prep_kernel<<<((int)(Ln * BH / 4 + BH / 4) + 255) / 256, 256>>>(
        prev_hidden, action, W_a, b_a, pqh, pql, uAh, uAl);
    // [2] GI slot0 = x0 @ W_ih0.T + b_ih0 (2-plane)
    gemm_h2<0, 2><<<dim3(12, 32), 256, GEMM_SMEM2>>>(uAh, uAl, wih, b_ih, GI, H3);
    // [3] fused GRU step, layer 0, t=0  <-- ncu captures launch index 3
    gru_step<0><<<stepGrid, 256, STEP_SMEM>>>(pqh, pql, whh, b_hh,
                                              GI, gt, 0, prev_hidden,
                                              hseqF, Oh, Ol);
    // [4] P = emb @ W_tp.T + b_tp
    gemm_h2<0, 2><<<dim3(4, 4), 256, GEMM_SMEM2>>>(embh, embl, wt, b_tp, P, Hn);
    // [5] P -> fp16 planes
    split2_kernel<<<((Cn * Hn / 4) + 255) / 256, 256>>>(P, Pqh, Pql, Cn * Hn / 4);
    // [6] Gtab = Pq @ W_ih0.T + b_ih0
    gemm_h2<0, 2><<<dim3(12, 4), 256, GEMM_SMEM2>>>(Pqh, Pql, wih, b_ih, Gtab, H3);

    // ---- layer 0 t = 1..16 (token-table GI) ----
    for (int t = 1; t < NSTEP; t++) {
        const __half* ph = Oh + (size_t)(t - 1) * BH;
        const __half* pl = Ol + (size_t)(t - 1) * BH;
        const float* hpF = hseqF + (size_t)(t - 1) * BH;
        float*  hF = hseqF + (size_t)t * BH;
        __half* oh = Oh + (size_t)t * BH;
        __half* ol = Ol + (size_t)t * BH;
        if (t == 1)
            gru_step<1><<<stepGrid, 256, STEP_SMEM>>>(ph, pl, whh, b_hh,
                                                      b_ih, gt, t, hpF, hF, oh, ol);
        else
            gru_step<2><<<stepGrid, 256, STEP_SMEM>>>(ph, pl, whh, b_hh,
                                                      Gtab, gt, t, hpF, hF, oh, ol);
    }
    copyf4_kernel<<<((int)(BH / 4) + 255) / 256, 256>>>(
        hseqF + (size_t)16 * BH, outFinal);
    { __half* tp = Uh; Uh = Oh; Oh = tp; tp = Ul; Ul = Ol; Ol = tp; }

    // ---- layers 1, 2: single-plane batched GI + fused 2-plane steps ----
    for (int l = 1; l < Ln; l++) {
        gemm_h2<0, 1><<<dim3(12, 544), 256, GEMM_SMEM1>>>(
            Uh, nullptr, wih + (size_t)l * H3 * Hn, b_ih + l * H3, GI, H3);
        for (int t = 0; t < NSTEP; t++) {
            const __half* ph = t ? (Oh + (size_t)(t - 1) * BH) : (pqh + (size_t)l * BH);
            const __half* pl = t ? (Ol + (size_t)(t - 1) * BH) : (pql + (size_t)l * BH);
            const float* hpF = t ? (hseqF + (size_t)(t - 1) * BH)
                                 : (prev_hidden + (size_t)l * BH);
            gru_step<0><<<stepGrid, 256, STEP_SMEM>>>(
                ph, pl, whh + (size_t)l * H3 * Hn, b_hh + l * H3,
                GI + (size_t)t * BH3, gt, t,
                hpF, hseqF + (size_t)t * BH,
                Oh + (size_t)t * BH, Ol + (size_t)t * BH);
        }
        copyf4_kernel<<<((int)(BH / 4) + 255) / 256, 256>>>(
            hseqF + (size_t)16 * BH, outFinal + (size_t)l * BH);
        __half* tp;
        tp = Uh; Uh = Oh; Oh = tp;
        tp = Ul; Ul = Ol; Ol = tp;
    }

    // ---- logits over scan slots 1..16 (single-plane A) ----
    gemm_h2<2, 1><<<dim3(4, 512), 256, GEMM_SMEM1>>>(
        Uh + BH, nullptr, wo, b_out, outLogits, 0);

    // ---- reward / done heads ----
    heads_kernel<<<(Bsz * 32 + 255) / 256, 256>>>(
        hseqF, W_r, b_r, W_d, b_d, outReward, outDone);
}

// round 9
// speedup vs baseline: 5.0286x; 1.3367x over previous
#include <cuda_runtime.h>
#include <cuda_fp16.h>
#include <cstdint>
#include <math.h>

// ---------------- problem constants ----------------
#define Bsz   4096
#define Hn    512
#define H3    1536
#define Ln    3
#define Tn    16
#define Cn    512
#define NSTEP 17
#define KDIM  512
#define NCH   8            // K chunks of 64 fp16 (128B rows)

static const size_t BH  = (size_t)Bsz * Hn;
static const size_t BH3 = (size_t)Bsz * H3;

// ---------------- persistent device scratch ----------------
__device__ __align__(128) __half g_uA_hi[(size_t)NSTEP * Bsz * Hn];
__device__ __align__(128) __half g_uA_lo[(size_t)Bsz * Hn];          // x0 lo only
__device__ __align__(128) __half g_uB_hi[(size_t)NSTEP * Bsz * Hn];
__device__ __align__(128) __half g_pq_hi[(size_t)Ln * Bsz * Hn];
__device__ __align__(128) float  g_hseqF[(size_t)NSTEP * Bsz * Hn];
__device__ __align__(128) float  g_GI[(size_t)NSTEP * Bsz * H3];
__device__ __align__(128) __half g_wih[(size_t)Ln * H3 * Hn];
__device__ __align__(128) __half g_whh[(size_t)Ln * H3 * Hn];
__device__ __align__(128) __half g_wo[(size_t)Cn * Hn];
__device__ __align__(128) __half g_wt[(size_t)Hn * Hn];
__device__ __align__(128) __half g_embh[(size_t)Cn * Hn];
__device__ __align__(128) __half g_embl[(size_t)Cn * Hn];
__device__ __align__(128) float  g_P[(size_t)Cn * Hn];
__device__ __align__(128) __half g_Pqh[(size_t)Cn * Hn];
__device__ __align__(128) __half g_Pql[(size_t)Cn * Hn];
__device__ __align__(128) float  g_Gtab[(size_t)Cn * H3];

// ---------------- PTX helpers ----------------
__device__ __forceinline__ uint32_t smem_u32(const void* p) {
    uint32_t a;
    asm("{ .reg .u64 t; cvta.to.shared.u64 t, %1; cvt.u32.u64 %0, t; }" : "=r"(a) : "l"(p));
    return a;
}
__device__ __forceinline__ void cpasync16(uint32_t s, const void* g) {
    asm volatile("cp.async.cg.shared.global [%0], [%1], 16;" :: "r"(s), "l"(g));
}
__device__ __forceinline__ void cp_commit() {
    asm volatile("cp.async.commit_group;" ::: "memory");
}
template <int N> __device__ __forceinline__ void cp_wait() {
    asm volatile("cp.async.wait_group %0;" :: "n"(N) : "memory");
}
__device__ __forceinline__ void ldsm4(uint32_t& r0, uint32_t& r1, uint32_t& r2, uint32_t& r3,
                                      uint32_t addr) {
    asm volatile("ldmatrix.sync.aligned.m8n8.x4.shared.b16 {%0,%1,%2,%3}, [%4];"
                 : "=r"(r0), "=r"(r1), "=r"(r2), "=r"(r3) : "r"(addr));
}
__device__ __forceinline__ void hmma16816(float* d, const uint32_t* a, uint32_t b0, uint32_t b1) {
    asm volatile(
        "mma.sync.aligned.m16n8k16.row.col.f32.f16.f16.f32 "
        "{%0,%1,%2,%3}, {%4,%5,%6,%7}, {%8,%9}, {%0,%1,%2,%3};"
        : "+f"(d[0]), "+f"(d[1]), "+f"(d[2]), "+f"(d[3])
        : "r"(a[0]), "r"(a[1]), "r"(a[2]), "r"(a[3]), "r"(b0), "r"(b1));
}

#define GEMM_SMEM2 (2 * 49152)   // 2-plane 128x128 gemm
#define GEMM_SMEM1 (2 * 32768)   // 1-plane 128x128 gemm
#define STEP_SMEM  (2 * 28672)   // fused step: 2 stages x (16KB A + 12KB B)

__device__ __forceinline__ float sigf(float x) { return 1.f / (1.f + __expf(-x)); }
__device__ __forceinline__ void split1h(float x, __half& h, __half& l) {
    h = __float2half_rn(x);
    l = __float2half_rn(x - __half2float(h));
}

// ---------------------------------------------------------------------------
// fp16 GEMM, 128x128 tile. PLANES = A planes (2 or 1).
// MODE 0: row-major C. MODE 2: logits scatter [B,T,C].
// ---------------------------------------------------------------------------
template <int MODE, int PLANES>
__global__ void __launch_bounds__(256, 2)
gemm_h2(const __half* __restrict__ Ahi, const __half* __restrict__ Alo,
        const __half* __restrict__ Bh,
        const float* __restrict__ bias, float* __restrict__ C, int ldc)
{
    constexpr int STAGE = (PLANES == 2) ? 49152 : 32768;
    constexpr int BOFF  = PLANES * 16384;
    extern __shared__ __align__(128) char smem[];
    const uint32_t sb = smem_u32(smem);
    const int tid  = threadIdx.x;
    const int wid  = tid >> 5, lane = tid & 31;
    const int wM   = wid >> 1;
    const int wN   = wid & 1;
    const int m0   = blockIdx.y << 7, n0 = blockIdx.x << 7;

    const char* gAh = (const char*)(Ahi + (size_t)m0 * KDIM);
    const char* gAl = (const char*)(Alo + (size_t)m0 * KDIM);
    const char* gB  = (const char*)(Bh  + (size_t)n0 * KDIM);

    int srow[4], soff[4]; uint32_t sso[4];
#pragma unroll
    for (int q = 0; q < 4; q++) {
        int id = tid * 4 + q;
        srow[q] = id >> 3;
        soff[q] = (id & 7) << 4;
        sso[q]  = (uint32_t)((srow[q] << 7) | (soff[q] ^ ((srow[q] & 7) << 4)));
    }

    const int lr16 = lane & 15;
    const int lhi  = (lane >> 4) << 4;
    uint32_t aBase[2], aXr[2];
#pragma unroll
    for (int mt = 0; mt < 2; mt++) {
        int r = wM * 32 + mt * 16 + lr16;
        aBase[mt] = (uint32_t)(r << 7);
        aXr[mt]   = ((r & 7) << 4);
    }
    uint32_t bBase[4], bXr[4];
#pragma unroll
    for (int nt = 0; nt < 4; nt++) {
        int r = wN * 64 + nt * 16 + lr16;
        bBase[nt] = (uint32_t)(r << 7);
        bXr[nt]   = ((r & 7) << 4);
    }

    float acc[2][8][4];
#pragma unroll
    for (int i = 0; i < 2; i++)
#pragma unroll
        for (int j = 0; j < 8; j++)
#pragma unroll
            for (int v = 0; v < 4; v++) acc[i][j][v] = 0.f;

    auto load_chunk = [&](int s, int c) {
        const uint32_t st = sb + s * STAGE;
        const int cb = c * 128;
#pragma unroll
        for (int q = 0; q < 4; q++) {
            int go = srow[q] * 1024 + cb + soff[q];
            cpasync16(st + sso[q], gAh + go);
            if (PLANES == 2) cpasync16(st + 16384 + sso[q], gAl + go);
            cpasync16(st + BOFF + sso[q], gB + go);
        }
        cp_commit();
    };

    load_chunk(0, 0);

    for (int c = 0; c < NCH; c++) {
        const int s = c & 1;
        if (c + 1 < NCH) { load_chunk(s ^ 1, c + 1); cp_wait<1>(); }
        else             { cp_wait<0>(); }
        __syncthreads();

        const uint32_t stA0 = sb + s * STAGE;
        const uint32_t stA1 = stA0 + 16384;
        const uint32_t stB0 = stA0 + BOFF;

#pragma unroll
        for (int k16 = 0; k16 < 4; k16++) {
            const uint32_t ko = (uint32_t)(k16 * 32 + lhi);
            uint32_t ah[2][4], al[2][4];
#pragma unroll
            for (int mt = 0; mt < 2; mt++) {
                ldsm4(ah[mt][0], ah[mt][1], ah[mt][2], ah[mt][3],
                      stA0 + aBase[mt] + (ko ^ aXr[mt]));
                if (PLANES == 2)
                    ldsm4(al[mt][0], al[mt][1], al[mt][2], al[mt][3],
                          stA1 + aBase[mt] + (ko ^ aXr[mt]));
            }
            uint32_t bh[4][4];
#pragma unroll
            for (int nt = 0; nt < 4; nt++)
                ldsm4(bh[nt][0], bh[nt][1], bh[nt][2], bh[nt][3],
                      stB0 + bBase[nt] + (ko ^ bXr[nt]));
#pragma unroll
            for (int mt = 0; mt < 2; mt++)
#pragma unroll
                for (int nt = 0; nt < 4; nt++) {
                    hmma16816(acc[mt][2 * nt + 0], ah[mt], bh[nt][0], bh[nt][2]);
                    hmma16816(acc[mt][2 * nt + 1], ah[mt], bh[nt][1], bh[nt][3]);
                    if (PLANES == 2) {
                        hmma16816(acc[mt][2 * nt + 0], al[mt], bh[nt][0], bh[nt][2]);
                        hmma16816(acc[mt][2 * nt + 1], al[mt], bh[nt][1], bh[nt][3]);
                    }
                }
        }
        __syncthreads();
    }

    const int lr = lane >> 2;
    const int lc = (lane & 3) << 1;
#pragma unroll
    for (int mt = 0; mt < 2; mt++) {
        const int mBase = m0 + wM * 32 + mt * 16 + lr;
#pragma unroll
        for (int nt = 0; nt < 8; nt++) {
            const int n = n0 + wN * 64 + nt * 8 + lc;
            const float b0 = bias[n], b1 = bias[n + 1];
            float2 v0 = make_float2(acc[mt][nt][0] + b0, acc[mt][nt][1] + b1);
            float2 v1 = make_float2(acc[mt][nt][2] + b0, acc[mt][nt][3] + b1);
            size_t o0, o1;
            if (MODE == 2) {
                int bb0 = mBase & (Bsz - 1),       t0 = mBase >> 12;
                int bb1 = (mBase + 8) & (Bsz - 1), t1 = (mBase + 8) >> 12;
                o0 = (size_t)bb0 * (Tn * Cn) + (size_t)t0 * Cn + n;
                o1 = (size_t)bb1 * (Tn * Cn) + (size_t)t1 * Cn + n;
            } else {
                o0 = (size_t)mBase * ldc + n;
                o1 = (size_t)(mBase + 8) * ldc + n;
            }
            *(float2*)(C + o0) = v0;
            *(float2*)(C + o1) = v1;
        }
    }
}

// ---------------------------------------------------------------------------
// FUSED GRU step, single-plane hidden state (A = fp16 h only).
// CTA: 128 batch rows x 32 j-cols of all 3 gates.
// GIMODE: 0 = GI slice; 1 = bias-only; 2 = token table.
// ---------------------------------------------------------------------------
template <int GIMODE>
__global__ void __launch_bounds__(256, 2)
gru_step(const __half* __restrict__ Ahi,
         const __half* __restrict__ W, const float* __restrict__ bhh,
         const float* __restrict__ GIt, const int* __restrict__ gt, int step,
         const float* __restrict__ hprevF, float* __restrict__ houtF,
         __half* __restrict__ hi)
{
    extern __shared__ __align__(128) char smem[];
    const uint32_t sb = smem_u32(smem);
    const int tid  = threadIdx.x;
    const int wid  = tid >> 5, lane = tid & 31;
    const int wM   = wid >> 1;
    const int wN   = wid & 1;
    const int m0   = blockIdx.y << 7;
    const int j0   = blockIdx.x << 5;

    const char* gAh = (const char*)(Ahi + (size_t)m0 * KDIM);
    const char* gW  = (const char*)W;

    int srow[4], soff[4]; uint32_t sso[4];
#pragma unroll
    for (int q = 0; q < 4; q++) {
        int id = tid * 4 + q;
        srow[q] = id >> 3;
        soff[q] = (id & 7) << 4;
        sso[q]  = (uint32_t)((srow[q] << 7) | (soff[q] ^ ((srow[q] & 7) << 4)));
    }
    int bgr[3], boff[3]; uint32_t bso[3];
#pragma unroll
    for (int q = 0; q < 3; q++) {
        int id = tid * 3 + q;
        int rb = id >> 3;
        boff[q] = (id & 7) << 4;
        bgr[q]  = j0 + (rb & 31) + (rb >> 5) * 512;
        bso[q]  = (uint32_t)((rb << 7) | (boff[q] ^ ((rb & 7) << 4)));
    }

    const int lr16 = lane & 15;
    const int lhi  = (lane >> 4) << 4;
    uint32_t aBase[2], aXr[2];
#pragma unroll
    for (int mt = 0; mt < 2; mt++) {
        int r = wM * 32 + mt * 16 + lr16;
        aBase[mt] = (uint32_t)(r << 7);
        aXr[mt]   = ((r & 7) << 4);
    }
    uint32_t bBase[3], bXr[3];
#pragma unroll
    for (int g = 0; g < 3; g++) {
        int r = wN * 16 + g * 32 + lr16;
        bBase[g] = (uint32_t)(r << 7);
        bXr[g]   = ((r & 7) << 4);
    }

    float acc[2][3][2][4];
#pragma unroll
    for (int i = 0; i < 2; i++)
#pragma unroll
        for (int g = 0; g < 3; g++)
#pragma unroll
            for (int a = 0; a < 2; a++)
#pragma unroll
                for (int v = 0; v < 4; v++) acc[i][g][a][v] = 0.f;

    auto load_chunk = [&](int s, int c) {
        const uint32_t st = sb + s * 28672;
        const int cb = c * 128;
#pragma unroll
        for (int q = 0; q < 4; q++) {
            int go = srow[q] * 1024 + cb + soff[q];
            cpasync16(st + sso[q], gAh + go);
        }
#pragma unroll
        for (int q = 0; q < 3; q++) {
            int go = bgr[q] * 1024 + cb + boff[q];
            cpasync16(st + 16384 + bso[q], gW + go);
        }
        cp_commit();
    };

    load_chunk(0, 0);

    for (int c = 0; c < NCH; c++) {
        const int s = c & 1;
        if (c + 1 < NCH) { load_chunk(s ^ 1, c + 1); cp_wait<1>(); }
        else             { cp_wait<0>(); }
        __syncthreads();

        const uint32_t stA0 = sb + s * 28672;
        const uint32_t stB0 = stA0 + 16384;

#pragma unroll
        for (int k16 = 0; k16 < 4; k16++) {
            const uint32_t ko = (uint32_t)(k16 * 32 + lhi);
            uint32_t ah[2][4];
#pragma unroll
            for (int mt = 0; mt < 2; mt++)
                ldsm4(ah[mt][0], ah[mt][1], ah[mt][2], ah[mt][3],
                      stA0 + aBase[mt] + (ko ^ aXr[mt]));
            uint32_t bh[3][4];
#pragma unroll
            for (int g = 0; g < 3; g++)
                ldsm4(bh[g][0], bh[g][1], bh[g][2], bh[g][3],
                      stB0 + bBase[g] + (ko ^ bXr[g]));
#pragma unroll
            for (int mt = 0; mt < 2; mt++)
#pragma unroll
                for (int g = 0; g < 3; g++) {
                    hmma16816(acc[mt][g][0], ah[mt], bh[g][0], bh[g][2]);
                    hmma16816(acc[mt][g][1], ah[mt], bh[g][1], bh[g][3]);
                }
        }
        __syncthreads();
    }

    const int lr = lane >> 2;
    const int lc = (lane & 3) << 1;
#pragma unroll
    for (int mt = 0; mt < 2; mt++) {
        const int mBase = m0 + wM * 32 + mt * 16 + lr;
#pragma unroll
        for (int a = 0; a < 2; a++) {
            const int j = j0 + wN * 16 + a * 8 + lc;
            const float2 bR = *(const float2*)(bhh + j);
            const float2 bZ = *(const float2*)(bhh + 512 + j);
            const float2 bN = *(const float2*)(bhh + 1024 + j);
#pragma unroll
            for (int hh = 0; hh < 2; hh++) {
                const int row = mBase + hh * 8;
                const int vi = hh * 2;
                const float* gi;
                if (GIMODE == 0)      gi = GIt + (size_t)row * H3 + j;
                else if (GIMODE == 1) gi = GIt + j;
                else {
                    int tok = gt[row * Tn + (step - 2)];
                    gi = GIt + (size_t)tok * H3 + j;
                }
                float2 gR = *(const float2*)(gi);
                float2 gZ = *(const float2*)(gi + 512);
                float2 gN = *(const float2*)(gi + 1024);
                float2 hp = *(const float2*)(hprevF + (size_t)row * Hn + j);
                float r0 = sigf(gR.x + acc[mt][0][a][vi]     + bR.x);
                float r1 = sigf(gR.y + acc[mt][0][a][vi + 1] + bR.y);
                float z0 = sigf(gZ.x + acc[mt][1][a][vi]     + bZ.x);
                float z1 = sigf(gZ.y + acc[mt][1][a][vi + 1] + bZ.y);
                float n0 = tanhf(gN.x + r0 * (acc[mt][2][a][vi]     + bN.x));
                float n1 = tanhf(gN.y + r1 * (acc[mt][2][a][vi + 1] + bN.y));
                float h0 = (1.f - z0) * n0 + z0 * hp.x;
                float h1 = (1.f - z1) * n1 + z1 * hp.y;
                size_t oh = (size_t)row * Hn + j;
                *(float2*)(houtF + oh) = make_float2(h0, h1);
                *(__half2*)(hi + oh) = __floats2half2_rn(h0, h1);
            }
        }
    }
}

// ---------------- elementwise kernels ----------------
__global__ void convW(const float* __restrict__ W_ih, const float* __restrict__ W_hh,
                      const float* __restrict__ W_out, const float* __restrict__ W_tp,
                      const float* __restrict__ emb,
                      __half* __restrict__ wih, __half* __restrict__ whh,
                      __half* __restrict__ wo,  __half* __restrict__ wt,
                      __half* __restrict__ embh, __half* __restrict__ embl)
{
    int i = blockIdx.x * blockDim.x + threadIdx.x;
    if (i >= 1376256) return;
    if (i < 1310720) {
        const float* s; __half* d; int j;
        if (i < 589824)       { s = W_ih;  d = wih; j = i; }
        else if (i < 1179648) { s = W_hh;  d = whh; j = i - 589824; }
        else if (i < 1245184) { s = W_out; d = wo;  j = i - 1179648; }
        else                  { s = W_tp;  d = wt;  j = i - 1245184; }
        float4 v = ((const float4*)s)[j];
        ((__half2*)d)[2 * j + 0] = __floats2half2_rn(v.x, v.y);
        ((__half2*)d)[2 * j + 1] = __floats2half2_rn(v.z, v.w);
    } else {
        int j = i - 1310720;
        float4 v = ((const float4*)emb)[j];
        __half h0, h1, h2, h3, l0, l1, l2, l3;
        split1h(v.x, h0, l0); split1h(v.y, h1, l1);
        split1h(v.z, h2, l2); split1h(v.w, h3, l3);
        ((__half2*)embh)[2 * j + 0] = __halves2half2(h0, h1);
        ((__half2*)embh)[2 * j + 1] = __halves2half2(h2, h3);
        ((__half2*)embl)[2 * j + 0] = __halves2half2(l0, l1);
        ((__half2*)embl)[2 * j + 1] = __halves2half2(l2, l3);
    }
}

// prev hidden -> fp16 hi plane; x0 compute + 2-plane split
__global__ void prep_kernel(const float* __restrict__ prev,
                            const float* __restrict__ action,
                            const float* __restrict__ W_a, const float* __restrict__ b_a,
                            __half* __restrict__ pqh,
                            __half* __restrict__ x0h, __half* __restrict__ x0l)
{
    const int NPREV = (int)(Ln * BH / 4);
    int i = blockIdx.x * blockDim.x + threadIdx.x;
    if (i < NPREV) {
        float4 v = ((const float4*)prev)[i];
        ((__half2*)pqh)[2 * i + 0] = __floats2half2_rn(v.x, v.y);
        ((__half2*)pqh)[2 * i + 1] = __floats2half2_rn(v.z, v.w);
    } else if (i < NPREV + (int)(BH / 4)) {
        int j = i - NPREV;
        int e0 = j * 4;
        int b = e0 >> 9, c = e0 & 511;
        float a0 = action[b * 3 + 0], a1 = action[b * 3 + 1], a2 = action[b * 3 + 2];
        __half hs[4], ls[4];
#pragma unroll
        for (int q = 0; q < 4; q++) {
            int jj = c + q;
            float s = b_a[jj] + a0 * W_a[jj * 3 + 0] + a1 * W_a[jj * 3 + 1]
                              + a2 * W_a[jj * 3 + 2];
            split1h(s, hs[q], ls[q]);
        }
        ((__half2*)x0h)[2 * j + 0] = __halves2half2(hs[0], hs[1]);
        ((__half2*)x0h)[2 * j + 1] = __halves2half2(hs[2], hs[3]);
        ((__half2*)x0l)[2 * j + 0] = __halves2half2(ls[0], ls[1]);
        ((__half2*)x0l)[2 * j + 1] = __halves2half2(ls[2], ls[3]);
    }
}

__global__ void split2_kernel(const float* __restrict__ src,
                              __half* __restrict__ hi, __half* __restrict__ lo, int n4)
{
    int i = blockIdx.x * blockDim.x + threadIdx.x;
    if (i >= n4) return;
    float4 v = ((const float4*)src)[i];
    __half h0, h1, h2, h3, l0, l1, l2, l3;
    split1h(v.x, h0, l0); split1h(v.y, h1, l1);
    split1h(v.z, h2, l2); split1h(v.w, h3, l3);
    ((__half2*)hi)[2 * i + 0] = __halves2half2(h0, h1);
    ((__half2*)hi)[2 * i + 1] = __halves2half2(h2, h3);
    ((__half2*)lo)[2 * i + 0] = __halves2half2(l0, l1);
    ((__half2*)lo)[2 * i + 1] = __halves2half2(l2, l3);
}

__global__ void copyf4_kernel(const float* __restrict__ src, float* __restrict__ dst)
{
    int i = blockIdx.x * blockDim.x + threadIdx.x;
    if (i >= (int)(BH / 4)) return;
    ((float4*)dst)[i] = ((const float4*)src)[i];
}

__global__ void heads_kernel(const float* __restrict__ h2, const float* __restrict__ W_r,
                             const float* __restrict__ b_r, const float* __restrict__ W_d,
                             const float* __restrict__ b_d,
                             float* __restrict__ outr, float* __restrict__ outd)
{
    int gw = (blockIdx.x * blockDim.x + threadIdx.x) >> 5;
    int lane = threadIdx.x & 31;
    if (gw >= Bsz) return;
    const float* hb = h2 + (size_t)gw * Hn;
    float sr = 0.f, sd = 0.f;
#pragma unroll
    for (int k = lane; k < Hn; k += 32) {
        float v = hb[k];
        sr = fmaf(v, W_r[k], sr);
        sd = fmaf(v, W_d[k], sd);
    }
#pragma unroll
    for (int o = 16; o > 0; o >>= 1) {
        sr += __shfl_down_sync(0xffffffffu, sr, o);
        sd += __shfl_down_sync(0xffffffffu, sd, o);
    }
    if (lane == 0) { outr[gw] = sr + b_r[0]; outd[gw] = sd + b_d[0]; }
}

// ---------------------------------------------------------------------------
extern "C" void kernel_launch(void* const* d_in, const int* in_sizes, int n_in,
                              void* d_out, int out_size)
{
    const float* action      = (const float*)d_in[0];
    const float* prev_hidden = (const float*)d_in[1];
    const int*   gt          = (const int*)d_in[2];
    const float* W_a         = (const float*)d_in[3];
    const float* b_a         = (const float*)d_in[4];
    const float* emb         = (const float*)d_in[5];
    const float* W_tp        = (const float*)d_in[6];
    const float* b_tp        = (const float*)d_in[7];
    const float* W_ih        = (const float*)d_in[8];
    const float* W_hh        = (const float*)d_in[9];
    const float* b_ih        = (const float*)d_in[10];
    const float* b_hh        = (const float*)d_in[11];
    const float* W_out       = (const float*)d_in[12];
    const float* b_out       = (const float*)d_in[13];
    const float* W_r         = (const float*)d_in[14];
    const float* b_r         = (const float*)d_in[15];
    const float* W_d         = (const float*)d_in[16];
    const float* b_d         = (const float*)d_in[17];
    float* out = (float*)d_out;

    static bool attr_done = false;
    if (!attr_done) {
        cudaFuncSetAttribute((const void*)gemm_h2<0, 2>, cudaFuncAttributeMaxDynamicSharedMemorySize, GEMM_SMEM2);
        cudaFuncSetAttribute((const void*)gemm_h2<0, 1>, cudaFuncAttributeMaxDynamicSharedMemorySize, GEMM_SMEM1);
        cudaFuncSetAttribute((const void*)gemm_h2<2, 1>, cudaFuncAttributeMaxDynamicSharedMemorySize, GEMM_SMEM1);
        cudaFuncSetAttribute((const void*)gru_step<0>, cudaFuncAttributeMaxDynamicSharedMemorySize, STEP_SMEM);
        cudaFuncSetAttribute((const void*)gru_step<1>, cudaFuncAttributeMaxDynamicSharedMemorySize, STEP_SMEM);
        cudaFuncSetAttribute((const void*)gru_step<2>, cudaFuncAttributeMaxDynamicSharedMemorySize, STEP_SMEM);
        attr_done = true;
    }

    __half *uAh, *uAl, *uBh, *pqh;
    __half *wih, *whh, *wo, *wt, *embh, *embl, *Pqh, *Pql;
    float *hseqF, *GI, *P, *Gtab;
    cudaGetSymbolAddress((void**)&uAh, g_uA_hi);  cudaGetSymbolAddress((void**)&uAl, g_uA_lo);
    cudaGetSymbolAddress((void**)&uBh, g_uB_hi);
    cudaGetSymbolAddress((void**)&pqh, g_pq_hi);
    cudaGetSymbolAddress((void**)&wih, g_wih);    cudaGetSymbolAddress((void**)&whh, g_whh);
    cudaGetSymbolAddress((void**)&wo,  g_wo);     cudaGetSymbolAddress((void**)&wt,  g_wt);
    cudaGetSymbolAddress((void**)&embh, g_embh);  cudaGetSymbolAddress((void**)&embl, g_embl);
    cudaGetSymbolAddress((void**)&Pqh, g_Pqh);    cudaGetSymbolAddress((void**)&Pql, g_Pql);
    cudaGetSymbolAddress((void**)&hseqF, g_hseqF);
    cudaGetSymbolAddress((void**)&GI, g_GI);
    cudaGetSymbolAddress((void**)&P, g_P);
    cudaGetSymbolAddress((void**)&Gtab, g_Gtab);

    float* outLogits = out;
    float* outReward = out + (size_t)Bsz * Tn * Cn;
    float* outDone   = outReward + Bsz;
    float* outFinal  = outDone + Bsz;

    const dim3 stepGrid(16, 32);
    __half *Uh = uAh, *Oh = uBh;

    // [0] weights -> fp16
    convW<<<(1376256 + 255) / 256, 256>>>(W_ih, W_hh, W_out, W_tp, emb,
                                          wih, whh, wo, wt, embh, embl);
    // [1] prev hidden hi + x0 2-plane
    prep_kernel<<<((int)(Ln * BH / 4 + BH / 4) + 255) / 256, 256>>>(
        prev_hidden, action, W_a, b_a, pqh, uAh, uAl);
    // [2] GI slot0 = x0 @ W_ih0.T + b_ih0 (2-plane)
    gemm_h2<0, 2><<<dim3(12, 32), 256, GEMM_SMEM2>>>(uAh, uAl, wih, b_ih, GI, H3);
    // [3] fused GRU step, layer 0, t=0  <-- ncu captures launch index 3
    gru_step<0><<<stepGrid, 256, STEP_SMEM>>>(pqh, whh, b_hh,
                                              GI, gt, 0, prev_hidden, hseqF, Oh);
    // [4] P = emb @ W_tp.T + b_tp (2-plane)
    gemm_h2<0, 2><<<dim3(4, 4), 256, GEMM_SMEM2>>>(embh, embl, wt, b_tp, P, Hn);
    // [5] P -> fp16 planes
    split2_kernel<<<((Cn * Hn / 4) + 255) / 256, 256>>>(P, Pqh, Pql, Cn * Hn / 4);
    // [6] Gtab = Pq @ W_ih0.T + b_ih0 (2-plane)
    gemm_h2<0, 2><<<dim3(12, 4), 256, GEMM_SMEM2>>>(Pqh, Pql, wih, b_ih, Gtab, H3);

    // ---- layer 0 t = 1..16 (token-table GI) ----
    for (int t = 1; t < NSTEP; t++) {
        const __half* ph = Oh + (size_t)(t - 1) * BH;
        const float* hpF = hseqF + (size_t)(t - 1) * BH;
        float*  hF = hseqF + (size_t)t * BH;
        __half* oh = Oh + (size_t)t * BH;
        if (t == 1)
            gru_step<1><<<stepGrid, 256, STEP_SMEM>>>(ph, whh, b_hh,
                                                      b_ih, gt, t, hpF, hF, oh);
        else
            gru_step<2><<<stepGrid, 256, STEP_SMEM>>>(ph, whh, b_hh,
                                                      Gtab, gt, t, hpF, hF, oh);
    }
    copyf4_kernel<<<((int)(BH / 4) + 255) / 256, 256>>>(
        hseqF + (size_t)16 * BH, outFinal);
    { __half* tp = Uh; Uh = Oh; Oh = tp; }

    // ---- layers 1, 2: 1-plane batched GI + fused 1-plane steps ----
    for (int l = 1; l < Ln; l++) {
        gemm_h2<0, 1><<<dim3(12, 544), 256, GEMM_SMEM1>>>(
            Uh, nullptr, wih + (size_t)l * H3 * Hn, b_ih + l * H3, GI, H3);
        for (int t = 0; t < NSTEP; t++) {
            const __half* ph = t ? (Oh + (size_t)(t - 1) * BH) : (pqh + (size_t)l * BH);
            const float* hpF = t ? (hseqF + (size_t)(t - 1) * BH)
                                 : (prev_hidden + (size_t)l * BH);
            gru_step<0><<<stepGrid, 256, STEP_SMEM>>>(
                ph, whh + (size_t)l * H3 * Hn, b_hh + l * H3,
                GI + (size_t)t * BH3, gt, t,
                hpF, hseqF + (size_t)t * BH, Oh + (size_t)t * BH);
        }
        copyf4_kernel<<<((int)(BH / 4) + 255) / 256, 256>>>(
            hseqF + (size_t)16 * BH, outFinal + (size_t)l * BH);
        __half* tp = Uh; Uh = Oh; Oh = tp;
    }

    // ---- logits over scan slots 1..16 (1-plane A) ----
    gemm_h2<2, 1><<<dim3(4, 512), 256, GEMM_SMEM1>>>(
        Uh + BH, nullptr, wo, b_out, outLogits, 0);

    // ---- reward / done heads ----
    heads_kernel<<<(Bsz * 32 + 255) / 256, 256>>>(
        hseqF, W_r, b_r, W_d, b_d, outReward, outDone);
}

// round 10
// speedup vs baseline: 5.3681x; 1.0675x over previous
#include <cuda_runtime.h>
#include <cuda_fp16.h>
#include <cstdint>
#include <math.h>

// ---------------- problem constants ----------------
#define Bsz   4096
#define Hn    512
#define H3    1536
#define Ln    3
#define Tn    16
#define Cn    512
#define NSTEP 17
#define KDIM  512
#define NCH   8            // K chunks of 64 fp16 (128B rows)

static const size_t BH  = (size_t)Bsz * Hn;
static const size_t BH3 = (size_t)Bsz * H3;

// ---------------- persistent device scratch ----------------
__device__ __align__(128) __half g_uA_hi[(size_t)NSTEP * Bsz * Hn];
__device__ __align__(128) __half g_uA_lo[(size_t)Bsz * Hn];          // x0 lo only
__device__ __align__(128) __half g_uB_hi[(size_t)NSTEP * Bsz * Hn];
__device__ __align__(128) __half g_pq_hi[(size_t)Ln * Bsz * Hn];
__device__ __align__(128) float  g_hseqF[(size_t)NSTEP * Bsz * Hn];
__device__ __align__(128) __half g_GIh[(size_t)NSTEP * Bsz * H3];    // fp16 input gates
__device__ __align__(128) __half g_wih[(size_t)Ln * H3 * Hn];
__device__ __align__(128) __half g_whh[(size_t)Ln * H3 * Hn];
__device__ __align__(128) __half g_wo[(size_t)Cn * Hn];
__device__ __align__(128) __half g_wt[(size_t)Hn * Hn];
__device__ __align__(128) __half g_embh[(size_t)Cn * Hn];
__device__ __align__(128) __half g_embl[(size_t)Cn * Hn];
__device__ __align__(128) float  g_P[(size_t)Cn * Hn];
__device__ __align__(128) __half g_Pqh[(size_t)Cn * Hn];
__device__ __align__(128) __half g_Pql[(size_t)Cn * Hn];
__device__ __align__(128) __half g_Gtabh[(size_t)Cn * H3];           // fp16 token table

// ---------------- PTX helpers ----------------
__device__ __forceinline__ uint32_t smem_u32(const void* p) {
    uint32_t a;
    asm("{ .reg .u64 t; cvta.to.shared.u64 t, %1; cvt.u32.u64 %0, t; }" : "=r"(a) : "l"(p));
    return a;
}
__device__ __forceinline__ void cpasync16(uint32_t s, const void* g) {
    asm volatile("cp.async.cg.shared.global [%0], [%1], 16;" :: "r"(s), "l"(g));
}
__device__ __forceinline__ void cp_commit() {
    asm volatile("cp.async.commit_group;" ::: "memory");
}
template <int N> __device__ __forceinline__ void cp_wait() {
    asm volatile("cp.async.wait_group %0;" :: "n"(N) : "memory");
}
__device__ __forceinline__ void ldsm4(uint32_t& r0, uint32_t& r1, uint32_t& r2, uint32_t& r3,
                                      uint32_t addr) {
    asm volatile("ldmatrix.sync.aligned.m8n8.x4.shared.b16 {%0,%1,%2,%3}, [%4];"
                 : "=r"(r0), "=r"(r1), "=r"(r2), "=r"(r3) : "r"(addr));
}
__device__ __forceinline__ void hmma16816(float* d, const uint32_t* a, uint32_t b0, uint32_t b1) {
    asm volatile(
        "mma.sync.aligned.m16n8k16.row.col.f32.f16.f16.f32 "
        "{%0,%1,%2,%3}, {%4,%5,%6,%7}, {%8,%9}, {%0,%1,%2,%3};"
        : "+f"(d[0]), "+f"(d[1]), "+f"(d[2]), "+f"(d[3])
        : "r"(a[0]), "r"(a[1]), "r"(a[2]), "r"(a[3]), "r"(b0), "r"(b1));
}

#define GEMM_SMEM2 (2 * 49152)
#define GEMM_SMEM1 (2 * 32768)
#define STEP_SMEM  (2 * 28672)

__device__ __forceinline__ float sigf(float x) { return 1.f / (1.f + __expf(-x)); }
__device__ __forceinline__ void split1h(float x, __half& h, __half& l) {
    h = __float2half_rn(x);
    l = __float2half_rn(x - __half2float(h));
}

// ---------------------------------------------------------------------------
// fp16 GEMM, 128x128 tile. PLANES: A planes. OUTH: 1 => fp16 C.
// MODE 0: row-major C (ld = ldc_or_slot).
// MODE 3: per-slot logits chunk: C[b, slot, n] (fp32), slot = ldc_or_slot.
// ---------------------------------------------------------------------------
template <int MODE, int PLANES, int OUTH>
__global__ void __launch_bounds__(256, 2)
gemm_h2(const __half* __restrict__ Ahi, const __half* __restrict__ Alo,
        const __half* __restrict__ Bh,
        const float* __restrict__ bias, void* __restrict__ Cv, int ldc_or_slot)
{
    constexpr int STAGE = (PLANES == 2) ? 49152 : 32768;
    constexpr int BOFF  = PLANES * 16384;
    extern __shared__ __align__(128) char smem[];
    const uint32_t sb = smem_u32(smem);
    const int tid  = threadIdx.x;
    const int wid  = tid >> 5, lane = tid & 31;
    const int wM   = wid >> 1;
    const int wN   = wid & 1;
    const int m0   = blockIdx.y << 7, n0 = blockIdx.x << 7;

    const char* gAh = (const char*)(Ahi + (size_t)m0 * KDIM);
    const char* gAl = (const char*)(Alo + (size_t)m0 * KDIM);
    const char* gB  = (const char*)(Bh  + (size_t)n0 * KDIM);

    int srow[4], soff[4]; uint32_t sso[4];
#pragma unroll
    for (int q = 0; q < 4; q++) {
        int id = tid * 4 + q;
        srow[q] = id >> 3;
        soff[q] = (id & 7) << 4;
        sso[q]  = (uint32_t)((srow[q] << 7) | (soff[q] ^ ((srow[q] & 7) << 4)));
    }

    const int lr16 = lane & 15;
    const int lhi  = (lane >> 4) << 4;
    uint32_t aBase[2], aXr[2];
#pragma unroll
    for (int mt = 0; mt < 2; mt++) {
        int r = wM * 32 + mt * 16 + lr16;
        aBase[mt] = (uint32_t)(r << 7);
        aXr[mt]   = ((r & 7) << 4);
    }
    uint32_t bBase[4], bXr[4];
#pragma unroll
    for (int nt = 0; nt < 4; nt++) {
        int r = wN * 64 + nt * 16 + lr16;
        bBase[nt] = (uint32_t)(r << 7);
        bXr[nt]   = ((r & 7) << 4);
    }

    float acc[2][8][4];
#pragma unroll
    for (int i = 0; i < 2; i++)
#pragma unroll
        for (int j = 0; j < 8; j++)
#pragma unroll
            for (int v = 0; v < 4; v++) acc[i][j][v] = 0.f;

    auto load_chunk = [&](int s, int c) {
        const uint32_t st = sb + s * STAGE;
        const int cb = c * 128;
#pragma unroll
        for (int q = 0; q < 4; q++) {
            int go = srow[q] * 1024 + cb + soff[q];
            cpasync16(st + sso[q], gAh + go);
            if (PLANES == 2) cpasync16(st + 16384 + sso[q], gAl + go);
            cpasync16(st + BOFF + sso[q], gB + go);
        }
        cp_commit();
    };

    load_chunk(0, 0);

    for (int c = 0; c < NCH; c++) {
        const int s = c & 1;
        if (c + 1 < NCH) { load_chunk(s ^ 1, c + 1); cp_wait<1>(); }
        else             { cp_wait<0>(); }
        __syncthreads();

        const uint32_t stA0 = sb + s * STAGE;
        const uint32_t stA1 = stA0 + 16384;
        const uint32_t stB0 = stA0 + BOFF;

#pragma unroll
        for (int k16 = 0; k16 < 4; k16++) {
            const uint32_t ko = (uint32_t)(k16 * 32 + lhi);
            uint32_t ah[2][4], al[2][4];
#pragma unroll
            for (int mt = 0; mt < 2; mt++) {
                ldsm4(ah[mt][0], ah[mt][1], ah[mt][2], ah[mt][3],
                      stA0 + aBase[mt] + (ko ^ aXr[mt]));
                if (PLANES == 2)
                    ldsm4(al[mt][0], al[mt][1], al[mt][2], al[mt][3],
                          stA1 + aBase[mt] + (ko ^ aXr[mt]));
            }
            uint32_t bh[4][4];
#pragma unroll
            for (int nt = 0; nt < 4; nt++)
                ldsm4(bh[nt][0], bh[nt][1], bh[nt][2], bh[nt][3],
                      stB0 + bBase[nt] + (ko ^ bXr[nt]));
#pragma unroll
            for (int mt = 0; mt < 2; mt++)
#pragma unroll
                for (int nt = 0; nt < 4; nt++) {
                    hmma16816(acc[mt][2 * nt + 0], ah[mt], bh[nt][0], bh[nt][2]);
                    hmma16816(acc[mt][2 * nt + 1], ah[mt], bh[nt][1], bh[nt][3]);
                    if (PLANES == 2) {
                        hmma16816(acc[mt][2 * nt + 0], al[mt], bh[nt][0], bh[nt][2]);
                        hmma16816(acc[mt][2 * nt + 1], al[mt], bh[nt][1], bh[nt][3]);
                    }
                }
        }
        __syncthreads();
    }

    const int lr = lane >> 2;
    const int lc = (lane & 3) << 1;
#pragma unroll
    for (int mt = 0; mt < 2; mt++) {
        const int mBase = m0 + wM * 32 + mt * 16 + lr;
#pragma unroll
        for (int nt = 0; nt < 8; nt++) {
            const int n = n0 + wN * 64 + nt * 8 + lc;
            const float b0 = bias[n], b1 = bias[n + 1];
            float2 v0 = make_float2(acc[mt][nt][0] + b0, acc[mt][nt][1] + b1);
            float2 v1 = make_float2(acc[mt][nt][2] + b0, acc[mt][nt][3] + b1);
            size_t o0, o1;
            if (MODE == 3) {
                o0 = (size_t)mBase * (Tn * Cn) + (size_t)ldc_or_slot * Cn + n;
                o1 = (size_t)(mBase + 8) * (Tn * Cn) + (size_t)ldc_or_slot * Cn + n;
            } else {
                o0 = (size_t)mBase * ldc_or_slot + n;
                o1 = (size_t)(mBase + 8) * ldc_or_slot + n;
            }
            if (OUTH) {
                __half* C = (__half*)Cv;
                *(__half2*)(C + o0) = __floats2half2_rn(v0.x, v0.y);
                *(__half2*)(C + o1) = __floats2half2_rn(v1.x, v1.y);
            } else {
                float* C = (float*)Cv;
                *(float2*)(C + o0) = v0;
                *(float2*)(C + o1) = v1;
            }
        }
    }
}

// ---------------------------------------------------------------------------
// FUSED GRU step, single-plane fp16 hidden state.
// GIMODE: 0 = fp16 GI slice [B,3H]; 1 = fp32 bias row; 2 = fp16 token table.
// ---------------------------------------------------------------------------
template <int GIMODE>
__global__ void __launch_bounds__(256, 2)
gru_step(const __half* __restrict__ Ahi,
         const __half* __restrict__ W, const float* __restrict__ bhh,
         const void* __restrict__ GIt, const int* __restrict__ gt, int step,
         const float* __restrict__ hprevF, float* __restrict__ houtF,
         __half* __restrict__ hi)
{
    extern __shared__ __align__(128) char smem[];
    const uint32_t sb = smem_u32(smem);
    const int tid  = threadIdx.x;
    const int wid  = tid >> 5, lane = tid & 31;
    const int wM   = wid >> 1;
    const int wN   = wid & 1;
    const int m0   = blockIdx.y << 7;
    const int j0   = blockIdx.x << 5;

    const char* gAh = (const char*)(Ahi + (size_t)m0 * KDIM);
    const char* gW  = (const char*)W;

    int srow[4], soff[4]; uint32_t sso[4];
#pragma unroll
    for (int q = 0; q < 4; q++) {
        int id = tid * 4 + q;
        srow[q] = id >> 3;
        soff[q] = (id & 7) << 4;
        sso[q]  = (uint32_t)((srow[q] << 7) | (soff[q] ^ ((srow[q] & 7) << 4)));
    }
    int bgr[3], boff[3]; uint32_t bso[3];
#pragma unroll
    for (int q = 0; q < 3; q++) {
        int id = tid * 3 + q;
        int rb = id >> 3;
        boff[q] = (id & 7) << 4;
        bgr[q]  = j0 + (rb & 31) + (rb >> 5) * 512;
        bso[q]  = (uint32_t)((rb << 7) | (boff[q] ^ ((rb & 7) << 4)));
    }

    const int lr16 = lane & 15;
    const int lhi  = (lane >> 4) << 4;
    uint32_t aBase[2], aXr[2];
#pragma unroll
    for (int mt = 0; mt < 2; mt++) {
        int r = wM * 32 + mt * 16 + lr16;
        aBase[mt] = (uint32_t)(r << 7);
        aXr[mt]   = ((r & 7) << 4);
    }
    uint32_t bBase[3], bXr[3];
#pragma unroll
    for (int g = 0; g < 3; g++) {
        int r = wN * 16 + g * 32 + lr16;
        bBase[g] = (uint32_t)(r << 7);
        bXr[g]   = ((r & 7) << 4);
    }

    float acc[2][3][2][4];
#pragma unroll
    for (int i = 0; i < 2; i++)
#pragma unroll
        for (int g = 0; g < 3; g++)
#pragma unroll
            for (int a = 0; a < 2; a++)
#pragma unroll
                for (int v = 0; v < 4; v++) acc[i][g][a][v] = 0.f;

    auto load_chunk = [&](int s, int c) {
        const uint32_t st = sb + s * 28672;
        const int cb = c * 128;
#pragma unroll
        for (int q = 0; q < 4; q++) {
            int go = srow[q] * 1024 + cb + soff[q];
            cpasync16(st + sso[q], gAh + go);
        }
#pragma unroll
        for (int q = 0; q < 3; q++) {
            int go = bgr[q] * 1024 + cb + boff[q];
            cpasync16(st + 16384 + bso[q], gW + go);
        }
        cp_commit();
    };

    load_chunk(0, 0);

    for (int c = 0; c < NCH; c++) {
        const int s = c & 1;
        if (c + 1 < NCH) { load_chunk(s ^ 1, c + 1); cp_wait<1>(); }
        else             { cp_wait<0>(); }
        __syncthreads();

        const uint32_t stA0 = sb + s * 28672;
        const uint32_t stB0 = stA0 + 16384;

#pragma unroll
        for (int k16 = 0; k16 < 4; k16++) {
            const uint32_t ko = (uint32_t)(k16 * 32 + lhi);
            uint32_t ah[2][4];
#pragma unroll
            for (int mt = 0; mt < 2; mt++)
                ldsm4(ah[mt][0], ah[mt][1], ah[mt][2], ah[mt][3],
                      stA0 + aBase[mt] + (ko ^ aXr[mt]));
            uint32_t bh[3][4];
#pragma unroll
            for (int g = 0; g < 3; g++)
                ldsm4(bh[g][0], bh[g][1], bh[g][2], bh[g][3],
                      stB0 + bBase[g] + (ko ^ bXr[g]));
#pragma unroll
            for (int mt = 0; mt < 2; mt++)
#pragma unroll
                for (int g = 0; g < 3; g++) {
                    hmma16816(acc[mt][g][0], ah[mt], bh[g][0], bh[g][2]);
                    hmma16816(acc[mt][g][1], ah[mt], bh[g][1], bh[g][3]);
                }
        }
        __syncthreads();
    }

    const int lr = lane >> 2;
    const int lc = (lane & 3) << 1;
#pragma unroll
    for (int mt = 0; mt < 2; mt++) {
        const int mBase = m0 + wM * 32 + mt * 16 + lr;
#pragma unroll
        for (int a = 0; a < 2; a++) {
            const int j = j0 + wN * 16 + a * 8 + lc;
            const float2 bR = *(const float2*)(bhh + j);
            const float2 bZ = *(const float2*)(bhh + 512 + j);
            const float2 bN = *(const float2*)(bhh + 1024 + j);
#pragma unroll
            for (int hh = 0; hh < 2; hh++) {
                const int row = mBase + hh * 8;
                const int vi = hh * 2;
                float2 gR, gZ, gN;
                if (GIMODE == 1) {
                    const float* gi = (const float*)GIt + j;
                    gR = *(const float2*)(gi);
                    gZ = *(const float2*)(gi + 512);
                    gN = *(const float2*)(gi + 1024);
                } else {
                    const __half* gi;
                    if (GIMODE == 0)
                        gi = (const __half*)GIt + (size_t)row * H3 + j;
                    else {
                        int tok = gt[row * Tn + (step - 2)];
                        gi = (const __half*)GIt + (size_t)tok * H3 + j;
                    }
                    gR = __half22float2(*(const __half2*)(gi));
                    gZ = __half22float2(*(const __half2*)(gi + 512));
                    gN = __half22float2(*(const __half2*)(gi + 1024));
                }
                float2 hp = *(const float2*)(hprevF + (size_t)row * Hn + j);
                float r0 = sigf(gR.x + acc[mt][0][a][vi]     + bR.x);
                float r1 = sigf(gR.y + acc[mt][0][a][vi + 1] + bR.y);
                float z0 = sigf(gZ.x + acc[mt][1][a][vi]     + bZ.x);
                float z1 = sigf(gZ.y + acc[mt][1][a][vi + 1] + bZ.y);
                float n0 = tanhf(gN.x + r0 * (acc[mt][2][a][vi]     + bN.x));
                float n1 = tanhf(gN.y + r1 * (acc[mt][2][a][vi + 1] + bN.y));
                float h0 = (1.f - z0) * n0 + z0 * hp.x;
                float h1 = (1.f - z1) * n1 + z1 * hp.y;
                size_t oh = (size_t)row * Hn + j;
                *(float2*)(houtF + oh) = make_float2(h0, h1);
                *(__half2*)(hi + oh) = __floats2half2_rn(h0, h1);
            }
        }
    }
}

// ---------------- elementwise kernels ----------------
__global__ void convW(const float* __restrict__ W_ih, const float* __restrict__ W_hh,
                      const float* __restrict__ W_out, const float* __restrict__ W_tp,
                      const float* __restrict__ emb,
                      __half* __restrict__ wih, __half* __restrict__ whh,
                      __half* __restrict__ wo,  __half* __restrict__ wt,
                      __half* __restrict__ embh, __half* __restrict__ embl)
{
    int i = blockIdx.x * blockDim.x + threadIdx.x;
    if (i >= 1376256) return;
    if (i < 1310720) {
        const float* s; __half* d; int j;
        if (i < 589824)       { s = W_ih;  d = wih; j = i; }
        else if (i < 1179648) { s = W_hh;  d = whh; j = i - 589824; }
        else if (i < 1245184) { s = W_out; d = wo;  j = i - 1179648; }
        else                  { s = W_tp;  d = wt;  j = i - 1245184; }
        float4 v = ((const float4*)s)[j];
        ((__half2*)d)[2 * j + 0] = __floats2half2_rn(v.x, v.y);
        ((__half2*)d)[2 * j + 1] = __floats2half2_rn(v.z, v.w);
    } else {
        int j = i - 1310720;
        float4 v = ((const float4*)emb)[j];
        __half h0, h1, h2, h3, l0, l1, l2, l3;
        split1h(v.x, h0, l0); split1h(v.y, h1, l1);
        split1h(v.z, h2, l2); split1h(v.w, h3, l3);
        ((__half2*)embh)[2 * j + 0] = __halves2half2(h0, h1);
        ((__half2*)embh)[2 * j + 1] = __halves2half2(h2, h3);
        ((__half2*)embl)[2 * j + 0] = __halves2half2(l0, l1);
        ((__half2*)embl)[2 * j + 1] = __halves2half2(l2, l3);
    }
}

__global__ void prep_kernel(const float* __restrict__ prev,
                            const float* __restrict__ action,
                            const float* __restrict__ W_a, const float* __restrict__ b_a,
                            __half* __restrict__ pqh,
                            __half* __restrict__ x0h, __half* __restrict__ x0l)
{
    const int NPREV = (int)(Ln * BH / 4);
    int i = blockIdx.x * blockDim.x + threadIdx.x;
    if (i < NPREV) {
        float4 v = ((const float4*)prev)[i];
        ((__half2*)pqh)[2 * i + 0] = __floats2half2_rn(v.x, v.y);
        ((__half2*)pqh)[2 * i + 1] = __floats2half2_rn(v.z, v.w);
    } else if (i < NPREV + (int)(BH / 4)) {
        int j = i - NPREV;
        int e0 = j * 4;
        int b = e0 >> 9, c = e0 & 511;
        float a0 = action[b * 3 + 0], a1 = action[b * 3 + 1], a2 = action[b * 3 + 2];
        __half hs[4], ls[4];
#pragma unroll
        for (int q = 0; q < 4; q++) {
            int jj = c + q;
            float s = b_a[jj] + a0 * W_a[jj * 3 + 0] + a1 * W_a[jj * 3 + 1]
                              + a2 * W_a[jj * 3 + 2];
            split1h(s, hs[q], ls[q]);
        }
        ((__half2*)x0h)[2 * j + 0] = __halves2half2(hs[0], hs[1]);
        ((__half2*)x0h)[2 * j + 1] = __halves2half2(hs[2], hs[3]);
        ((__half2*)x0l)[2 * j + 0] = __halves2half2(ls[0], ls[1]);
        ((__half2*)x0l)[2 * j + 1] = __halves2half2(ls[2], ls[3]);
    }
}

__global__ void split2_kernel(const float* __restrict__ src,
                              __half* __restrict__ hi, __half* __restrict__ lo, int n4)
{
    int i = blockIdx.x * blockDim.x + threadIdx.x;
    if (i >= n4) return;
    float4 v = ((const float4*)src)[i];
    __half h0, h1, h2, h3, l0, l1, l2, l3;
    split1h(v.x, h0, l0); split1h(v.y, h1, l1);
    split1h(v.z, h2, l2); split1h(v.w, h3, l3);
    ((__half2*)hi)[2 * i + 0] = __halves2half2(h0, h1);
    ((__half2*)hi)[2 * i + 1] = __halves2half2(h2, h3);
    ((__half2*)lo)[2 * i + 0] = __halves2half2(l0, l1);
    ((__half2*)lo)[2 * i + 1] = __halves2half2(l2, l3);
}

__global__ void copyf4_kernel(const float* __restrict__ src, float* __restrict__ dst)
{
    int i = blockIdx.x * blockDim.x + threadIdx.x;
    if (i >= (int)(BH / 4)) return;
    ((float4*)dst)[i] = ((const float4*)src)[i];
}

__global__ void heads_kernel(const float* __restrict__ h2, const float* __restrict__ W_r,
                             const float* __restrict__ b_r, const float* __restrict__ W_d,
                             const float* __restrict__ b_d,
                             float* __restrict__ outr, float* __restrict__ outd)
{
    int gw = (blockIdx.x * blockDim.x + threadIdx.x) >> 5;
    int lane = threadIdx.x & 31;
    if (gw >= Bsz) return;
    const float* hb = h2 + (size_t)gw * Hn;
    float sr = 0.f, sd = 0.f;
#pragma unroll
    for (int k = lane; k < Hn; k += 32) {
        float v = hb[k];
        sr = fmaf(v, W_r[k], sr);
        sd = fmaf(v, W_d[k], sd);
    }
#pragma unroll
    for (int o = 16; o > 0; o >>= 1) {
        sr += __shfl_down_sync(0xffffffffu, sr, o);
        sd += __shfl_down_sync(0xffffffffu, sd, o);
    }
    if (lane == 0) { outr[gw] = sr + b_r[0]; outd[gw] = sd + b_d[0]; }
}

// ---------------------------------------------------------------------------
extern "C" void kernel_launch(void* const* d_in, const int* in_sizes, int n_in,
                              void* d_out, int out_size)
{
    const float* action      = (const float*)d_in[0];
    const float* prev_hidden = (const float*)d_in[1];
    const int*   gt          = (const int*)d_in[2];
    const float* W_a         = (const float*)d_in[3];
    const float* b_a         = (const float*)d_in[4];
    const float* emb         = (const float*)d_in[5];
    const float* W_tp        = (const float*)d_in[6];
    const float* b_tp        = (const float*)d_in[7];
    const float* W_ih        = (const float*)d_in[8];
    const float* W_hh        = (const float*)d_in[9];
    const float* b_ih        = (const float*)d_in[10];
    const float* b_hh        = (const float*)d_in[11];
    const float* W_out       = (const float*)d_in[12];
    const float* b_out       = (const float*)d_in[13];
    const float* W_r         = (const float*)d_in[14];
    const float* b_r         = (const float*)d_in[15];
    const float* W_d         = (const float*)d_in[16];
    const float* b_d         = (const float*)d_in[17];
    float* out = (float*)d_out;

    static cudaStream_t s2 = nullptr;
    static cudaEvent_t evp[160];
    if (!s2) {
        cudaStreamCreateWithFlags(&s2, cudaStreamNonBlocking);
        for (int i = 0; i < 160; i++)
            cudaEventCreateWithFlags(&evp[i], cudaEventDisableTiming);
        cudaFuncSetAttribute((const void*)gemm_h2<0, 2, 0>, cudaFuncAttributeMaxDynamicSharedMemorySize, GEMM_SMEM2);
        cudaFuncSetAttribute((const void*)gemm_h2<0, 2, 1>, cudaFuncAttributeMaxDynamicSharedMemorySize, GEMM_SMEM2);
        cudaFuncSetAttribute((const void*)gemm_h2<0, 1, 1>, cudaFuncAttributeMaxDynamicSharedMemorySize, GEMM_SMEM1);
        cudaFuncSetAttribute((const void*)gemm_h2<3, 1, 0>, cudaFuncAttributeMaxDynamicSharedMemorySize, GEMM_SMEM1);
        cudaFuncSetAttribute((const void*)gru_step<0>, cudaFuncAttributeMaxDynamicSharedMemorySize, STEP_SMEM);
        cudaFuncSetAttribute((const void*)gru_step<1>, cudaFuncAttributeMaxDynamicSharedMemorySize, STEP_SMEM);
        cudaFuncSetAttribute((const void*)gru_step<2>, cudaFuncAttributeMaxDynamicSharedMemorySize, STEP_SMEM);
    }
    int ev = 0;

    __half *uAh, *uAl, *uBh, *pqh;
    __half *wih, *whh, *wo, *wt, *embh, *embl, *Pqh, *Pql, *GIh, *Gtabh;
    float *hseqF, *P;
    cudaGetSymbolAddress((void**)&uAh, g_uA_hi);  cudaGetSymbolAddress((void**)&uAl, g_uA_lo);
    cudaGetSymbolAddress((void**)&uBh, g_uB_hi);
    cudaGetSymbolAddress((void**)&pqh, g_pq_hi);
    cudaGetSymbolAddress((void**)&wih, g_wih);    cudaGetSymbolAddress((void**)&whh, g_whh);
    cudaGetSymbolAddress((void**)&wo,  g_wo);     cudaGetSymbolAddress((void**)&wt,  g_wt);
    cudaGetSymbolAddress((void**)&embh, g_embh);  cudaGetSymbolAddress((void**)&embl, g_embl);
    cudaGetSymbolAddress((void**)&Pqh, g_Pqh);    cudaGetSymbolAddress((void**)&Pql, g_Pql);
    cudaGetSymbolAddress((void**)&hseqF, g_hseqF);
    cudaGetSymbolAddress((void**)&GIh, g_GIh);
    cudaGetSymbolAddress((void**)&P, g_P);
    cudaGetSymbolAddress((void**)&Gtabh, g_Gtabh);

    float* outLogits = out;
    float* outReward = out + (size_t)Bsz * Tn * Cn;
    float* outDone   = outReward + Bsz;
    float* outFinal  = outDone + Bsz;

    const dim3 stepGrid(16, 32);
    __half *Uh = uAh, *Oh = uBh;

    // ---- preamble (main stream) ----
    convW<<<(1376256 + 255) / 256, 256>>>(W_ih, W_hh, W_out, W_tp, emb,
                                          wih, whh, wo, wt, embh, embl);
    prep_kernel<<<((int)(Ln * BH / 4 + BH / 4) + 255) / 256, 256>>>(
        prev_hidden, action, W_a, b_a, pqh, uAh, uAl);
    // GI slot0 (fp16 out, 2-plane x0)
    gemm_h2<0, 2, 1><<<dim3(12, 32), 256, GEMM_SMEM2>>>(uAh, uAl, wih, b_ih, GIh, H3);
    // P = emb @ W_tp.T + b_tp
    gemm_h2<0, 2, 0><<<dim3(4, 4), 256, GEMM_SMEM2>>>(embh, embl, wt, b_tp, P, Hn);
    split2_kernel<<<((Cn * Hn / 4) + 255) / 256, 256>>>(P, Pqh, Pql, Cn * Hn / 4);
    // Gtab (fp16 out)
    gemm_h2<0, 2, 1><<<dim3(12, 4), 256, GEMM_SMEM2>>>(Pqh, Pql, wih, b_ih, Gtabh, H3);

    int evGI[NSTEP];

    // ---- layer 0 (token-table GI); side stream computes layer-1 GI chunks ----
    for (int t = 0; t < NSTEP; t++) {
        const __half* ph = t ? (Oh + (size_t)(t - 1) * BH) : pqh;
        const float* hpF = t ? (hseqF + (size_t)(t - 1) * BH) : prev_hidden;
        float*  hF = hseqF + (size_t)t * BH;
        __half* oh = Oh + (size_t)t * BH;
        if (t == 0)
            gru_step<0><<<stepGrid, 256, STEP_SMEM>>>(ph, whh, b_hh,
                                                      GIh, gt, t, hpF, hF, oh);
        else if (t == 1)
            gru_step<1><<<stepGrid, 256, STEP_SMEM>>>(ph, whh, b_hh,
                                                      b_ih, gt, t, hpF, hF, oh);
        else
            gru_step<2><<<stepGrid, 256, STEP_SMEM>>>(ph, whh, b_hh,
                                                      Gtabh, gt, t, hpF, hF, oh);
        // side: GI chunk for layer 1, slot t
        cudaEventRecord(evp[ev], 0);
        cudaStreamWaitEvent(s2, evp[ev], 0); ev++;
        gemm_h2<0, 1, 1><<<dim3(12, 32), 256, GEMM_SMEM1, s2>>>(
            oh, nullptr, wih + (size_t)1 * H3 * Hn, b_ih + 1 * H3,
            GIh + (size_t)t * BH3, H3);
        cudaEventRecord(evp[ev], s2);
        evGI[t] = ev; ev++;
    }
    copyf4_kernel<<<((int)(BH / 4) + 255) / 256, 256>>>(
        hseqF + (size_t)16 * BH, outFinal);
    { __half* tp = Uh; Uh = Oh; Oh = tp; }

    // ---- layer 1; side computes layer-2 GI chunks ----
    for (int t = 0; t < NSTEP; t++) {
        cudaStreamWaitEvent(0, evp[evGI[t]], 0);
        const __half* ph = t ? (Oh + (size_t)(t - 1) * BH) : (pqh + BH);
        const float* hpF = t ? (hseqF + (size_t)(t - 1) * BH) : (prev_hidden + BH);
        float*  hF = hseqF + (size_t)t * BH;
        __half* oh = Oh + (size_t)t * BH;
        gru_step<0><<<stepGrid, 256, STEP_SMEM>>>(
            ph, whh + (size_t)1 * H3 * Hn, b_hh + 1 * H3,
            GIh + (size_t)t * BH3, gt, t, hpF, hF, oh);
        cudaEventRecord(evp[ev], 0);
        cudaStreamWaitEvent(s2, evp[ev], 0); ev++;
        gemm_h2<0, 1, 1><<<dim3(12, 32), 256, GEMM_SMEM1, s2>>>(
            oh, nullptr, wih + (size_t)2 * H3 * Hn, b_ih + 2 * H3,
            GIh + (size_t)t * BH3, H3);
        cudaEventRecord(evp[ev], s2);
        evGI[t] = ev; ev++;
    }
    copyf4_kernel<<<((int)(BH / 4) + 255) / 256, 256>>>(
        hseqF + (size_t)16 * BH, outFinal + BH);
    { __half* tp = Uh; Uh = Oh; Oh = tp; }

    // ---- layer 2; side computes logits chunks for slots 1..16 ----
    int lastSide = -1;
    for (int t = 0; t < NSTEP; t++) {
        cudaStreamWaitEvent(0, evp[evGI[t]], 0);
        const __half* ph = t ? (Oh + (size_t)(t - 1) * BH) : (pqh + 2 * BH);
        const float* hpF = t ? (hseqF + (size_t)(t - 1) * BH) : (prev_hidden + 2 * BH);
        float*  hF = hseqF + (size_t)t * BH;
        __half* oh = Oh + (size_t)t * BH;
        gru_step<0><<<stepGrid, 256, STEP_SMEM>>>(
            ph, whh + (size_t)2 * H3 * Hn, b_hh + 2 * H3,
            GIh + (size_t)t * BH3, gt, t, hpF, hF, oh);
        if (t >= 1) {
            cudaEventRecord(evp[ev], 0);
            cudaStreamWaitEvent(s2, evp[ev], 0); ev++;
            gemm_h2<3, 1, 0><<<dim3(4, 32), 256, GEMM_SMEM1, s2>>>(
                oh, nullptr, wo, b_out, outLogits, t - 1);
            cudaEventRecord(evp[ev], s2);
            lastSide = ev; ev++;
        }
    }
    copyf4_kernel<<<((int)(BH / 4) + 255) / 256, 256>>>(
        hseqF + (size_t)16 * BH, outFinal + 2 * BH);
    heads_kernel<<<(Bsz * 32 + 255) / 256, 256>>>(
        hseqF, W_r, b_r, W_d, b_d, outReward, outDone);
    // join side stream back into main before returning
    cudaStreamWaitEvent(0, evp[lastSide], 0);
}

// round 11
// speedup vs baseline: 6.1410x; 1.1440x over previous
#include <cuda_runtime.h>
#include <cuda_fp16.h>
#include <cstdint>
#include <math.h>

// ---------------- problem constants ----------------
#define Bsz   4096
#define Hn    512
#define H3    1536
#define Ln    3
#define Tn    16
#define Cn    512
#define NSTEP 17
#define KDIM  512
#define NCH   8            // K chunks of 64 fp16 (128B rows)

static const size_t BH  = (size_t)Bsz * Hn;
static const size_t BH3 = (size_t)Bsz * H3;

// ---------------- persistent device scratch ----------------
__device__ __align__(128) __half g_u0[(size_t)NSTEP * Bsz * Hn];   // layer0 fp16 out
__device__ __align__(128) __half g_u1[(size_t)NSTEP * Bsz * Hn];   // layer1 fp16 out
__device__ __align__(128) __half g_u2[(size_t)NSTEP * Bsz * Hn];   // layer2 fp16 out
__device__ __align__(128) __half g_x0h[(size_t)Bsz * Hn];
__device__ __align__(128) __half g_x0l[(size_t)Bsz * Hn];
__device__ __align__(128) __half g_pq_hi[(size_t)Ln * Bsz * Hn];
__device__ __align__(128) float  g_h0F[(size_t)NSTEP * Bsz * Hn];  // per-layer fp32 state
__device__ __align__(128) float  g_h1F[(size_t)NSTEP * Bsz * Hn];
__device__ __align__(128) float  g_h2F[(size_t)NSTEP * Bsz * Hn];
__device__ __align__(128) __half g_GIh[(size_t)NSTEP * Bsz * H3];  // fp16 input gates
__device__ __align__(128) __half g_wih[(size_t)Ln * H3 * Hn];
__device__ __align__(128) __half g_whh[(size_t)Ln * H3 * Hn];
__device__ __align__(128) __half g_wo[(size_t)Cn * Hn];
__device__ __align__(128) __half g_wt[(size_t)Hn * Hn];
__device__ __align__(128) __half g_embh[(size_t)Cn * Hn];
__device__ __align__(128) __half g_embl[(size_t)Cn * Hn];
__device__ __align__(128) float  g_P[(size_t)Cn * Hn];
__device__ __align__(128) __half g_Pqh[(size_t)Cn * Hn];
__device__ __align__(128) __half g_Pql[(size_t)Cn * Hn];
__device__ __align__(128) __half g_Gtabh[(size_t)Cn * H3];

// ---------------- PTX helpers ----------------
__device__ __forceinline__ uint32_t smem_u32(const void* p) {
    uint32_t a;
    asm("{ .reg .u64 t; cvta.to.shared.u64 t, %1; cvt.u32.u64 %0, t; }" : "=r"(a) : "l"(p));
    return a;
}
__device__ __forceinline__ void cpasync16(uint32_t s, const void* g) {
    asm volatile("cp.async.cg.shared.global [%0], [%1], 16;" :: "r"(s), "l"(g));
}
__device__ __forceinline__ void cp_commit() {
    asm volatile("cp.async.commit_group;" ::: "memory");
}
template <int N> __device__ __forceinline__ void cp_wait() {
    asm volatile("cp.async.wait_group %0;" :: "n"(N) : "memory");
}
__device__ __forceinline__ void ldsm4(uint32_t& r0, uint32_t& r1, uint32_t& r2, uint32_t& r3,
                                      uint32_t addr) {
    asm volatile("ldmatrix.sync.aligned.m8n8.x4.shared.b16 {%0,%1,%2,%3}, [%4];"
                 : "=r"(r0), "=r"(r1), "=r"(r2), "=r"(r3) : "r"(addr));
}
__device__ __forceinline__ void hmma16816(float* d, const uint32_t* a, uint32_t b0, uint32_t b1) {
    asm volatile(
        "mma.sync.aligned.m16n8k16.row.col.f32.f16.f16.f32 "
        "{%0,%1,%2,%3}, {%4,%5,%6,%7}, {%8,%9}, {%0,%1,%2,%3};"
        : "+f"(d[0]), "+f"(d[1]), "+f"(d[2]), "+f"(d[3])
        : "r"(a[0]), "r"(a[1]), "r"(a[2]), "r"(a[3]), "r"(b0), "r"(b1));
}

#define GEMM_SMEM2 (2 * 49152)
#define GEMM_SMEM1 (2 * 32768)
#define STEP_SMEM  (2 * 28672)

__device__ __forceinline__ float sigf(float x) { return 1.f / (1.f + __expf(-x)); }
__device__ __forceinline__ void split1h(float x, __half& h, __half& l) {
    h = __float2half_rn(x);
    l = __float2half_rn(x - __half2float(h));
}

// ---------------------------------------------------------------------------
// fp16 GEMM, 128x128 tile. PLANES: A planes. OUTH: 1 => fp16 C.
// MODE 0: row-major C (ld = ldc_or_slot).
// MODE 3: logits chunk: C[b, slot, n] fp32, slot = ldc_or_slot.
// ---------------------------------------------------------------------------
template <int MODE, int PLANES, int OUTH>
__global__ void __launch_bounds__(256, 2)
gemm_h2(const __half* __restrict__ Ahi, const __half* __restrict__ Alo,
        const __half* __restrict__ Bh,
        const float* __restrict__ bias, void* __restrict__ Cv, int ldc_or_slot)
{
    constexpr int STAGE = (PLANES == 2) ? 49152 : 32768;
    constexpr int BOFF  = PLANES * 16384;
    extern __shared__ __align__(128) char smem[];
    const uint32_t sb = smem_u32(smem);
    const int tid  = threadIdx.x;
    const int wid  = tid >> 5, lane = tid & 31;
    const int wM   = wid >> 1;
    const int wN   = wid & 1;
    const int m0   = blockIdx.y << 7, n0 = blockIdx.x << 7;

    const char* gAh = (const char*)(Ahi + (size_t)m0 * KDIM);
    const char* gAl = (const char*)(Alo + (size_t)m0 * KDIM);
    const char* gB  = (const char*)(Bh  + (size_t)n0 * KDIM);

    int srow[4], soff[4]; uint32_t sso[4];
#pragma unroll
    for (int q = 0; q < 4; q++) {
        int id = tid * 4 + q;
        srow[q] = id >> 3;
        soff[q] = (id & 7) << 4;
        sso[q]  = (uint32_t)((srow[q] << 7) | (soff[q] ^ ((srow[q] & 7) << 4)));
    }

    const int lr16 = lane & 15;
    const int lhi  = (lane >> 4) << 4;
    uint32_t aBase[2], aXr[2];
#pragma unroll
    for (int mt = 0; mt < 2; mt++) {
        int r = wM * 32 + mt * 16 + lr16;
        aBase[mt] = (uint32_t)(r << 7);
        aXr[mt]   = ((r & 7) << 4);
    }
    uint32_t bBase[4], bXr[4];
#pragma unroll
    for (int nt = 0; nt < 4; nt++) {
        int r = wN * 64 + nt * 16 + lr16;
        bBase[nt] = (uint32_t)(r << 7);
        bXr[nt]   = ((r & 7) << 4);
    }

    float acc[2][8][4];
#pragma unroll
    for (int i = 0; i < 2; i++)
#pragma unroll
        for (int j = 0; j < 8; j++)
#pragma unroll
            for (int v = 0; v < 4; v++) acc[i][j][v] = 0.f;

    auto load_chunk = [&](int s, int c) {
        const uint32_t st = sb + s * STAGE;
        const int cb = c * 128;
#pragma unroll
        for (int q = 0; q < 4; q++) {
            int go = srow[q] * 1024 + cb + soff[q];
            cpasync16(st + sso[q], gAh + go);
            if (PLANES == 2) cpasync16(st + 16384 + sso[q], gAl + go);
            cpasync16(st + BOFF + sso[q], gB + go);
        }
        cp_commit();
    };

    load_chunk(0, 0);

    for (int c = 0; c < NCH; c++) {
        const int s = c & 1;
        if (c + 1 < NCH) { load_chunk(s ^ 1, c + 1); cp_wait<1>(); }
        else             { cp_wait<0>(); }
        __syncthreads();

        const uint32_t stA0 = sb + s * STAGE;
        const uint32_t stA1 = stA0 + 16384;
        const uint32_t stB0 = stA0 + BOFF;

#pragma unroll
        for (int k16 = 0; k16 < 4; k16++) {
            const uint32_t ko = (uint32_t)(k16 * 32 + lhi);
            uint32_t ah[2][4], al[2][4];
#pragma unroll
            for (int mt = 0; mt < 2; mt++) {
                ldsm4(ah[mt][0], ah[mt][1], ah[mt][2], ah[mt][3],
                      stA0 + aBase[mt] + (ko ^ aXr[mt]));
                if (PLANES == 2)
                    ldsm4(al[mt][0], al[mt][1], al[mt][2], al[mt][3],
                          stA1 + aBase[mt] + (ko ^ aXr[mt]));
            }
            uint32_t bh[4][4];
#pragma unroll
            for (int nt = 0; nt < 4; nt++)
                ldsm4(bh[nt][0], bh[nt][1], bh[nt][2], bh[nt][3],
                      stB0 + bBase[nt] + (ko ^ bXr[nt]));
#pragma unroll
            for (int mt = 0; mt < 2; mt++)
#pragma unroll
                for (int nt = 0; nt < 4; nt++) {
                    hmma16816(acc[mt][2 * nt + 0], ah[mt], bh[nt][0], bh[nt][2]);
                    hmma16816(acc[mt][2 * nt + 1], ah[mt], bh[nt][1], bh[nt][3]);
                    if (PLANES == 2) {
                        hmma16816(acc[mt][2 * nt + 0], al[mt], bh[nt][0], bh[nt][2]);
                        hmma16816(acc[mt][2 * nt + 1], al[mt], bh[nt][1], bh[nt][3]);
                    }
                }
        }
        __syncthreads();
    }

    const int lr = lane >> 2;
    const int lc = (lane & 3) << 1;
#pragma unroll
    for (int mt = 0; mt < 2; mt++) {
        const int mBase = m0 + wM * 32 + mt * 16 + lr;
#pragma unroll
        for (int nt = 0; nt < 8; nt++) {
            const int n = n0 + wN * 64 + nt * 8 + lc;
            const float b0 = bias[n], b1 = bias[n + 1];
            float2 v0 = make_float2(acc[mt][nt][0] + b0, acc[mt][nt][1] + b1);
            float2 v1 = make_float2(acc[mt][nt][2] + b0, acc[mt][nt][3] + b1);
            size_t o0, o1;
            if (MODE == 3) {
                o0 = (size_t)mBase * (Tn * Cn) + (size_t)ldc_or_slot * Cn + n;
                o1 = (size_t)(mBase + 8) * (Tn * Cn) + (size_t)ldc_or_slot * Cn + n;
            } else {
                o0 = (size_t)mBase * ldc_or_slot + n;
                o1 = (size_t)(mBase + 8) * ldc_or_slot + n;
            }
            if (OUTH) {
                __half* C = (__half*)Cv;
                *(__half2*)(C + o0) = __floats2half2_rn(v0.x, v0.y);
                *(__half2*)(C + o1) = __floats2half2_rn(v1.x, v1.y);
            } else {
                float* C = (float*)Cv;
                *(float2*)(C + o0) = v0;
                *(float2*)(C + o1) = v1;
            }
        }
    }
}

// ---------------------------------------------------------------------------
// FUSED GRU step, single-plane fp16 hidden state.
// GIMODE: 0 = fp16 GI slice [B,3H]; 1 = fp32 bias row; 2 = fp16 token table.
// ---------------------------------------------------------------------------
template <int GIMODE>
__global__ void __launch_bounds__(256, 2)
gru_step(const __half* __restrict__ Ahi,
         const __half* __restrict__ W, const float* __restrict__ bhh,
         const void* __restrict__ GIt, const int* __restrict__ gt, int step,
         const float* __restrict__ hprevF, float* __restrict__ houtF,
         __half* __restrict__ hi)
{
    extern __shared__ __align__(128) char smem[];
    const uint32_t sb = smem_u32(smem);
    const int tid  = threadIdx.x;
    const int wid  = tid >> 5, lane = tid & 31;
    const int wM   = wid >> 1;
    const int wN   = wid & 1;
    const int m0   = blockIdx.y << 7;
    const int j0   = blockIdx.x << 5;

    const char* gAh = (const char*)(Ahi + (size_t)m0 * KDIM);
    const char* gW  = (const char*)W;

    int srow[4], soff[4]; uint32_t sso[4];
#pragma unroll
    for (int q = 0; q < 4; q++) {
        int id = tid * 4 + q;
        srow[q] = id >> 3;
        soff[q] = (id & 7) << 4;
        sso[q]  = (uint32_t)((srow[q] << 7) | (soff[q] ^ ((srow[q] & 7) << 4)));
    }
    int bgr[3], boff[3]; uint32_t bso[3];
#pragma unroll
    for (int q = 0; q < 3; q++) {
        int id = tid * 3 + q;
        int rb = id >> 3;
        boff[q] = (id & 7) << 4;
        bgr[q]  = j0 + (rb & 31) + (rb >> 5) * 512;
        bso[q]  = (uint32_t)((rb << 7) | (boff[q] ^ ((rb & 7) << 4)));
    }

    const int lr16 = lane & 15;
    const int lhi  = (lane >> 4) << 4;
    uint32_t aBase[2], aXr[2];
#pragma unroll
    for (int mt = 0; mt < 2; mt++) {
        int r = wM * 32 + mt * 16 + lr16;
        aBase[mt] = (uint32_t)(r << 7);
        aXr[mt]   = ((r & 7) << 4);
    }
    uint32_t bBase[3], bXr[3];
#pragma unroll
    for (int g = 0; g < 3; g++) {
        int r = wN * 16 + g * 32 + lr16;
        bBase[g] = (uint32_t)(r << 7);
        bXr[g]   = ((r & 7) << 4);
    }

    float acc[2][3][2][4];
#pragma unroll
    for (int i = 0; i < 2; i++)
#pragma unroll
        for (int g = 0; g < 3; g++)
#pragma unroll
            for (int a = 0; a < 2; a++)
#pragma unroll
                for (int v = 0; v < 4; v++) acc[i][g][a][v] = 0.f;

    auto load_chunk = [&](int s, int c) {
        const uint32_t st = sb + s * 28672;
        const int cb = c * 128;
#pragma unroll
        for (int q = 0; q < 4; q++) {
            int go = srow[q] * 1024 + cb + soff[q];
            cpasync16(st + sso[q], gAh + go);
        }
#pragma unroll
        for (int q = 0; q < 3; q++) {
            int go = bgr[q] * 1024 + cb + boff[q];
            cpasync16(st + 16384 + bso[q], gW + go);
        }
        cp_commit();
    };

    load_chunk(0, 0);

    for (int c = 0; c < NCH; c++) {
        const int s = c & 1;
        if (c + 1 < NCH) { load_chunk(s ^ 1, c + 1); cp_wait<1>(); }
        else             { cp_wait<0>(); }
        __syncthreads();

        const uint32_t stA0 = sb + s * 28672;
        const uint32_t stB0 = stA0 + 16384;

#pragma unroll
        for (int k16 = 0; k16 < 4; k16++) {
            const uint32_t ko = (uint32_t)(k16 * 32 + lhi);
            uint32_t ah[2][4];
#pragma unroll
            for (int mt = 0; mt < 2; mt++)
                ldsm4(ah[mt][0], ah[mt][1], ah[mt][2], ah[mt][3],
                      stA0 + aBase[mt] + (ko ^ aXr[mt]));
            uint32_t bh[3][4];
#pragma unroll
            for (int g = 0; g < 3; g++)
                ldsm4(bh[g][0], bh[g][1], bh[g][2], bh[g][3],
                      stB0 + bBase[g] + (ko ^ bXr[g]));
#pragma unroll
            for (int mt = 0; mt < 2; mt++)
#pragma unroll
                for (int g = 0; g < 3; g++) {
                    hmma16816(acc[mt][g][0], ah[mt], bh[g][0], bh[g][2]);
                    hmma16816(acc[mt][g][1], ah[mt], bh[g][1], bh[g][3]);
                }
        }
        __syncthreads();
    }

    const int lr = lane >> 2;
    const int lc = (lane & 3) << 1;
#pragma unroll
    for (int mt = 0; mt < 2; mt++) {
        const int mBase = m0 + wM * 32 + mt * 16 + lr;
#pragma unroll
        for (int a = 0; a < 2; a++) {
            const int j = j0 + wN * 16 + a * 8 + lc;
            const float2 bR = *(const float2*)(bhh + j);
            const float2 bZ = *(const float2*)(bhh + 512 + j);
            const float2 bN = *(const float2*)(bhh + 1024 + j);
#pragma unroll
            for (int hh = 0; hh < 2; hh++) {
                const int row = mBase + hh * 8;
                const int vi = hh * 2;
                float2 gR, gZ, gN;
                if (GIMODE == 1) {
                    const float* gi = (const float*)GIt + j;
                    gR = *(const float2*)(gi);
                    gZ = *(const float2*)(gi + 512);
                    gN = *(const float2*)(gi + 1024);
                } else {
                    const __half* gi;
                    if (GIMODE == 0)
                        gi = (const __half*)GIt + (size_t)row * H3 + j;
                    else {
                        int tok = gt[row * Tn + (step - 2)];
                        gi = (const __half*)GIt + (size_t)tok * H3 + j;
                    }
                    gR = __half22float2(*(const __half2*)(gi));
                    gZ = __half22float2(*(const __half2*)(gi + 512));
                    gN = __half22float2(*(const __half2*)(gi + 1024));
                }
                float2 hp = *(const float2*)(hprevF + (size_t)row * Hn + j);
                float r0 = sigf(gR.x + acc[mt][0][a][vi]     + bR.x);
                float r1 = sigf(gR.y + acc[mt][0][a][vi + 1] + bR.y);
                float z0 = sigf(gZ.x + acc[mt][1][a][vi]     + bZ.x);
                float z1 = sigf(gZ.y + acc[mt][1][a][vi + 1] + bZ.y);
                float n0 = tanhf(gN.x + r0 * (acc[mt][2][a][vi]     + bN.x));
                float n1 = tanhf(gN.y + r1 * (acc[mt][2][a][vi + 1] + bN.y));
                float h0 = (1.f - z0) * n0 + z0 * hp.x;
                float h1 = (1.f - z1) * n1 + z1 * hp.y;
                size_t oh = (size_t)row * Hn + j;
                *(float2*)(houtF + oh) = make_float2(h0, h1);
                *(__half2*)(hi + oh) = __floats2half2_rn(h0, h1);
            }
        }
    }
}

// ---------------- elementwise kernels ----------------
__global__ void convW(const float* __restrict__ W_ih, const float* __restrict__ W_hh,
                      const float* __restrict__ W_out, const float* __restrict__ W_tp,
                      const float* __restrict__ emb,
                      __half* __restrict__ wih, __half* __restrict__ whh,
                      __half* __restrict__ wo,  __half* __restrict__ wt,
                      __half* __restrict__ embh, __half* __restrict__ embl)
{
    int i = blockIdx.x * blockDim.x + threadIdx.x;
    if (i >= 1376256) return;
    if (i < 1310720) {
        const float* s; __half* d; int j;
        if (i < 589824)       { s = W_ih;  d = wih; j = i; }
        else if (i < 1179648) { s = W_hh;  d = whh; j = i - 589824; }
        else if (i < 1245184) { s = W_out; d = wo;  j = i - 1179648; }
        else                  { s = W_tp;  d = wt;  j = i - 1245184; }
        float4 v = ((const float4*)s)[j];
        ((__half2*)d)[2 * j + 0] = __floats2half2_rn(v.x, v.y);
        ((__half2*)d)[2 * j + 1] = __floats2half2_rn(v.z, v.w);
    } else {
        int j = i - 1310720;
        float4 v = ((const float4*)emb)[j];
        __half h0, h1, h2, h3, l0, l1, l2, l3;
        split1h(v.x, h0, l0); split1h(v.y, h1, l1);
        split1h(v.z, h2, l2); split1h(v.w, h3, l3);
        ((__half2*)embh)[2 * j + 0] = __halves2half2(h0, h1);
        ((__half2*)embh)[2 * j + 1] = __halves2half2(h2, h3);
        ((__half2*)embl)[2 * j + 0] = __halves2half2(l0, l1);
        ((__half2*)embl)[2 * j + 1] = __halves2half2(l2, l3);
    }
}

__global__ void prep_kernel(const float* __restrict__ prev,
                            const float* __restrict__ action,
                            const float* __restrict__ W_a, const float* __restrict__ b_a,
                            __half* __restrict__ pqh,
                            __half* __restrict__ x0h, __half* __restrict__ x0l)
{
    const int NPREV = (int)(Ln * BH / 4);
    int i = blockIdx.x * blockDim.x + threadIdx.x;
    if (i < NPREV) {
        float4 v = ((const float4*)prev)[i];
        ((__half2*)pqh)[2 * i + 0] = __floats2half2_rn(v.x, v.y);
        ((__half2*)pqh)[2 * i + 1] = __floats2half2_rn(v.z, v.w);
    } else if (i < NPREV + (int)(BH / 4)) {
        int j = i - NPREV;
        int e0 = j * 4;
        int b = e0 >> 9, c = e0 & 511;
        float a0 = action[b * 3 + 0], a1 = action[b * 3 + 1], a2 = action[b * 3 + 2];
        __half hs[4], ls[4];
#pragma unroll
        for (int q = 0; q < 4; q++) {
            int jj = c + q;
            float s = b_a[jj] + a0 * W_a[jj * 3 + 0] + a1 * W_a[jj * 3 + 1]
                              + a2 * W_a[jj * 3 + 2];
            split1h(s, hs[q], ls[q]);
        }
        ((__half2*)x0h)[2 * j + 0] = __halves2half2(hs[0], hs[1]);
        ((__half2*)x0h)[2 * j + 1] = __halves2half2(hs[2], hs[3]);
        ((__half2*)x0l)[2 * j + 0] = __halves2half2(ls[0], ls[1]);
        ((__half2*)x0l)[2 * j + 1] = __halves2half2(ls[2], ls[3]);
    }
}

__global__ void split2_kernel(const float* __restrict__ src,
                              __half* __restrict__ hi, __half* __restrict__ lo, int n4)
{
    int i = blockIdx.x * blockDim.x + threadIdx.x;
    if (i >= n4) return;
    float4 v = ((const float4*)src)[i];
    __half h0, h1, h2, h3, l0, l1, l2, l3;
    split1h(v.x, h0, l0); split1h(v.y, h1, l1);
    split1h(v.z, h2, l2); split1h(v.w, h3, l3);
    ((__half2*)hi)[2 * i + 0] = __halves2half2(h0, h1);
    ((__half2*)hi)[2 * i + 1] = __halves2half2(h2, h3);
    ((__half2*)lo)[2 * i + 0] = __halves2half2(l0, l1);
    ((__half2*)lo)[2 * i + 1] = __halves2half2(l2, l3);
}

__global__ void copyf4_kernel(const float* __restrict__ src, float* __restrict__ dst)
{
    int i = blockIdx.x * blockDim.x + threadIdx.x;
    if (i >= (int)(BH / 4)) return;
    ((float4*)dst)[i] = ((const float4*)src)[i];
}

__global__ void heads_kernel(const float* __restrict__ h2, const float* __restrict__ W_r,
                             const float* __restrict__ b_r, const float* __restrict__ W_d,
                             const float* __restrict__ b_d,
                             float* __restrict__ outr, float* __restrict__ outd)
{
    int gw = (blockIdx.x * blockDim.x + threadIdx.x) >> 5;
    int lane = threadIdx.x & 31;
    if (gw >= Bsz) return;
    const float* hb = h2 + (size_t)gw * Hn;
    float sr = 0.f, sd = 0.f;
#pragma unroll
    for (int k = lane; k < Hn; k += 32) {
        float v = hb[k];
        sr = fmaf(v, W_r[k], sr);
        sd = fmaf(v, W_d[k], sd);
    }
#pragma unroll
    for (int o = 16; o > 0; o >>= 1) {
        sr += __shfl_down_sync(0xffffffffu, sr, o);
        sd += __shfl_down_sync(0xffffffffu, sd, o);
    }
    if (lane == 0) { outr[gw] = sr + b_r[0]; outd[gw] = sd + b_d[0]; }
}

// ---------------------------------------------------------------------------
extern "C" void kernel_launch(void* const* d_in, const int* in_sizes, int n_in,
                              void* d_out, int out_size)
{
    const float* action      = (const float*)d_in[0];
    const float* prev_hidden = (const float*)d_in[1];
    const int*   gt          = (const int*)d_in[2];
    const float* W_a         = (const float*)d_in[3];
    const float* b_a         = (const float*)d_in[4];
    const float* emb         = (const float*)d_in[5];
    const float* W_tp        = (const float*)d_in[6];
    const float* b_tp        = (const float*)d_in[7];
    const float* W_ih        = (const float*)d_in[8];
    const float* W_hh        = (const float*)d_in[9];
    const float* b_ih        = (const float*)d_in[10];
    const float* b_hh        = (const float*)d_in[11];
    const float* W_out       = (const float*)d_in[12];
    const float* b_out       = (const float*)d_in[13];
    const float* W_r         = (const float*)d_in[14];
    const float* b_r         = (const float*)d_in[15];
    const float* W_d         = (const float*)d_in[16];
    const float* b_d         = (const float*)d_in[17];
    float* out = (float*)d_out;

    static cudaStream_t sL1 = nullptr, sL2 = nullptr, sLg = nullptr;
    static cudaEvent_t evL0[NSTEP], evL1[NSTEP], evL2[NSTEP], evLg[NSTEP];
    if (!sL1) {
        cudaStreamCreateWithFlags(&sL1, cudaStreamNonBlocking);
        cudaStreamCreateWithFlags(&sL2, cudaStreamNonBlocking);
        cudaStreamCreateWithFlags(&sLg, cudaStreamNonBlocking);
        for (int i = 0; i < NSTEP; i++) {
            cudaEventCreateWithFlags(&evL0[i], cudaEventDisableTiming);
            cudaEventCreateWithFlags(&evL1[i], cudaEventDisableTiming);
            cudaEventCreateWithFlags(&evL2[i], cudaEventDisableTiming);
            cudaEventCreateWithFlags(&evLg[i], cudaEventDisableTiming);
        }
        cudaFuncSetAttribute((const void*)gemm_h2<0, 2, 0>, cudaFuncAttributeMaxDynamicSharedMemorySize, GEMM_SMEM2);
        cudaFuncSetAttribute((const void*)gemm_h2<0, 2, 1>, cudaFuncAttributeMaxDynamicSharedMemorySize, GEMM_SMEM2);
        cudaFuncSetAttribute((const void*)gemm_h2<0, 1, 1>, cudaFuncAttributeMaxDynamicSharedMemorySize, GEMM_SMEM1);
        cudaFuncSetAttribute((const void*)gemm_h2<3, 1, 0>, cudaFuncAttributeMaxDynamicSharedMemorySize, GEMM_SMEM1);
        cudaFuncSetAttribute((const void*)gru_step<0>, cudaFuncAttributeMaxDynamicSharedMemorySize, STEP_SMEM);
        cudaFuncSetAttribute((const void*)gru_step<1>, cudaFuncAttributeMaxDynamicSharedMemorySize, STEP_SMEM);
        cudaFuncSetAttribute((const void*)gru_step<2>, cudaFuncAttributeMaxDynamicSharedMemorySize, STEP_SMEM);
    }

    __half *u0, *u1, *u2, *x0h, *x0l, *pqh;
    __half *wih, *whh, *wo, *wt, *embh, *embl, *Pqh, *Pql, *GIh, *Gtabh;
    float *h0F, *h1F, *h2F, *P;
    cudaGetSymbolAddress((void**)&u0, g_u0);
    cudaGetSymbolAddress((void**)&u1, g_u1);
    cudaGetSymbolAddress((void**)&u2, g_u2);
    cudaGetSymbolAddress((void**)&x0h, g_x0h);   cudaGetSymbolAddress((void**)&x0l, g_x0l);
    cudaGetSymbolAddress((void**)&pqh, g_pq_hi);
    cudaGetSymbolAddress((void**)&wih, g_wih);   cudaGetSymbolAddress((void**)&whh, g_whh);
    cudaGetSymbolAddress((void**)&wo,  g_wo);    cudaGetSymbolAddress((void**)&wt,  g_wt);
    cudaGetSymbolAddress((void**)&embh, g_embh); cudaGetSymbolAddress((void**)&embl, g_embl);
    cudaGetSymbolAddress((void**)&Pqh, g_Pqh);   cudaGetSymbolAddress((void**)&Pql, g_Pql);
    cudaGetSymbolAddress((void**)&h0F, g_h0F);
    cudaGetSymbolAddress((void**)&h1F, g_h1F);
    cudaGetSymbolAddress((void**)&h2F, g_h2F);
    cudaGetSymbolAddress((void**)&GIh, g_GIh);
    cudaGetSymbolAddress((void**)&P, g_P);
    cudaGetSymbolAddress((void**)&Gtabh, g_Gtabh);

    float* outLogits = out;
    float* outReward = out + (size_t)Bsz * Tn * Cn;
    float* outDone   = outReward + Bsz;
    float* outFinal  = outDone + Bsz;

    const dim3 stepGrid(16, 32);

    // ---- preamble (main stream) ----
    convW<<<(1376256 + 255) / 256, 256>>>(W_ih, W_hh, W_out, W_tp, emb,
                                          wih, whh, wo, wt, embh, embl);
    prep_kernel<<<((int)(Ln * BH / 4 + BH / 4) + 255) / 256, 256>>>(
        prev_hidden, action, W_a, b_a, pqh, x0h, x0l);
    // GI slot0 for layer0 (2-plane x0, fp16 out)
    gemm_h2<0, 2, 1><<<dim3(12, 32), 256, GEMM_SMEM2>>>(x0h, x0l, wih, b_ih, GIh, H3);
    // P = emb @ W_tp.T + b_tp
    gemm_h2<0, 2, 0><<<dim3(4, 4), 256, GEMM_SMEM2>>>(embh, embl, wt, b_tp, P, Hn);
    split2_kernel<<<((Cn * Hn / 4) + 255) / 256, 256>>>(P, Pqh, Pql, Cn * Hn / 4);
    gemm_h2<0, 2, 1><<<dim3(12, 4), 256, GEMM_SMEM2>>>(Pqh, Pql, wih, b_ih, Gtabh, H3);

    // ---- layer 0 recurrence on main stream ----
    for (int t = 0; t < NSTEP; t++) {
        const __half* ph = t ? (u0 + (size_t)(t - 1) * BH) : pqh;
        const float* hpF = t ? (h0F + (size_t)(t - 1) * BH) : prev_hidden;
        float*  hF = h0F + (size_t)t * BH;
        __half* oh = u0 + (size_t)t * BH;
        if (t == 0)
            gru_step<0><<<stepGrid, 256, STEP_SMEM>>>(ph, whh, b_hh,
                                                      GIh, gt, t, hpF, hF, oh);
        else if (t == 1)
            gru_step<1><<<stepGrid, 256, STEP_SMEM>>>(ph, whh, b_hh,
                                                      b_ih, gt, t, hpF, hF, oh);
        else
            gru_step<2><<<stepGrid, 256, STEP_SMEM>>>(ph, whh, b_hh,
                                                      Gtabh, gt, t, hpF, hF, oh);
        cudaEventRecord(evL0[t], 0);
    }
    copyf4_kernel<<<((int)(BH / 4) + 255) / 256, 256>>>(
        h0F + (size_t)16 * BH, outFinal);

    // ---- layer 1 recurrence on sL1 (wavefront: one step behind layer 0) ----
    for (int t = 0; t < NSTEP; t++) {
        cudaStreamWaitEvent(sL1, evL0[t], 0);
        gemm_h2<0, 1, 1><<<dim3(12, 32), 256, GEMM_SMEM1, sL1>>>(
            u0 + (size_t)t * BH, nullptr, wih + (size_t)1 * H3 * Hn,
            b_ih + 1 * H3, GIh + (size_t)t * BH3, H3);
        const __half* ph = t ? (u1 + (size_t)(t - 1) * BH) : (pqh + BH);
        const float* hpF = t ? (h1F + (size_t)(t - 1) * BH) : (prev_hidden + BH);
        gru_step<0><<<stepGrid, 256, STEP_SMEM, sL1>>>(
            ph, whh + (size_t)1 * H3 * Hn, b_hh + 1 * H3,
            GIh + (size_t)t * BH3, gt, t,
            hpF, h1F + (size_t)t * BH, u1 + (size_t)t * BH);
        cudaEventRecord(evL1[t], sL1);
    }

    // ---- layer 2 recurrence on sL2 ----
    for (int t = 0; t < NSTEP; t++) {
        cudaStreamWaitEvent(sL2, evL1[t], 0);
        gemm_h2<0, 1, 1><<<dim3(12, 32), 256, GEMM_SMEM1, sL2>>>(
            u1 + (size_t)t * BH, nullptr, wih + (size_t)2 * H3 * Hn,
            b_ih + 2 * H3, GIh + (size_t)t * BH3, H3);
        const __half* ph = t ? (u2 + (size_t)(t - 1) * BH) : (pqh + 2 * BH);
        const float* hpF = t ? (h2F + (size_t)(t - 1) * BH) : (prev_hidden + 2 * BH);
        gru_step<0><<<stepGrid, 256, STEP_SMEM, sL2>>>(
            ph, whh + (size_t)2 * H3 * Hn, b_hh + 2 * H3,
            GIh + (size_t)t * BH3, gt, t,
            hpF, h2F + (size_t)t * BH, u2 + (size_t)t * BH);
        cudaEventRecord(evL2[t], sL2);
    }

    // ---- logits chunks on sLg (slot t -> logits position t-1) ----
    for (int t = 1; t < NSTEP; t++) {
        cudaStreamWaitEvent(sLg, evL2[t], 0);
        gemm_h2<3, 1, 0><<<dim3(4, 32), 256, GEMM_SMEM1, sLg>>>(
            u2 + (size_t)t * BH, nullptr, wo, b_out, outLogits, t - 1);
        cudaEventRecord(evLg[t], sLg);
    }

    // ---- epilogue on main stream ----
    cudaStreamWaitEvent(0, evL1[16], 0);
    copyf4_kernel<<<((int)(BH / 4) + 255) / 256, 256>>>(
        h1F + (size_t)16 * BH, outFinal + BH);
    cudaStreamWaitEvent(0, evL2[16], 0);
    copyf4_kernel<<<((int)(BH / 4) + 255) / 256, 256>>>(
        h2F + (size_t)16 * BH, outFinal + 2 * BH);
    heads_kernel<<<(Bsz * 32 + 255) / 256, 256>>>(
        h2F, W_r, b_r, W_d, b_d, outReward, outDone);
    for (int t = 1; t < NSTEP; t++)
        cudaStreamWaitEvent(0, evLg[t], 0);
}